// round 13
// baseline (speedup 1.0000x reference)
#include <cuda_runtime.h>
#include <cuda_bf16.h>
#include <cuda_fp16.h>
#include <cstdint>

#define BSZ   8
#define NPER  8192
#define NTOT  65536
#define EMB   128
#define ENCD  512
#define LQ    512
#define NE    1048576
#define NHE   4096
#define NP    1048576
#define NROWS (BSZ*LQ)   // 4096
#define SPLIT 16
#define KEYS_PER (NPER/SPLIT)   // 512
#define KT    64

#define LDKA 24
#define LDNB 136

__device__ __forceinline__ uint32_t smem_u32(const void* p) {
    uint32_t a;
    asm("{ .reg .u64 t; cvta.to.shared.u64 t, %1; cvt.u32.u64 %0, t; }"
        : "=r"(a) : "l"(p));
    return a;
}
__device__ __forceinline__ void ldsm_x4(uint32_t* r, uint32_t addr) {
    asm volatile("ldmatrix.sync.aligned.m8n8.x4.shared.b16 {%0,%1,%2,%3}, [%4];"
                 : "=r"(r[0]), "=r"(r[1]), "=r"(r[2]), "=r"(r[3]) : "r"(addr));
}
__device__ __forceinline__ void ldsm_x4t(uint32_t* r, uint32_t addr) {
    asm volatile("ldmatrix.sync.aligned.m8n8.x4.trans.shared.b16 {%0,%1,%2,%3}, [%4];"
                 : "=r"(r[0]), "=r"(r[1]), "=r"(r[2]), "=r"(r[3]) : "r"(addr));
}
__device__ __forceinline__ void mma16816(float* c, const uint32_t* a,
                                         uint32_t b0, uint32_t b1) {
    asm volatile("mma.sync.aligned.m16n8k16.row.col.f32.bf16.bf16.f32 "
                 "{%0,%1,%2,%3}, {%4,%5,%6,%7}, {%8,%9}, {%0,%1,%2,%3};"
                 : "+f"(c[0]), "+f"(c[1]), "+f"(c[2]), "+f"(c[3])
                 : "r"(a[0]), "r"(a[1]), "r"(a[2]), "r"(a[3]), "r"(b0), "r"(b1));
}
__device__ __forceinline__ void split4(float4 av, uint2& hp, uint2& lp) {
    __nv_bfloat162 h0, h1, l0, l1;
    h0.x = __float2bfloat16_rn(av.x); h0.y = __float2bfloat16_rn(av.y);
    h1.x = __float2bfloat16_rn(av.z); h1.y = __float2bfloat16_rn(av.w);
    l0.x = __float2bfloat16_rn(av.x - __bfloat162float(h0.x));
    l0.y = __float2bfloat16_rn(av.y - __bfloat162float(h0.y));
    l1.x = __float2bfloat16_rn(av.z - __bfloat162float(h1.x));
    l1.y = __float2bfloat16_rn(av.w - __bfloat162float(h1.y));
    hp.x = *(uint32_t*)&h0; hp.y = *(uint32_t*)&h1;
    lp.x = *(uint32_t*)&l0; lp.y = *(uint32_t*)&l1;
}
__device__ __forceinline__ void splitpair(float a, float b, uint32_t& h, uint32_t& l) {
    __nv_bfloat162 hh, ll;
    hh.x = __float2bfloat16_rn(a); hh.y = __float2bfloat16_rn(b);
    ll.x = __float2bfloat16_rn(a - __bfloat162float(hh.x));
    ll.y = __float2bfloat16_rn(b - __bfloat162float(hh.y));
    h = *(uint32_t*)&hh; l = *(uint32_t*)&ll;
}
__device__ __forceinline__ uint32_t packbf(float a, float b) {
    __nv_bfloat162 h;
    h.x = __float2bfloat16_rn(a); h.y = __float2bfloat16_rn(b);
    return *(uint32_t*)&h;
}

#define CP16(s, gp) asm volatile("cp.async.ca.shared.global [%0], [%1], 16;" :: "r"(s), "l"(gp))
#define CPCOMMIT()  asm volatile("cp.async.commit_group;" ::: "memory")
#define CPWAIT1()   asm volatile("cp.async.wait_group 1;" ::: "memory")
#define CPWAIT0()   asm volatile("cp.async.wait_group 0;" ::: "memory")

// ---------------- scratch ----------------------------------------------------
__device__ float d_t  [(size_t)NTOT*EMB];      // reused as __half buffer
__device__ float d_ef [(size_t)NTOT*EMB];      // reused as __half buffer
__device__ float d_H  [(size_t)NROWS*EMB];
__device__ float d_Op [(size_t)SPLIT*NROWS*EMB];   // reused as __half buffer
__device__ float d_pm [SPLIT*NROWS], d_pl[SPLIT*NROWS];
__device__ __nv_bfloat16 d_aggh[(size_t)NTOT*EMB], d_aggl[(size_t)NTOT*EMB];
__device__ __nv_bfloat16 d_vh  [(size_t)NTOT*EMB], d_vl  [(size_t)NTOT*EMB];
__device__ __nv_bfloat16 d_qh[(size_t)NROWS*EMB],  d_ql[(size_t)NROWS*EMB];
__device__ __nv_bfloat16 d_kmh[(size_t)EMB*NTOT],  d_kml[(size_t)EMB*NTOT];
__device__ __nv_bfloat16 d_gh[(size_t)NTOT*EMB],   d_gl[(size_t)NTOT*EMB];
#define OFF_WG1 0
#define OFF_WH1 16384
#define OFF_WG2 32768
#define OFF_WH2 49152
#define OFF_WM2 65536
#define OFF_WM  81920
#define OFF_WS  147456
#define OFF_WT  229376
__device__ __nv_bfloat16 d_wh[311296], d_wl[311296];
__device__ float d_rsout[NTOT], d_rsin[NTOT], d_Dinv[NTOT], d_Binv[NHE];
__device__ int   d_c0[NTOT], d_c1[NTOT], d_c2[NTOT], d_c3[NHE];
__device__ int d_off_e [NTOT+1], d_col_e [NE];
__device__ int d_off_hn[NTOT+1], d_col_hn[NP];
__device__ int d_off_he[NHE+1],  d_col_he[NP];
__device__ int d_cre[NTOT], d_crn[NTOT], d_crh[NHE];
__device__ int d_part3[3][257];

// ---------------- utility ----------------------------------------------------
struct PSArgs { const float* s[8]; };
__global__ void presplit_all(PSArgs a, __nv_bfloat16* __restrict__ hi,
                             __nv_bfloat16* __restrict__ lo) {
    const int bstart[8] = {0, 16, 32, 48, 64, 80, 144, 224};
    const int dstoff[8] = {0, 4096, 8192, 12288, 16384, 20480, 36864, 57344};
    int b = blockIdx.x;
    int seg = 0;
    #pragma unroll
    for (int s = 1; s < 8; s++) if (b >= bstart[s]) seg = s;
    int li = (b - bstart[seg]) * 256 + threadIdx.x;
    int n4 = (seg < 5) ? 4096 : (seg == 5 ? 16384 : 20480);
    if (li >= n4) return;
    float4 v = ((const float4*)a.s[seg])[li];
    uint2 hp, lp;
    split4(v, hp, lp);
    *(uint2*)(hi + ((size_t)dstoff[seg] + li) * 4) = hp;
    *(uint2*)(lo + ((size_t)dstoff[seg] + li) * 4) = lp;
}

__global__ void zero_counts() {
    int i = blockIdx.x * blockDim.x + threadIdx.x;
    if (i < NTOT) { d_c0[i] = 0; d_c1[i] = 0; d_c2[i] = 0; d_cre[i] = 0; d_crn[i] = 0; }
    if (i < NHE)  { d_c3[i] = 0; d_crh[i] = 0; }
}
__global__ void count_all(const int* __restrict__ eidx, const int* __restrict__ hidx) {
    int b = blockIdx.x, t = threadIdx.x;
    if (b < NE / 256) {
        int i = b * 256 + t;
        atomicAdd(&d_c0[eidx[i]], 1);
        atomicAdd(&d_c1[eidx[NE + i]], 1);
    } else {
        int i = (b - NE / 256) * 256 + t;
        atomicAdd(&d_c2[hidx[2 * i]], 1);
        atomicAdd(&d_c3[hidx[2 * i + 1]], 1);
    }
}
__global__ void finalize_scales() {
    int i = blockIdx.x * blockDim.x + threadIdx.x;
    if (i < NTOT) {
        d_rsout[i] = rsqrtf((float)max(d_c0[i], 1));
        d_rsin[i]  = rsqrtf((float)max(d_c1[i], 1));
        d_Dinv[i]  = d_c2[i] > 0 ? 1.f / (float)d_c2[i] : 0.f;
    }
    if (i < NHE) d_Binv[i] = d_c3[i] > 0 ? 1.f / (float)d_c3[i] : 0.f;
}

// ---------------- merged scans ----------------------------------------------
__global__ void scan1c() {
    int b = blockIdx.x;
    const int* cnt; int* off; int* part; int li;
    if (b < 256)      { cnt = d_c1; off = d_off_e;  part = d_part3[0]; li = b; }
    else if (b < 512) { cnt = d_c2; off = d_off_hn; part = d_part3[1]; li = b - 256; }
    else              { cnt = d_c3; off = d_off_he; part = d_part3[2]; li = b - 512; }
    __shared__ int sh[256];
    int t = threadIdx.x;
    int i = li * 256 + t;
    int v = cnt[i];
    sh[t] = v;
    __syncthreads();
    #pragma unroll
    for (int o = 1; o < 256; o <<= 1) {
        int add = (t >= o) ? sh[t - o] : 0;
        __syncthreads();
        sh[t] += add;
        __syncthreads();
    }
    off[i] = sh[t] - v;
    if (t == 255) part[li] = sh[255];
}
__global__ void scan2c() {
    int a = blockIdx.x;
    int nb = (a == 2) ? 16 : 256;
    int* part = d_part3[a];
    __shared__ int sh[256];
    int t = threadIdx.x;
    int v = (t < nb) ? part[t] : 0;
    sh[t] = v;
    __syncthreads();
    #pragma unroll
    for (int o = 1; o < 256; o <<= 1) {
        int add = (t >= o) ? sh[t - o] : 0;
        __syncthreads();
        sh[t] += add;
        __syncthreads();
    }
    part[t] = sh[t] - v;
    if (t == nb - 1) part[256] = sh[t];
}
__global__ void scan3c() {
    int b = blockIdx.x;
    int* off; int* part; int li; int n;
    if (b < 256)      { off = d_off_e;  part = d_part3[0]; li = b; n = NTOT; }
    else if (b < 512) { off = d_off_hn; part = d_part3[1]; li = b - 256; n = NTOT; }
    else              { off = d_off_he; part = d_part3[2]; li = b - 512; n = NHE; }
    int i = li * 256 + threadIdx.x;
    off[i] += part[li];
    if (i == 0) off[n] = part[256];
}

__global__ void fill_all(const int* __restrict__ eidx, const int* __restrict__ hidx) {
    int b = blockIdx.x, t = threadIdx.x;
    if (b < NE / 256) {
        int i = b * 256 + t;
        int s = eidx[i], d = eidx[NE + i];
        int p = atomicAdd(&d_cre[d], 1);
        d_col_e[d_off_e[d] + p] = s;
    } else {
        int i = (b - NE / 256) * 256 + t;
        int n = hidx[2 * i], e = hidx[2 * i + 1];
        int p1 = atomicAdd(&d_crn[n], 1);
        d_col_hn[d_off_hn[n] + p1] = e;
        int p2 = atomicAdd(&d_crh[e], 1);
        d_col_he[d_off_he[e] + p2] = n;
    }
}

// ---------------- CSR gather: half-warp per row, fp16 in ---------------------
// GEPI 4: scaled store -> half
// GEPI 2: (acc*s1[r]+pb[k]) -> bf16 hi/lo
// GEPI 3: ((relu(acc*s1[r]+pb[k])+padd[r,k])*s2[r]) -> bf16 hi/lo
// GEPI 1: (relu(acc*s1[r]+pb[k])+padd[r,k]) -> bf16 hi/lo
template<int GEPI, bool OSC, bool ISC>
__global__ void __launch_bounds__(256) gather_k(const int* __restrict__ off,
                                                const int* __restrict__ col,
                                                const __half* __restrict__ in,
                                                void* __restrict__ outp,
                                                const float* __restrict__ oscale,
                                                const float* __restrict__ iscale,
                                                const float* __restrict__ s1,
                                                const float* __restrict__ pb,
                                                const float* __restrict__ padd,
                                                const float* __restrict__ s2,
                                                __nv_bfloat16* __restrict__ oh,
                                                __nv_bfloat16* __restrict__ ol) {
    int warp = threadIdx.x >> 5, lane = threadIdx.x & 31;
    int half = lane >> 4, hl = lane & 15;
    int r = blockIdx.x * 16 + warp * 2 + half;
    uint32_t hmask = 0xFFFFu << (half * 16);
    int b = off[r], e = off[r + 1];
    float acc[8];
    #pragma unroll
    for (int i = 0; i < 8; i++) acc[i] = 0.f;

    for (int j0 = b; j0 < e; j0 += 16) {
        int cj = 0;
        if (j0 + hl < e) cj = col[j0 + hl];
        int m = min(e - j0, 16);
        #pragma unroll 8
        for (int k = 0; k < m; k++) {
            int c = __shfl_sync(hmask, cj, k, 16);
            uint4 raw = *(const uint4*)(in + (size_t)c * EMB + hl * 8);
            float2 f0 = __half22float2(*(__half2*)&raw.x);
            float2 f1 = __half22float2(*(__half2*)&raw.y);
            float2 f2 = __half22float2(*(__half2*)&raw.z);
            float2 f3 = __half22float2(*(__half2*)&raw.w);
            if (ISC) {
                float s = iscale[c];
                f0.x *= s; f0.y *= s; f1.x *= s; f1.y *= s;
                f2.x *= s; f2.y *= s; f3.x *= s; f3.y *= s;
            }
            acc[0] += f0.x; acc[1] += f0.y; acc[2] += f1.x; acc[3] += f1.y;
            acc[4] += f2.x; acc[5] += f2.y; acc[6] += f3.x; acc[7] += f3.y;
        }
    }
    if (OSC) {
        float s = oscale[r];
        #pragma unroll
        for (int i = 0; i < 8; i++) acc[i] *= s;
    }
    size_t base = (size_t)r * EMB + hl * 8;
    if (GEPI == 4) {
        __half2 h0 = __floats2half2_rn(acc[0], acc[1]);
        __half2 h1 = __floats2half2_rn(acc[2], acc[3]);
        __half2 h2 = __floats2half2_rn(acc[4], acc[5]);
        __half2 h3 = __floats2half2_rn(acc[6], acc[7]);
        uint4 st;
        st.x = *(uint32_t*)&h0; st.y = *(uint32_t*)&h1;
        st.z = *(uint32_t*)&h2; st.w = *(uint32_t*)&h3;
        *(uint4*)((__half*)outp + base) = st;
        return;
    }
    float sr = s1[r];
    float4 b0 = *(const float4*)(pb + hl * 8);
    float4 b1 = *(const float4*)(pb + hl * 8 + 4);
    acc[0] = acc[0] * sr + b0.x; acc[1] = acc[1] * sr + b0.y;
    acc[2] = acc[2] * sr + b0.z; acc[3] = acc[3] * sr + b0.w;
    acc[4] = acc[4] * sr + b1.x; acc[5] = acc[5] * sr + b1.y;
    acc[6] = acc[6] * sr + b1.z; acc[7] = acc[7] * sr + b1.w;
    if (GEPI == 3 || GEPI == 1) {
        float4 n0 = *(const float4*)(padd + base);
        float4 n1 = *(const float4*)(padd + base + 4);
        acc[0] = fmaxf(acc[0], 0.f) + n0.x; acc[1] = fmaxf(acc[1], 0.f) + n0.y;
        acc[2] = fmaxf(acc[2], 0.f) + n0.z; acc[3] = fmaxf(acc[3], 0.f) + n0.w;
        acc[4] = fmaxf(acc[4], 0.f) + n1.x; acc[5] = fmaxf(acc[5], 0.f) + n1.y;
        acc[6] = fmaxf(acc[6], 0.f) + n1.z; acc[7] = fmaxf(acc[7], 0.f) + n1.w;
        if (GEPI == 3) {
            float so = s2[r];
            #pragma unroll
            for (int i = 0; i < 8; i++) acc[i] *= so;
        }
    }
    float4 v0; v0.x = acc[0]; v0.y = acc[1]; v0.z = acc[2]; v0.w = acc[3];
    float4 v1; v1.x = acc[4]; v1.y = acc[5]; v1.z = acc[6]; v1.w = acc[7];
    uint2 hp0, lp0, hp1, lp1;
    split4(v0, hp0, lp0);
    split4(v1, hp1, lp1);
    uint4 sh_, sl_;
    sh_.x = hp0.x; sh_.y = hp0.y; sh_.z = hp1.x; sh_.w = hp1.y;
    sl_.x = lp0.x; sl_.y = lp0.y; sl_.z = lp1.x; sl_.w = lp1.y;
    *(uint4*)(oh + base) = sh_;
    *(uint4*)(ol + base) = sl_;
}

// =============== mma.sync bf16-split GEMM ===================================
// MODE 0: chunked fp32 A (K=512/640) | MODE 1: B-res, fp32 A | MODE 2: B-res, pre-split A cp.async
// EPI: 0 fp32 | 6 relu+bias->hi/lo | 7 relu+bias->hi/lo transposed | 8 dual-head
//      | 9 plain store -> half (via Ch)
struct MArgs {
    const float* A; long lda;
    const __nv_bfloat16* Ah; const __nv_bfloat16* Al;
    const __nv_bfloat16* Bh; const __nv_bfloat16* Bl; long ldb;
    const __nv_bfloat16* Bh2; const __nv_bfloat16* Bl2;
    float* C; long ldc;
    __nv_bfloat16* Ch; __nv_bfloat16* Cl;
    int K;
    const float* padd; long ldadd;
    const float* bias; const float* bias2;
};

template<int PRO, int EPI, int MODE>
__global__ void __launch_bounds__(256, 2) mma_gemm(MArgs g) {
    constexpr int BROWS = (MODE >= 1) ? 128 : 16;
    constexpr int ABUF  = (MODE == 2) ? 3 : (MODE == 1 ? 2 : 1);
    __shared__ __align__(16) __nv_bfloat16 sAh[ABUF][128 * LDKA];
    __shared__ __align__(16) __nv_bfloat16 sAl[ABUF][128 * LDKA];
    __shared__ __align__(16) __nv_bfloat16 sBh[BROWS * LDNB];
    __shared__ __align__(16) __nv_bfloat16 sBl[BROWS * LDNB];

    const float* A = g.A;
    float* C = g.C;
    const __nv_bfloat16* Bh = g.Bh;
    const __nv_bfloat16* Bl = g.Bl;
    const float* bias = g.bias;
    if (EPI == 8 && blockIdx.y == 1) {
        Bh = g.Bh2; Bl = g.Bl2; bias = g.bias2; C = g.C + 128;
    }
    int m0 = blockIdx.x * 128;

    int tid = threadIdx.x, wid = tid >> 5, lane = tid & 31;
    int wm = wid >> 1, wn = wid & 1;

    float acc[2][8][4];
    #pragma unroll
    for (int i = 0; i < 2; i++)
        #pragma unroll
        for (int j = 0; j < 8; j++)
            #pragma unroll
            for (int q = 0; q < 4; q++) acc[i][j][q] = 0.f;

    uint32_t sBh_b = smem_u32(sBh), sBl_b = smem_u32(sBl);

    int arow = lane & 15, akoff = (lane >> 4) * 8;
    int bkrow = (lane & 7) + ((lane >> 3) & 1) * 8;
    int bnoff = (lane >> 4) * 8;

    if (MODE == 2) {
        #pragma unroll
        for (int i = 0; i < 16; i++) {
            int idx = tid + i * 256;
            int kr = idx >> 5, n = (idx & 31) * 4;
            size_t boff = (size_t)kr * g.ldb + n;
            *(uint2*)&sBh[kr * LDNB + n] = *(const uint2*)(Bh + boff);
            *(uint2*)&sBl[kr * LDNB + n] = *(const uint2*)(Bl + boff);
        }
        int row = tid >> 1, half = tid & 1;
        auto cpA = [&](int c) {
            int slot = c % 3;
            uint32_t sh_ = smem_u32(&sAh[slot][row * LDKA + half * 8]);
            uint32_t sl_ = smem_u32(&sAl[slot][row * LDKA + half * 8]);
            const __nv_bfloat16* gph = g.Ah + (size_t)(m0 + row) * 128 + c * 16 + half * 8;
            const __nv_bfloat16* gpl = g.Al + (size_t)(m0 + row) * 128 + c * 16 + half * 8;
            CP16(sh_, gph);
            CP16(sl_, gpl);
        };
        cpA(0); CPCOMMIT();
        cpA(1); CPCOMMIT();

        #pragma unroll
        for (int c = 0; c < 8; c++) {
            CPWAIT1();
            __syncthreads();
            if (c + 2 < 8) cpA(c + 2);
            CPCOMMIT();

            int slot = c % 3;
            uint32_t sAh_b = smem_u32(sAh[slot]), sAl_b = smem_u32(sAl[slot]);
            uint32_t a_h[2][4], a_l[2][4];
            #pragma unroll
            for (int mt = 0; mt < 2; mt++) {
                uint32_t off = (uint32_t)(((wm * 32 + mt * 16 + arow) * LDKA + akoff) * 2);
                ldsm_x4(a_h[mt], sAh_b + off);
                ldsm_x4(a_l[mt], sAl_b + off);
            }
            uint32_t b_h[4][4], b_l[4][4];
            #pragma unroll
            for (int ng = 0; ng < 4; ng++) {
                uint32_t off = (uint32_t)(((c * 16 + bkrow) * LDNB + wn * 64 + ng * 16 + bnoff) * 2);
                ldsm_x4t(b_h[ng], sBh_b + off);
                ldsm_x4t(b_l[ng], sBl_b + off);
            }
            #pragma unroll
            for (int mt = 0; mt < 2; mt++)
                #pragma unroll
                for (int ng = 0; ng < 4; ng++)
                    #pragma unroll
                    for (int h = 0; h < 2; h++) {
                        int nt = ng * 2 + h;
                        mma16816(acc[mt][nt], a_h[mt], b_h[ng][h*2], b_h[ng][h*2+1]);
                        mma16816(acc[mt][nt], a_h[mt], b_l[ng][h*2], b_l[ng][h*2+1]);
                        mma16816(acc[mt][nt], a_l[mt], b_h[ng][h*2], b_h[ng][h*2+1]);
                    }
        }
    } else if (MODE == 1) {
        float4 pAv[2];
        auto prefetchA = [&](int k0) {
            #pragma unroll
            for (int i = 0; i < 2; i++) {
                int idx = tid + i * 256;
                int r = idx >> 2, k = (idx & 3) * 4;
                pAv[i] = *(const float4*)(A + (size_t)(m0 + r) * g.lda + k0 + k);
            }
        };
        auto commitA = [&](int p) {
            #pragma unroll
            for (int i = 0; i < 2; i++) {
                int idx = tid + i * 256;
                int r = idx >> 2, k = (idx & 3) * 4;
                uint2 hp, lp;
                split4(pAv[i], hp, lp);
                *(uint2*)&sAh[p][r * LDKA + k] = hp;
                *(uint2*)&sAl[p][r * LDKA + k] = lp;
            }
        };
        #pragma unroll
        for (int i = 0; i < 16; i++) {
            int idx = tid + i * 256;
            int kr = idx >> 5, n = (idx & 31) * 4;
            size_t boff = (size_t)kr * g.ldb + n;
            *(uint2*)&sBh[kr * LDNB + n] = *(const uint2*)(Bh + boff);
            *(uint2*)&sBl[kr * LDNB + n] = *(const uint2*)(Bl + boff);
        }
        prefetchA(0);
        commitA(0);
        __syncthreads();
        #pragma unroll
        for (int c = 0; c < 8; c++) {
            int p = c & 1;
            uint32_t sAh_b = smem_u32(sAh[p]), sAl_b = smem_u32(sAl[p]);
            uint32_t a_h[2][4], a_l[2][4];
            #pragma unroll
            for (int mt = 0; mt < 2; mt++) {
                uint32_t off = (uint32_t)(((wm * 32 + mt * 16 + arow) * LDKA + akoff) * 2);
                ldsm_x4(a_h[mt], sAh_b + off);
                ldsm_x4(a_l[mt], sAl_b + off);
            }
            uint32_t b_h[4][4], b_l[4][4];
            #pragma unroll
            for (int ng = 0; ng < 4; ng++) {
                uint32_t off = (uint32_t)(((c * 16 + bkrow) * LDNB + wn * 64 + ng * 16 + bnoff) * 2);
                ldsm_x4t(b_h[ng], sBh_b + off);
                ldsm_x4t(b_l[ng], sBl_b + off);
            }
            if (c < 7) prefetchA((c + 1) * 16);
            #pragma unroll
            for (int mt = 0; mt < 2; mt++)
                #pragma unroll
                for (int ng = 0; ng < 4; ng++)
                    #pragma unroll
                    for (int h = 0; h < 2; h++) {
                        int nt = ng * 2 + h;
                        mma16816(acc[mt][nt], a_h[mt], b_h[ng][h*2], b_h[ng][h*2+1]);
                        mma16816(acc[mt][nt], a_h[mt], b_l[ng][h*2], b_l[ng][h*2+1]);
                        mma16816(acc[mt][nt], a_l[mt], b_h[ng][h*2], b_h[ng][h*2+1]);
                    }
            if (c < 7) {
                commitA(p ^ 1);
                __syncthreads();
            }
        }
    } else {
        uint32_t sAh_b = smem_u32(sAh[0]), sAl_b = smem_u32(sAl[0]);
        float4 pAv[2];
        uint2 pBhr[2], pBlr[2];
        auto prefetch = [&](int k0) {
            #pragma unroll
            for (int i = 0; i < 2; i++) {
                int idx = tid + i * 256;
                int r = idx >> 2, k = (idx & 3) * 4;
                int kk = k0 + k;
                if (PRO == 4) {
                    pAv[i] = (kk < ENCD)
                        ? *(const float4*)(A + (size_t)(m0 + r) * g.lda + kk)
                        : *(const float4*)(g.padd + (size_t)(m0 + r) * g.ldadd + (kk - ENCD));
                } else {
                    pAv[i] = *(const float4*)(A + (size_t)(m0 + r) * g.lda + kk);
                }
                int kr = idx >> 5, n = (idx & 31) * 4;
                size_t boff = (size_t)(k0 + kr) * g.ldb + n;
                pBhr[i] = *(const uint2*)(Bh + boff);
                pBlr[i] = *(const uint2*)(Bl + boff);
            }
        };
        auto commit = [&]() {
            #pragma unroll
            for (int i = 0; i < 2; i++) {
                int idx = tid + i * 256;
                int r = idx >> 2, k = (idx & 3) * 4;
                uint2 hp, lp;
                split4(pAv[i], hp, lp);
                *(uint2*)&sAh[0][r * LDKA + k] = hp;
                *(uint2*)&sAl[0][r * LDKA + k] = lp;
                int kr = idx >> 5, n = (idx & 31) * 4;
                *(uint2*)&sBh[kr * LDNB + n] = pBhr[i];
                *(uint2*)&sBl[kr * LDNB + n] = pBlr[i];
            }
        };
        prefetch(0);
        for (int k0 = 0; k0 < g.K; k0 += 16) {
            commit();
            __syncthreads();
            if (k0 + 16 < g.K) prefetch(k0 + 16);

            uint32_t a_h[2][4], a_l[2][4];
            #pragma unroll
            for (int mt = 0; mt < 2; mt++) {
                uint32_t off = (uint32_t)(((wm * 32 + mt * 16 + arow) * LDKA + akoff) * 2);
                ldsm_x4(a_h[mt], sAh_b + off);
                ldsm_x4(a_l[mt], sAl_b + off);
            }
            uint32_t b_h[4][4], b_l[4][4];
            #pragma unroll
            for (int ng = 0; ng < 4; ng++) {
                uint32_t off = (uint32_t)((bkrow * LDNB + wn * 64 + ng * 16 + bnoff) * 2);
                ldsm_x4t(b_h[ng], sBh_b + off);
                ldsm_x4t(b_l[ng], sBl_b + off);
            }
            #pragma unroll
            for (int mt = 0; mt < 2; mt++)
                #pragma unroll
                for (int ng = 0; ng < 4; ng++)
                    #pragma unroll
                    for (int h = 0; h < 2; h++) {
                        int nt = ng * 2 + h;
                        mma16816(acc[mt][nt], a_h[mt], b_h[ng][h*2], b_h[ng][h*2+1]);
                        mma16816(acc[mt][nt], a_h[mt], b_l[ng][h*2], b_l[ng][h*2+1]);
                        mma16816(acc[mt][nt], a_l[mt], b_h[ng][h*2], b_h[ng][h*2+1]);
                    }
            __syncthreads();
        }
    }

    // ---- epilogue ----
    #pragma unroll
    for (int mt = 0; mt < 2; mt++) {
        #pragma unroll
        for (int nt = 0; nt < 8; nt++) {
            int r0 = m0 + wm * 32 + mt * 16 + (lane >> 2);
            int c  = wn * 64 + nt * 8 + (lane & 3) * 2;
            float* a4 = acc[mt][nt];
            #pragma unroll
            for (int half = 0; half < 2; half++) {
                int r = r0 + half * 8;
                float v0 = a4[half * 2 + 0], v1 = a4[half * 2 + 1];
                if (EPI >= 1 && EPI != 9) {
                    float2 bb = *(const float2*)(bias + c);
                    v0 += bb.x; v1 += bb.y;
                }
                if (EPI == 6 || EPI == 7) { v0 = fmaxf(v0, 0.f); v1 = fmaxf(v1, 0.f); }
                if (EPI == 8) {
                    if (blockIdx.y == 0) {
                        v0 = 1.f / (1.f + __expf(-v0));
                        v1 = 1.f / (1.f + __expf(-v1));
                    } else {
                        v0 = tanhf(v0); v1 = tanhf(v1);
                    }
                }
                if (EPI == 9) {
                    __half2 hp = __floats2half2_rn(v0, v1);
                    *(__half2*)((__half*)g.Ch + (size_t)r * 128 + c) = hp;
                } else if (EPI == 6) {
                    uint32_t h, l;
                    splitpair(v0, v1, h, l);
                    *(uint32_t*)(g.Ch + (size_t)r * 128 + c) = h;
                    *(uint32_t*)(g.Cl + (size_t)r * 128 + c) = l;
                } else if (EPI == 7) {
                    __nv_bfloat16 h0 = __float2bfloat16_rn(v0);
                    __nv_bfloat16 h1 = __float2bfloat16_rn(v1);
                    g.Ch[(size_t)c * g.ldc + r]       = h0;
                    g.Ch[(size_t)(c + 1) * g.ldc + r] = h1;
                    g.Cl[(size_t)c * g.ldc + r]       = __float2bfloat16_rn(v0 - __bfloat162float(h0));
                    g.Cl[(size_t)(c + 1) * g.ldc + r] = __float2bfloat16_rn(v1 - __bfloat162float(h1));
                } else {
                    float* p = C + (size_t)r * g.ldc + c;
                    float2 o; o.x = v0; o.y = v1;
                    *(float2*)p = o;
                }
            }
        }
    }
}

// =============== fused flash attention (split-KV, cp.async K/G pipeline) ====
#define FB_QH 0
#define FB_QL 17408
#define FB_BUF0 34816
#define FB_STRIDE 35840
#define FK_LO 9216
#define FG_HI 18432
#define FG_LO 27136
#define FSMEM2 ((34816 + 2*35840) * 2)   // 212992 B

__global__ void __launch_bounds__(256) flash_attn(
    const __nv_bfloat16* __restrict__ qh, const __nv_bfloat16* __restrict__ ql,
    const __nv_bfloat16* __restrict__ kmh, const __nv_bfloat16* __restrict__ kml,
    const __nv_bfloat16* __restrict__ gh, const __nv_bfloat16* __restrict__ gl,
    __half* __restrict__ Opart, float* __restrict__ pm, float* __restrict__ pl)
{
    extern __shared__ __align__(16) __nv_bfloat16 fsm[];
    int qt = blockIdx.x, b = blockIdx.y, sp = blockIdx.z;
    int tid = threadIdx.x, wid = tid >> 5, lane = tid & 31;
    int qrow0 = b * LQ + qt * 128;
    int kb0 = b * NPER + sp * KEYS_PER;
    uint32_t sbase = smem_u32(fsm);

    auto fillKG = [&](int kt) {
        int p = kt & 1;
        int kb = kb0 + kt * KT;
        uint32_t base = sbase + (uint32_t)(FB_BUF0 + p * FB_STRIDE) * 2;
        #pragma unroll
        for (int i = 0; i < 4; i++) {
            int idx = tid + i * 256;
            int e = idx >> 3, kq = (idx & 7) * 8;
            uint32_t dk = base + (uint32_t)(e * 72 + kq) * 2;
            CP16(dk, kmh + (size_t)e * NTOT + kb + kq);
            CP16(dk + FK_LO * 2, kml + (size_t)e * NTOT + kb + kq);
        }
        #pragma unroll
        for (int i = 0; i < 4; i++) {
            int idx = tid + i * 256;
            int ky = idx >> 4, eq = (idx & 15) * 8;
            uint32_t dg = base + (uint32_t)(FG_HI + ky * 136 + eq) * 2;
            CP16(dg, gh + (size_t)(kb + ky) * 128 + eq);
            CP16(dg + (FG_LO - FG_HI) * 2, gl + (size_t)(kb + ky) * 128 + eq);
        }
    };

    fillKG(0); CPCOMMIT();
    #pragma unroll
    for (int i = 0; i < 16; i++) {
        int idx = tid + i * 256;
        int r = idx >> 5, cq = idx & 31;
        size_t go = (size_t)(qrow0 + r) * 128 + cq * 4;
        *(uint2*)&fsm[FB_QH + r * 136 + cq * 4] = *(const uint2*)(qh + go);
        *(uint2*)&fsm[FB_QL + r * 136 + cq * 4] = *(const uint2*)(ql + go);
    }
    __syncthreads();

    int arow = lane & 15, akoff = (lane >> 4) * 8;
    int bkrow = (lane & 7) + ((lane >> 3) & 1) * 8;
    int bnoff = (lane >> 4) * 8;

    uint32_t qah[8][4], qal[8][4];
    #pragma unroll
    for (int kc = 0; kc < 8; kc++) {
        uint32_t qoff = (uint32_t)(((wid * 16 + arow) * 136 + kc * 16 + akoff) * 2);
        ldsm_x4(qah[kc], sbase + FB_QH * 2 + qoff);
        ldsm_x4(qal[kc], sbase + FB_QL * 2 + qoff);
    }

    float Oc[16][4];
    #pragma unroll
    for (int i = 0; i < 16; i++)
        #pragma unroll
        for (int j = 0; j < 4; j++) Oc[i][j] = 0.f;
    float m0 = -1e30f, m1 = -1e30f, l0 = 0.f, l1 = 0.f;

    constexpr int NKT = KEYS_PER / KT;   // 8
    for (int kt = 0; kt < NKT; kt++) {
        if (kt + 1 < NKT) { fillKG(kt + 1); CPCOMMIT(); CPWAIT1(); }
        else              { CPWAIT0(); }
        __syncthreads();

        int p = kt & 1;
        uint32_t sK_h = sbase + (uint32_t)(FB_BUF0 + p * FB_STRIDE) * 2;
        uint32_t sK_l = sK_h + FK_LO * 2;
        uint32_t sG_h = sK_h + FG_HI * 2;
        uint32_t sG_l = sK_h + FG_LO * 2;

        float S[8][4];
        #pragma unroll
        for (int i = 0; i < 8; i++)
            #pragma unroll
            for (int j = 0; j < 4; j++) S[i][j] = 0.f;

        #pragma unroll
        for (int kc = 0; kc < 8; kc++) {
            #pragma unroll
            for (int ng = 0; ng < 4; ng++) {
                uint32_t bh[4], bl[4];
                uint32_t koff = (uint32_t)(((kc * 16 + bkrow) * 72 + ng * 16 + bnoff) * 2);
                ldsm_x4t(bh, sK_h + koff);
                ldsm_x4t(bl, sK_l + koff);
                #pragma unroll
                for (int h = 0; h < 2; h++) {
                    int nt = ng * 2 + h;
                    mma16816(S[nt], qah[kc], bh[h*2], bh[h*2+1]);
                    mma16816(S[nt], qah[kc], bl[h*2], bl[h*2+1]);
                    mma16816(S[nt], qal[kc], bh[h*2], bh[h*2+1]);
                }
            }
        }

        float r0 = -1e30f, r1 = -1e30f;
        #pragma unroll
        for (int nt = 0; nt < 8; nt++) {
            r0 = fmaxf(r0, fmaxf(S[nt][0], S[nt][1]));
            r1 = fmaxf(r1, fmaxf(S[nt][2], S[nt][3]));
        }
        r0 = fmaxf(r0, __shfl_xor_sync(~0u, r0, 1));
        r0 = fmaxf(r0, __shfl_xor_sync(~0u, r0, 2));
        r1 = fmaxf(r1, __shfl_xor_sync(~0u, r1, 1));
        r1 = fmaxf(r1, __shfl_xor_sync(~0u, r1, 2));
        float mn0 = fmaxf(m0, r0), mn1 = fmaxf(m1, r1);
        float sc0 = __expf(m0 - mn0), sc1 = __expf(m1 - mn1);
        float rs0 = 0.f, rs1 = 0.f;
        #pragma unroll
        for (int nt = 0; nt < 8; nt++) {
            S[nt][0] = __expf(S[nt][0] - mn0);
            S[nt][1] = __expf(S[nt][1] - mn0);
            S[nt][2] = __expf(S[nt][2] - mn1);
            S[nt][3] = __expf(S[nt][3] - mn1);
            rs0 += S[nt][0] + S[nt][1];
            rs1 += S[nt][2] + S[nt][3];
        }
        rs0 += __shfl_xor_sync(~0u, rs0, 1);
        rs0 += __shfl_xor_sync(~0u, rs0, 2);
        rs1 += __shfl_xor_sync(~0u, rs1, 1);
        rs1 += __shfl_xor_sync(~0u, rs1, 2);
        l0 = l0 * sc0 + rs0;
        l1 = l1 * sc1 + rs1;
        m0 = mn0; m1 = mn1;
        #pragma unroll
        for (int nt = 0; nt < 16; nt++) {
            Oc[nt][0] *= sc0; Oc[nt][1] *= sc0;
            Oc[nt][2] *= sc1; Oc[nt][3] *= sc1;
        }

        #pragma unroll
        for (int j = 0; j < 4; j++) {
            uint32_t ph[4];
            ph[0] = packbf(S[2*j][0],   S[2*j][1]);
            ph[1] = packbf(S[2*j][2],   S[2*j][3]);
            ph[2] = packbf(S[2*j+1][0], S[2*j+1][1]);
            ph[3] = packbf(S[2*j+1][2], S[2*j+1][3]);
            #pragma unroll
            for (int ng = 0; ng < 8; ng++) {
                uint32_t gh4[4], gl4[4];
                uint32_t goff = (uint32_t)(((j * 16 + bkrow) * 136 + ng * 16 + bnoff) * 2);
                ldsm_x4t(gh4, sG_h + goff);
                ldsm_x4t(gl4, sG_l + goff);
                #pragma unroll
                for (int h = 0; h < 2; h++) {
                    int nt = ng * 2 + h;
                    mma16816(Oc[nt], ph, gh4[h*2], gh4[h*2+1]);
                    mma16816(Oc[nt], ph, gl4[h*2], gl4[h*2+1]);
                }
            }
        }
        __syncthreads();
    }

    int rr0 = qrow0 + wid * 16 + (lane >> 2);
    int rr1 = rr0 + 8;
    __half* Ob = Opart + (size_t)sp * NROWS * 128;
    #pragma unroll
    for (int nt = 0; nt < 16; nt++) {
        int c = nt * 8 + (lane & 3) * 2;
        __half2 o0 = __floats2half2_rn(Oc[nt][0], Oc[nt][1]);
        __half2 o1 = __floats2half2_rn(Oc[nt][2], Oc[nt][3]);
        *(__half2*)(Ob + (size_t)rr0 * 128 + c) = o0;
        *(__half2*)(Ob + (size_t)rr1 * 128 + c) = o1;
    }
    if ((lane & 3) == 0) {
        pm[sp * NROWS + rr0] = m0; pm[sp * NROWS + rr1] = m1;
        pl[sp * NROWS + rr0] = l0; pl[sp * NROWS + rr1] = l1;
    }
}

__global__ void __launch_bounds__(256) flash_combine(
    const __half* __restrict__ Opart, const float* __restrict__ pm,
    const float* __restrict__ pl, float* __restrict__ H)
{
    int row = blockIdx.x * 8 + (threadIdx.x >> 5);
    int lane = threadIdx.x & 31;
    float ms = -1e30f;
    #pragma unroll
    for (int s = 0; s < SPLIT; s++) ms = fmaxf(ms, pm[s * NROWS + row]);
    float w[SPLIT]; float lt = 0.f;
    #pragma unroll
    for (int s = 0; s < SPLIT; s++) {
        w[s] = __expf(pm[s * NROWS + row] - ms);
        lt += w[s] * pl[s * NROWS + row];
    }
    float4 acc = make_float4(0.f, 0.f, 0.f, 0.f);
    #pragma unroll
    for (int s = 0; s < SPLIT; s++) {
        uint2 raw = *(const uint2*)(Opart + ((size_t)s * NROWS + row) * 128 + lane * 4);
        float2 f0 = __half22float2(*(__half2*)&raw.x);
        float2 f1 = __half22float2(*(__half2*)&raw.y);
        acc.x += w[s] * f0.x; acc.y += w[s] * f0.y;
        acc.z += w[s] * f1.x; acc.w += w[s] * f1.y;
    }
    float inv = 1.f / lt;
    acc.x *= inv; acc.y *= inv; acc.z *= inv; acc.w *= inv;
    *(float4*)(H + (size_t)row * 128 + lane * 4) = acc;
}

// ---------------- orchestration ---------------------------------------------
extern "C" void kernel_launch(void* const* d_in, const int* in_sizes, int n_in,
                              void* d_out, int out_size) {
    const float* x    = (const float*)d_in[0];
    const float* nfr  = (const float*)d_in[1];
    const int*   eidx = (const int*)d_in[2];
    const int*   hidx = (const int*)d_in[3];
    const float* Wg1  = (const float*)d_in[4];   const float* bg1 = (const float*)d_in[5];
    const float* Wg2  = (const float*)d_in[6];   const float* bg2 = (const float*)d_in[7];
    const float* Wh1  = (const float*)d_in[8];   const float* bh1 = (const float*)d_in[9];
    const float* Wh2  = (const float*)d_in[10];  const float* bh2 = (const float*)d_in[11];
    const float* Wm   = (const float*)d_in[12];  const float* bm  = (const float*)d_in[13];
    const float* Wm2  = (const float*)d_in[14];  const float* bm2 = (const float*)d_in[15];
    const float* Ws   = (const float*)d_in[16];  const float* bsv = (const float*)d_in[17];
    const float* Wt   = (const float*)d_in[18];  const float* bt  = (const float*)d_in[19];
    float* out = (float*)d_out;

    float *t_, *ef_, *H_, *Op_, *pm_, *pl_;
    float *rsout_, *rsin_, *Dinv_, *Binv_;
    __nv_bfloat16 *aggh_, *aggl_, *vh_, *vl_, *qh_, *ql_, *kmh_, *kml_, *gh_, *gl_, *wh_, *wl_;
    int *offe_, *cole_, *offhn_, *colhn_, *offhe_, *colhe_;
    cudaGetSymbolAddress((void**)&t_,   d_t);
    cudaGetSymbolAddress((void**)&ef_,  d_ef);
    cudaGetSymbolAddress((void**)&H_,   d_H);
    cudaGetSymbolAddress((void**)&Op_,  d_Op);
    cudaGetSymbolAddress((void**)&pm_,  d_pm);
    cudaGetSymbolAddress((void**)&pl_,  d_pl);
    cudaGetSymbolAddress((void**)&aggh_, d_aggh);
    cudaGetSymbolAddress((void**)&aggl_, d_aggl);
    cudaGetSymbolAddress((void**)&vh_,  d_vh);
    cudaGetSymbolAddress((void**)&vl_,  d_vl);
    cudaGetSymbolAddress((void**)&qh_,  d_qh);
    cudaGetSymbolAddress((void**)&ql_,  d_ql);
    cudaGetSymbolAddress((void**)&kmh_, d_kmh);
    cudaGetSymbolAddress((void**)&kml_, d_kml);
    cudaGetSymbolAddress((void**)&gh_,  d_gh);
    cudaGetSymbolAddress((void**)&gl_,  d_gl);
    cudaGetSymbolAddress((void**)&wh_,  d_wh);
    cudaGetSymbolAddress((void**)&wl_,  d_wl);
    cudaGetSymbolAddress((void**)&rsout_, d_rsout);
    cudaGetSymbolAddress((void**)&rsin_,  d_rsin);
    cudaGetSymbolAddress((void**)&Dinv_,  d_Dinv);
    cudaGetSymbolAddress((void**)&Binv_,  d_Binv);
    cudaGetSymbolAddress((void**)&offe_,  d_off_e);
    cudaGetSymbolAddress((void**)&cole_,  d_col_e);
    cudaGetSymbolAddress((void**)&offhn_, d_off_hn);
    cudaGetSymbolAddress((void**)&colhn_, d_col_hn);
    cudaGetSymbolAddress((void**)&offhe_, d_off_he);
    cudaGetSymbolAddress((void**)&colhe_, d_col_he);
    __half* th_  = (__half*)t_;
    __half* efh_ = (__half*)ef_;
    __half* Oph_ = (__half*)Op_;

    cudaFuncSetAttribute(flash_attn, cudaFuncAttributeMaxDynamicSharedMemorySize, FSMEM2);
    dim3 thr(256);

    zero_counts<<<NTOT / 256, thr>>>();
    count_all<<<NE / 256 + NP / 256, thr>>>(eidx, hidx);
    PSArgs ps;
    ps.s[0] = Wg1; ps.s[1] = Wh1; ps.s[2] = Wg2; ps.s[3] = Wh2;
    ps.s[4] = Wm2; ps.s[5] = Wm;  ps.s[6] = Ws;  ps.s[7] = Wt;
    presplit_all<<<304, thr>>>(ps, wh_, wl_);
    // ncu slot: ga0 = nfr @ Wg1 (MODE1, half-out)
    MArgs ga0 = {};
    ga0.A = nfr; ga0.lda = 128; ga0.Bh = wh_ + OFF_WG1; ga0.Bl = wl_ + OFF_WG1; ga0.ldb = 128;
    ga0.Ch = (__nv_bfloat16*)th_; ga0.K = 128;
    mma_gemm<0, 9, 1><<<dim3(NTOT / 128, 1, 1), thr>>>(ga0);
    finalize_scales<<<NTOT / 256, thr>>>();
    scan1c<<<528, thr>>>();
    scan2c<<<3, thr>>>();
    scan3c<<<528, thr>>>();
    fill_all<<<NE / 256 + NP / 256, thr>>>(eidx, hidx);

    for (int layer = 0; layer < 2; layer++) {
        const float* bgv = layer ? bg2 : bg1;
        int whoff = layer ? OFF_WH2 : OFF_WH1;

        if (layer == 1) {
            MArgs ga = {};
            ga.Ah = vh_; ga.Al = vl_;
            ga.Bh = wh_ + OFF_WG2; ga.Bl = wl_ + OFF_WG2; ga.ldb = 128;
            ga.Ch = (__nv_bfloat16*)th_; ga.K = 128;
            mma_gemm<0, 9, 2><<<dim3(NTOT / 128, 1, 1), thr>>>(ga);
            gather_k<2, false, false><<<NTOT / 16, thr>>>(offe_, cole_, th_, nullptr,
                nullptr, nullptr, rsin_, bgv, nullptr, nullptr, aggh_, aggl_);
        } else {
            gather_k<2, false, true><<<NTOT / 16, thr>>>(offe_, cole_, th_, nullptr,
                nullptr, rsout_, rsin_, bgv, nullptr, nullptr, aggh_, aggl_);
        }

        MArgs gb = {};
        gb.Ah = aggh_; gb.Al = aggl_;
        gb.Bh = wh_ + whoff; gb.Bl = wl_ + whoff; gb.ldb = 128;
        gb.Ch = (__nv_bfloat16*)th_; gb.K = 128;
        mma_gemm<0, 9, 2><<<dim3(NTOT / 128, 1, 1), thr>>>(gb);

        gather_k<4, true, false><<<NHE / 16, thr>>>(offhe_, colhe_, th_, efh_,
            Binv_, nullptr, nullptr, nullptr, nullptr, nullptr, nullptr, nullptr);
        if (layer == 0) {
            gather_k<3, false, false><<<NTOT / 16, thr>>>(offhn_, colhn_, efh_, nullptr,
                nullptr, nullptr, Dinv_, bh1, nfr, rsout_, vh_, vl_);
        } else {
            gather_k<1, false, false><<<NTOT / 16, thr>>>(offhn_, colhn_, efh_, nullptr,
                nullptr, nullptr, Dinv_, bh2, nfr, nullptr, gh_, gl_);
        }
    }

    // q = relu(x @ Wm + bm) -> bf16 hi/lo
    MArgs gq = {};
    gq.A = x; gq.lda = ENCD; gq.Bh = wh_ + OFF_WM; gq.Bl = wl_ + OFF_WM; gq.ldb = 128;
    gq.Ch = qh_; gq.Cl = ql_; gq.K = ENCD; gq.bias = bm;
    mma_gemm<0, 6, 0><<<dim3(NROWS / 128, 1, 1), thr>>>(gq);

    // kmT = relu(g @ Wm2 + bm2)^T -> bf16 hi/lo
    MArgs gk = {};
    gk.Ah = gh_; gk.Al = gl_;
    gk.Bh = wh_ + OFF_WM2; gk.Bl = wl_ + OFF_WM2; gk.ldb = 128;
    gk.Ch = kmh_; gk.Cl = kml_; gk.ldc = NTOT; gk.K = 128; gk.bias = bm2;
    mma_gemm<0, 7, 2><<<dim3(NTOT / 128, 1, 1), thr>>>(gk);

    flash_attn<<<dim3(4, BSZ, SPLIT), thr, FSMEM2>>>(qh_, ql_, kmh_, kml_, gh_, gl_,
                                                     Oph_, pm_, pl_);
    flash_combine<<<NROWS / 8, thr>>>(Oph_, pm_, pl_, H_);

    MArgs ghd = {};
    ghd.A = x; ghd.lda = ENCD;
    ghd.Bh = wh_ + OFF_WS; ghd.Bl = wl_ + OFF_WS; ghd.ldb = 128;
    ghd.Bh2 = wh_ + OFF_WT; ghd.Bl2 = wl_ + OFF_WT;
    ghd.C = out; ghd.ldc = 256; ghd.K = ENCD + EMB;
    ghd.padd = H_; ghd.ldadd = 128; ghd.bias = bsv; ghd.bias2 = bt;
    mma_gemm<4, 8, 0><<<dim3(NROWS / 128, 2, 1), thr>>>(ghd);
}

// round 14
// speedup vs baseline: 1.0964x; 1.0964x over previous
#include <cuda_runtime.h>
#include <cuda_bf16.h>
#include <cuda_fp16.h>
#include <cstdint>

#define BSZ   8
#define NPER  8192
#define NTOT  65536
#define EMB   128
#define ENCD  512
#define LQ    512
#define NE    1048576
#define NHE   4096
#define NP    1048576
#define NROWS (BSZ*LQ)   // 4096
#define SPLIT 16
#define KEYS_PER (NPER/SPLIT)   // 512
#define KT    64

#define LDKA 24
#define LDNB 136

__device__ __forceinline__ uint32_t smem_u32(const void* p) {
    uint32_t a;
    asm("{ .reg .u64 t; cvta.to.shared.u64 t, %1; cvt.u32.u64 %0, t; }"
        : "=r"(a) : "l"(p));
    return a;
}
__device__ __forceinline__ void ldsm_x4(uint32_t* r, uint32_t addr) {
    asm volatile("ldmatrix.sync.aligned.m8n8.x4.shared.b16 {%0,%1,%2,%3}, [%4];"
                 : "=r"(r[0]), "=r"(r[1]), "=r"(r[2]), "=r"(r[3]) : "r"(addr));
}
__device__ __forceinline__ void ldsm_x4t(uint32_t* r, uint32_t addr) {
    asm volatile("ldmatrix.sync.aligned.m8n8.x4.trans.shared.b16 {%0,%1,%2,%3}, [%4];"
                 : "=r"(r[0]), "=r"(r[1]), "=r"(r[2]), "=r"(r[3]) : "r"(addr));
}
__device__ __forceinline__ void mma16816(float* c, const uint32_t* a,
                                         uint32_t b0, uint32_t b1) {
    asm volatile("mma.sync.aligned.m16n8k16.row.col.f32.bf16.bf16.f32 "
                 "{%0,%1,%2,%3}, {%4,%5,%6,%7}, {%8,%9}, {%0,%1,%2,%3};"
                 : "+f"(c[0]), "+f"(c[1]), "+f"(c[2]), "+f"(c[3])
                 : "r"(a[0]), "r"(a[1]), "r"(a[2]), "r"(a[3]), "r"(b0), "r"(b1));
}
__device__ __forceinline__ void split4(float4 av, uint2& hp, uint2& lp) {
    __nv_bfloat162 h0, h1, l0, l1;
    h0.x = __float2bfloat16_rn(av.x); h0.y = __float2bfloat16_rn(av.y);
    h1.x = __float2bfloat16_rn(av.z); h1.y = __float2bfloat16_rn(av.w);
    l0.x = __float2bfloat16_rn(av.x - __bfloat162float(h0.x));
    l0.y = __float2bfloat16_rn(av.y - __bfloat162float(h0.y));
    l1.x = __float2bfloat16_rn(av.z - __bfloat162float(h1.x));
    l1.y = __float2bfloat16_rn(av.w - __bfloat162float(h1.y));
    hp.x = *(uint32_t*)&h0; hp.y = *(uint32_t*)&h1;
    lp.x = *(uint32_t*)&l0; lp.y = *(uint32_t*)&l1;
}
__device__ __forceinline__ void splitpair(float a, float b, uint32_t& h, uint32_t& l) {
    __nv_bfloat162 hh, ll;
    hh.x = __float2bfloat16_rn(a); hh.y = __float2bfloat16_rn(b);
    ll.x = __float2bfloat16_rn(a - __bfloat162float(hh.x));
    ll.y = __float2bfloat16_rn(b - __bfloat162float(hh.y));
    h = *(uint32_t*)&hh; l = *(uint32_t*)&ll;
}
__device__ __forceinline__ uint32_t packbf(float a, float b) {
    __nv_bfloat162 h;
    h.x = __float2bfloat16_rn(a); h.y = __float2bfloat16_rn(b);
    return *(uint32_t*)&h;
}

#define CP16(s, gp) asm volatile("cp.async.ca.shared.global [%0], [%1], 16;" :: "r"(s), "l"(gp))
#define CPCOMMIT()  asm volatile("cp.async.commit_group;" ::: "memory")
#define CPWAIT1()   asm volatile("cp.async.wait_group 1;" ::: "memory")
#define CPWAIT0()   asm volatile("cp.async.wait_group 0;" ::: "memory")

// ---------------- scratch ----------------------------------------------------
__device__ float d_t  [(size_t)NTOT*EMB];      // reused as __half buffer
__device__ float d_ef [(size_t)NTOT*EMB];      // reused as __half buffer
__device__ float d_H  [(size_t)NROWS*EMB];
__device__ float d_Op [(size_t)SPLIT*NROWS*EMB];   // reused as __half buffer
__device__ float d_pm [SPLIT*NROWS], d_pl[SPLIT*NROWS];
__device__ __nv_bfloat16 d_aggh[(size_t)NTOT*EMB], d_aggl[(size_t)NTOT*EMB];
__device__ __nv_bfloat16 d_vh  [(size_t)NTOT*EMB], d_vl  [(size_t)NTOT*EMB];
__device__ __nv_bfloat16 d_qh[(size_t)NROWS*EMB],  d_ql[(size_t)NROWS*EMB];
__device__ __nv_bfloat16 d_kmh[(size_t)EMB*NTOT],  d_kml[(size_t)EMB*NTOT];
__device__ __nv_bfloat16 d_gh[(size_t)NTOT*EMB],   d_gl[(size_t)NTOT*EMB];
#define OFF_WG1 0
#define OFF_WH1 16384
#define OFF_WG2 32768
#define OFF_WH2 49152
#define OFF_WM2 65536
#define OFF_WM  81920
#define OFF_WS  147456
#define OFF_WT  229376
__device__ __nv_bfloat16 d_wh[311296], d_wl[311296];
__device__ float d_rsout[NTOT], d_rsin[NTOT], d_Dinv[NTOT], d_Binv[NHE];
__device__ int   d_c0[NTOT], d_c1[NTOT], d_c2[NTOT], d_c3[NHE];
__device__ int d_off_e [NTOT+1], d_col_e [NE];
__device__ int d_off_hn[NTOT+1], d_col_hn[NP];
__device__ int d_off_he[NHE+1],  d_col_he[NP];
__device__ int d_cre[NTOT], d_crn[NTOT], d_crh[NHE];
__device__ int d_part3[3][257];

// ---------------- utility ----------------------------------------------------
struct PSArgs { const float* s[8]; };
__global__ void presplit_all(PSArgs a, __nv_bfloat16* __restrict__ hi,
                             __nv_bfloat16* __restrict__ lo) {
    const int bstart[8] = {0, 16, 32, 48, 64, 80, 144, 224};
    const int dstoff[8] = {0, 4096, 8192, 12288, 16384, 20480, 36864, 57344};
    int b = blockIdx.x;
    int seg = 0;
    #pragma unroll
    for (int s = 1; s < 8; s++) if (b >= bstart[s]) seg = s;
    int li = (b - bstart[seg]) * 256 + threadIdx.x;
    int n4 = (seg < 5) ? 4096 : (seg == 5 ? 16384 : 20480);
    if (li >= n4) return;
    float4 v = ((const float4*)a.s[seg])[li];
    uint2 hp, lp;
    split4(v, hp, lp);
    *(uint2*)(hi + ((size_t)dstoff[seg] + li) * 4) = hp;
    *(uint2*)(lo + ((size_t)dstoff[seg] + li) * 4) = lp;
}

__global__ void zero_counts() {
    int i = blockIdx.x * blockDim.x + threadIdx.x;
    if (i < NTOT) { d_c0[i] = 0; d_c1[i] = 0; d_c2[i] = 0; d_cre[i] = 0; d_crn[i] = 0; }
    if (i < NHE)  { d_c3[i] = 0; d_crh[i] = 0; }
}
__global__ void count_all(const int* __restrict__ eidx, const int* __restrict__ hidx) {
    int b = blockIdx.x, t = threadIdx.x;
    if (b < NE / 256) {
        int i = b * 256 + t;
        atomicAdd(&d_c0[eidx[i]], 1);
        atomicAdd(&d_c1[eidx[NE + i]], 1);
    } else {
        int i = (b - NE / 256) * 256 + t;
        atomicAdd(&d_c2[hidx[2 * i]], 1);
        atomicAdd(&d_c3[hidx[2 * i + 1]], 1);
    }
}
__global__ void finalize_scales() {
    int i = blockIdx.x * blockDim.x + threadIdx.x;
    if (i < NTOT) {
        d_rsout[i] = rsqrtf((float)max(d_c0[i], 1));
        d_rsin[i]  = rsqrtf((float)max(d_c1[i], 1));
        d_Dinv[i]  = d_c2[i] > 0 ? 1.f / (float)d_c2[i] : 0.f;
    }
    if (i < NHE) d_Binv[i] = d_c3[i] > 0 ? 1.f / (float)d_c3[i] : 0.f;
}

// ---------------- merged scans ----------------------------------------------
__global__ void scan1c() {
    int b = blockIdx.x;
    const int* cnt; int* off; int* part; int li;
    if (b < 256)      { cnt = d_c1; off = d_off_e;  part = d_part3[0]; li = b; }
    else if (b < 512) { cnt = d_c2; off = d_off_hn; part = d_part3[1]; li = b - 256; }
    else              { cnt = d_c3; off = d_off_he; part = d_part3[2]; li = b - 512; }
    __shared__ int sh[256];
    int t = threadIdx.x;
    int i = li * 256 + t;
    int v = cnt[i];
    sh[t] = v;
    __syncthreads();
    #pragma unroll
    for (int o = 1; o < 256; o <<= 1) {
        int add = (t >= o) ? sh[t - o] : 0;
        __syncthreads();
        sh[t] += add;
        __syncthreads();
    }
    off[i] = sh[t] - v;
    if (t == 255) part[li] = sh[255];
}
__global__ void scan2c() {
    int a = blockIdx.x;
    int nb = (a == 2) ? 16 : 256;
    int* part = d_part3[a];
    __shared__ int sh[256];
    int t = threadIdx.x;
    int v = (t < nb) ? part[t] : 0;
    sh[t] = v;
    __syncthreads();
    #pragma unroll
    for (int o = 1; o < 256; o <<= 1) {
        int add = (t >= o) ? sh[t - o] : 0;
        __syncthreads();
        sh[t] += add;
        __syncthreads();
    }
    part[t] = sh[t] - v;
    if (t == nb - 1) part[256] = sh[t];
}
__global__ void scan3c() {
    int b = blockIdx.x;
    int* off; int* part; int li; int n;
    if (b < 256)      { off = d_off_e;  part = d_part3[0]; li = b; n = NTOT; }
    else if (b < 512) { off = d_off_hn; part = d_part3[1]; li = b - 256; n = NTOT; }
    else              { off = d_off_he; part = d_part3[2]; li = b - 512; n = NHE; }
    int i = li * 256 + threadIdx.x;
    off[i] += part[li];
    if (i == 0) off[n] = part[256];
}

__global__ void fill_all(const int* __restrict__ eidx, const int* __restrict__ hidx) {
    int b = blockIdx.x, t = threadIdx.x;
    if (b < NE / 256) {
        int i = b * 256 + t;
        int s = eidx[i], d = eidx[NE + i];
        int p = atomicAdd(&d_cre[d], 1);
        d_col_e[d_off_e[d] + p] = s;
    } else {
        int i = (b - NE / 256) * 256 + t;
        int n = hidx[2 * i], e = hidx[2 * i + 1];
        int p1 = atomicAdd(&d_crn[n], 1);
        d_col_hn[d_off_hn[n] + p1] = e;
        int p2 = atomicAdd(&d_crh[e], 1);
        d_col_he[d_off_he[e] + p2] = n;
    }
}

// ---------------- CSR gather (fp16 in), warp-per-row --------------------------
// GEPI 4: scaled store -> half
// GEPI 2: (acc*s1[r]+pb[k]) -> bf16 hi/lo
// GEPI 3: ((relu(acc*s1[r]+pb[k])+padd[r,k])*s2[r]) -> bf16 hi/lo
// GEPI 1: (relu(acc*s1[r]+pb[k])+padd[r,k]) -> bf16 hi/lo
template<int GEPI, bool OSC, bool ISC>
__global__ void __launch_bounds__(256) gather_k(const int* __restrict__ off,
                                                const int* __restrict__ col,
                                                const __half* __restrict__ in,
                                                void* __restrict__ outp,
                                                const float* __restrict__ oscale,
                                                const float* __restrict__ iscale,
                                                const float* __restrict__ s1,
                                                const float* __restrict__ pb,
                                                const float* __restrict__ padd,
                                                const float* __restrict__ s2,
                                                __nv_bfloat16* __restrict__ oh,
                                                __nv_bfloat16* __restrict__ ol) {
    int r    = blockIdx.x * 8 + (threadIdx.x >> 5);
    int lane = threadIdx.x & 31;
    int b = off[r], e = off[r + 1];
    float4 acc = make_float4(0.f, 0.f, 0.f, 0.f);
    for (int j0 = b; j0 < e; j0 += 32) {
        int cj = 0;
        if (j0 + lane < e) cj = col[j0 + lane];
        int m = min(e - j0, 32);
        #pragma unroll 4
        for (int k = 0; k < m; k++) {
            int c = __shfl_sync(~0u, cj, k);
            uint2 raw = *(const uint2*)(in + (size_t)c * EMB + lane * 4);
            float2 f01 = __half22float2(*(__half2*)&raw.x);
            float2 f23 = __half22float2(*(__half2*)&raw.y);
            if (ISC) {
                float s = iscale[c];
                f01.x *= s; f01.y *= s; f23.x *= s; f23.y *= s;
            }
            acc.x += f01.x; acc.y += f01.y; acc.z += f23.x; acc.w += f23.y;
        }
    }
    if (OSC) {
        float s = oscale[r];
        acc.x *= s; acc.y *= s; acc.z *= s; acc.w *= s;
    }
    if (GEPI == 4) {
        __half2 o01 = __floats2half2_rn(acc.x, acc.y);
        __half2 o23 = __floats2half2_rn(acc.z, acc.w);
        uint2 st; st.x = *(uint32_t*)&o01; st.y = *(uint32_t*)&o23;
        *(uint2*)((__half*)outp + (size_t)r * EMB + lane * 4) = st;
        return;
    }
    float sr = s1[r];
    float4 bb = *(const float4*)(pb + lane * 4);
    acc.x = acc.x * sr + bb.x;
    acc.y = acc.y * sr + bb.y;
    acc.z = acc.z * sr + bb.z;
    acc.w = acc.w * sr + bb.w;
    if (GEPI == 3 || GEPI == 1) {
        float4 nn = *(const float4*)(padd + (size_t)r * EMB + lane * 4);
        acc.x = fmaxf(acc.x, 0.f) + nn.x;
        acc.y = fmaxf(acc.y, 0.f) + nn.y;
        acc.z = fmaxf(acc.z, 0.f) + nn.z;
        acc.w = fmaxf(acc.w, 0.f) + nn.w;
        if (GEPI == 3) {
            float so = s2[r];
            acc.x *= so; acc.y *= so; acc.z *= so; acc.w *= so;
        }
    }
    uint2 hp, lp;
    split4(acc, hp, lp);
    *(uint2*)(oh + (size_t)r * EMB + lane * 4) = hp;
    *(uint2*)(ol + (size_t)r * EMB + lane * 4) = lp;
}

// =============== mma.sync bf16-split GEMM ===================================
// MODE 0: chunked fp32 A (K=512/640) | MODE 1: B-res, fp32 A | MODE 2: B-res, pre-split A cp.async
// EPI: 0 fp32 | 6 relu+bias->hi/lo | 7 relu+bias->hi/lo transposed | 8 dual-head
//      | 9 plain store -> half (via Ch)
struct MArgs {
    const float* A; long lda;
    const __nv_bfloat16* Ah; const __nv_bfloat16* Al;
    const __nv_bfloat16* Bh; const __nv_bfloat16* Bl; long ldb;
    const __nv_bfloat16* Bh2; const __nv_bfloat16* Bl2;
    float* C; long ldc;
    __nv_bfloat16* Ch; __nv_bfloat16* Cl;
    int K;
    const float* padd; long ldadd;
    const float* bias; const float* bias2;
};

template<int PRO, int EPI, int MODE>
__global__ void __launch_bounds__(256, 2) mma_gemm(MArgs g) {
    constexpr int BROWS = (MODE >= 1) ? 128 : 16;
    constexpr int ABUF  = (MODE == 2) ? 3 : (MODE == 1 ? 2 : 1);
    __shared__ __align__(16) __nv_bfloat16 sAh[ABUF][128 * LDKA];
    __shared__ __align__(16) __nv_bfloat16 sAl[ABUF][128 * LDKA];
    __shared__ __align__(16) __nv_bfloat16 sBh[BROWS * LDNB];
    __shared__ __align__(16) __nv_bfloat16 sBl[BROWS * LDNB];

    const float* A = g.A;
    float* C = g.C;
    const __nv_bfloat16* Bh = g.Bh;
    const __nv_bfloat16* Bl = g.Bl;
    const float* bias = g.bias;
    if (EPI == 8 && blockIdx.y == 1) {
        Bh = g.Bh2; Bl = g.Bl2; bias = g.bias2; C = g.C + 128;
    }
    int m0 = blockIdx.x * 128;

    int tid = threadIdx.x, wid = tid >> 5, lane = tid & 31;
    int wm = wid >> 1, wn = wid & 1;

    float acc[2][8][4];
    #pragma unroll
    for (int i = 0; i < 2; i++)
        #pragma unroll
        for (int j = 0; j < 8; j++)
            #pragma unroll
            for (int q = 0; q < 4; q++) acc[i][j][q] = 0.f;

    uint32_t sBh_b = smem_u32(sBh), sBl_b = smem_u32(sBl);

    int arow = lane & 15, akoff = (lane >> 4) * 8;
    int bkrow = (lane & 7) + ((lane >> 3) & 1) * 8;
    int bnoff = (lane >> 4) * 8;

    if (MODE == 2) {
        #pragma unroll
        for (int i = 0; i < 16; i++) {
            int idx = tid + i * 256;
            int kr = idx >> 5, n = (idx & 31) * 4;
            size_t boff = (size_t)kr * g.ldb + n;
            *(uint2*)&sBh[kr * LDNB + n] = *(const uint2*)(Bh + boff);
            *(uint2*)&sBl[kr * LDNB + n] = *(const uint2*)(Bl + boff);
        }
        int row = tid >> 1, half = tid & 1;
        auto cpA = [&](int c) {
            int slot = c % 3;
            uint32_t sh_ = smem_u32(&sAh[slot][row * LDKA + half * 8]);
            uint32_t sl_ = smem_u32(&sAl[slot][row * LDKA + half * 8]);
            const __nv_bfloat16* gph = g.Ah + (size_t)(m0 + row) * 128 + c * 16 + half * 8;
            const __nv_bfloat16* gpl = g.Al + (size_t)(m0 + row) * 128 + c * 16 + half * 8;
            CP16(sh_, gph);
            CP16(sl_, gpl);
        };
        cpA(0); CPCOMMIT();
        cpA(1); CPCOMMIT();

        #pragma unroll
        for (int c = 0; c < 8; c++) {
            CPWAIT1();
            __syncthreads();
            if (c + 2 < 8) cpA(c + 2);
            CPCOMMIT();

            int slot = c % 3;
            uint32_t sAh_b = smem_u32(sAh[slot]), sAl_b = smem_u32(sAl[slot]);
            uint32_t a_h[2][4], a_l[2][4];
            #pragma unroll
            for (int mt = 0; mt < 2; mt++) {
                uint32_t off = (uint32_t)(((wm * 32 + mt * 16 + arow) * LDKA + akoff) * 2);
                ldsm_x4(a_h[mt], sAh_b + off);
                ldsm_x4(a_l[mt], sAl_b + off);
            }
            uint32_t b_h[4][4], b_l[4][4];
            #pragma unroll
            for (int ng = 0; ng < 4; ng++) {
                uint32_t off = (uint32_t)(((c * 16 + bkrow) * LDNB + wn * 64 + ng * 16 + bnoff) * 2);
                ldsm_x4t(b_h[ng], sBh_b + off);
                ldsm_x4t(b_l[ng], sBl_b + off);
            }
            #pragma unroll
            for (int mt = 0; mt < 2; mt++)
                #pragma unroll
                for (int ng = 0; ng < 4; ng++)
                    #pragma unroll
                    for (int h = 0; h < 2; h++) {
                        int nt = ng * 2 + h;
                        mma16816(acc[mt][nt], a_h[mt], b_h[ng][h*2], b_h[ng][h*2+1]);
                        mma16816(acc[mt][nt], a_h[mt], b_l[ng][h*2], b_l[ng][h*2+1]);
                        mma16816(acc[mt][nt], a_l[mt], b_h[ng][h*2], b_h[ng][h*2+1]);
                    }
        }
    } else if (MODE == 1) {
        float4 pAv[2];
        auto prefetchA = [&](int k0) {
            #pragma unroll
            for (int i = 0; i < 2; i++) {
                int idx = tid + i * 256;
                int r = idx >> 2, k = (idx & 3) * 4;
                pAv[i] = *(const float4*)(A + (size_t)(m0 + r) * g.lda + k0 + k);
            }
        };
        auto commitA = [&](int p) {
            #pragma unroll
            for (int i = 0; i < 2; i++) {
                int idx = tid + i * 256;
                int r = idx >> 2, k = (idx & 3) * 4;
                uint2 hp, lp;
                split4(pAv[i], hp, lp);
                *(uint2*)&sAh[p][r * LDKA + k] = hp;
                *(uint2*)&sAl[p][r * LDKA + k] = lp;
            }
        };
        #pragma unroll
        for (int i = 0; i < 16; i++) {
            int idx = tid + i * 256;
            int kr = idx >> 5, n = (idx & 31) * 4;
            size_t boff = (size_t)kr * g.ldb + n;
            *(uint2*)&sBh[kr * LDNB + n] = *(const uint2*)(Bh + boff);
            *(uint2*)&sBl[kr * LDNB + n] = *(const uint2*)(Bl + boff);
        }
        prefetchA(0);
        commitA(0);
        __syncthreads();
        #pragma unroll
        for (int c = 0; c < 8; c++) {
            int p = c & 1;
            uint32_t sAh_b = smem_u32(sAh[p]), sAl_b = smem_u32(sAl[p]);
            uint32_t a_h[2][4], a_l[2][4];
            #pragma unroll
            for (int mt = 0; mt < 2; mt++) {
                uint32_t off = (uint32_t)(((wm * 32 + mt * 16 + arow) * LDKA + akoff) * 2);
                ldsm_x4(a_h[mt], sAh_b + off);
                ldsm_x4(a_l[mt], sAl_b + off);
            }
            uint32_t b_h[4][4], b_l[4][4];
            #pragma unroll
            for (int ng = 0; ng < 4; ng++) {
                uint32_t off = (uint32_t)(((c * 16 + bkrow) * LDNB + wn * 64 + ng * 16 + bnoff) * 2);
                ldsm_x4t(b_h[ng], sBh_b + off);
                ldsm_x4t(b_l[ng], sBl_b + off);
            }
            if (c < 7) prefetchA((c + 1) * 16);
            #pragma unroll
            for (int mt = 0; mt < 2; mt++)
                #pragma unroll
                for (int ng = 0; ng < 4; ng++)
                    #pragma unroll
                    for (int h = 0; h < 2; h++) {
                        int nt = ng * 2 + h;
                        mma16816(acc[mt][nt], a_h[mt], b_h[ng][h*2], b_h[ng][h*2+1]);
                        mma16816(acc[mt][nt], a_h[mt], b_l[ng][h*2], b_l[ng][h*2+1]);
                        mma16816(acc[mt][nt], a_l[mt], b_h[ng][h*2], b_h[ng][h*2+1]);
                    }
            if (c < 7) {
                commitA(p ^ 1);
                __syncthreads();
            }
        }
    } else {
        uint32_t sAh_b = smem_u32(sAh[0]), sAl_b = smem_u32(sAl[0]);
        float4 pAv[2];
        uint2 pBhr[2], pBlr[2];
        auto prefetch = [&](int k0) {
            #pragma unroll
            for (int i = 0; i < 2; i++) {
                int idx = tid + i * 256;
                int r = idx >> 2, k = (idx & 3) * 4;
                int kk = k0 + k;
                if (PRO == 4) {
                    pAv[i] = (kk < ENCD)
                        ? *(const float4*)(A + (size_t)(m0 + r) * g.lda + kk)
                        : *(const float4*)(g.padd + (size_t)(m0 + r) * g.ldadd + (kk - ENCD));
                } else {
                    pAv[i] = *(const float4*)(A + (size_t)(m0 + r) * g.lda + kk);
                }
                int kr = idx >> 5, n = (idx & 31) * 4;
                size_t boff = (size_t)(k0 + kr) * g.ldb + n;
                pBhr[i] = *(const uint2*)(Bh + boff);
                pBlr[i] = *(const uint2*)(Bl + boff);
            }
        };
        auto commit = [&]() {
            #pragma unroll
            for (int i = 0; i < 2; i++) {
                int idx = tid + i * 256;
                int r = idx >> 2, k = (idx & 3) * 4;
                uint2 hp, lp;
                split4(pAv[i], hp, lp);
                *(uint2*)&sAh[0][r * LDKA + k] = hp;
                *(uint2*)&sAl[0][r * LDKA + k] = lp;
                int kr = idx >> 5, n = (idx & 31) * 4;
                *(uint2*)&sBh[kr * LDNB + n] = pBhr[i];
                *(uint2*)&sBl[kr * LDNB + n] = pBlr[i];
            }
        };
        prefetch(0);
        for (int k0 = 0; k0 < g.K; k0 += 16) {
            commit();
            __syncthreads();
            if (k0 + 16 < g.K) prefetch(k0 + 16);

            uint32_t a_h[2][4], a_l[2][4];
            #pragma unroll
            for (int mt = 0; mt < 2; mt++) {
                uint32_t off = (uint32_t)(((wm * 32 + mt * 16 + arow) * LDKA + akoff) * 2);
                ldsm_x4(a_h[mt], sAh_b + off);
                ldsm_x4(a_l[mt], sAl_b + off);
            }
            uint32_t b_h[4][4], b_l[4][4];
            #pragma unroll
            for (int ng = 0; ng < 4; ng++) {
                uint32_t off = (uint32_t)((bkrow * LDNB + wn * 64 + ng * 16 + bnoff) * 2);
                ldsm_x4t(b_h[ng], sBh_b + off);
                ldsm_x4t(b_l[ng], sBl_b + off);
            }
            #pragma unroll
            for (int mt = 0; mt < 2; mt++)
                #pragma unroll
                for (int ng = 0; ng < 4; ng++)
                    #pragma unroll
                    for (int h = 0; h < 2; h++) {
                        int nt = ng * 2 + h;
                        mma16816(acc[mt][nt], a_h[mt], b_h[ng][h*2], b_h[ng][h*2+1]);
                        mma16816(acc[mt][nt], a_h[mt], b_l[ng][h*2], b_l[ng][h*2+1]);
                        mma16816(acc[mt][nt], a_l[mt], b_h[ng][h*2], b_h[ng][h*2+1]);
                    }
            __syncthreads();
        }
    }

    // ---- epilogue ----
    #pragma unroll
    for (int mt = 0; mt < 2; mt++) {
        #pragma unroll
        for (int nt = 0; nt < 8; nt++) {
            int r0 = m0 + wm * 32 + mt * 16 + (lane >> 2);
            int c  = wn * 64 + nt * 8 + (lane & 3) * 2;
            float* a4 = acc[mt][nt];
            #pragma unroll
            for (int half = 0; half < 2; half++) {
                int r = r0 + half * 8;
                float v0 = a4[half * 2 + 0], v1 = a4[half * 2 + 1];
                if (EPI >= 1 && EPI != 9) {
                    float2 bb = *(const float2*)(bias + c);
                    v0 += bb.x; v1 += bb.y;
                }
                if (EPI == 6 || EPI == 7) { v0 = fmaxf(v0, 0.f); v1 = fmaxf(v1, 0.f); }
                if (EPI == 8) {
                    if (blockIdx.y == 0) {
                        v0 = 1.f / (1.f + __expf(-v0));
                        v1 = 1.f / (1.f + __expf(-v1));
                    } else {
                        v0 = tanhf(v0); v1 = tanhf(v1);
                    }
                }
                if (EPI == 9) {
                    __half2 hp = __floats2half2_rn(v0, v1);
                    *(__half2*)((__half*)g.Ch + (size_t)r * 128 + c) = hp;
                } else if (EPI == 6) {
                    uint32_t h, l;
                    splitpair(v0, v1, h, l);
                    *(uint32_t*)(g.Ch + (size_t)r * 128 + c) = h;
                    *(uint32_t*)(g.Cl + (size_t)r * 128 + c) = l;
                } else if (EPI == 7) {
                    __nv_bfloat16 h0 = __float2bfloat16_rn(v0);
                    __nv_bfloat16 h1 = __float2bfloat16_rn(v1);
                    g.Ch[(size_t)c * g.ldc + r]       = h0;
                    g.Ch[(size_t)(c + 1) * g.ldc + r] = h1;
                    g.Cl[(size_t)c * g.ldc + r]       = __float2bfloat16_rn(v0 - __bfloat162float(h0));
                    g.Cl[(size_t)(c + 1) * g.ldc + r] = __float2bfloat16_rn(v1 - __bfloat162float(h1));
                } else {
                    float* p = C + (size_t)r * g.ldc + c;
                    float2 o; o.x = v0; o.y = v1;
                    *(float2*)p = o;
                }
            }
        }
    }
}

// =============== fused flash attention (split-KV, cp.async K/G pipeline) ====
#define FB_QH 0
#define FB_QL 17408
#define FB_BUF0 34816
#define FB_STRIDE 35840
#define FK_LO 9216
#define FG_HI 18432
#define FG_LO 27136
#define FSMEM2 ((34816 + 2*35840) * 2)   // 212992 B

__global__ void __launch_bounds__(256) flash_attn(
    const __nv_bfloat16* __restrict__ qh, const __nv_bfloat16* __restrict__ ql,
    const __nv_bfloat16* __restrict__ kmh, const __nv_bfloat16* __restrict__ kml,
    const __nv_bfloat16* __restrict__ gh, const __nv_bfloat16* __restrict__ gl,
    __half* __restrict__ Opart, float* __restrict__ pm, float* __restrict__ pl)
{
    extern __shared__ __align__(16) __nv_bfloat16 fsm[];
    int qt = blockIdx.x, b = blockIdx.y, sp = blockIdx.z;
    int tid = threadIdx.x, wid = tid >> 5, lane = tid & 31;
    int qrow0 = b * LQ + qt * 128;
    int kb0 = b * NPER + sp * KEYS_PER;
    uint32_t sbase = smem_u32(fsm);

    auto fillKG = [&](int kt) {
        int p = kt & 1;
        int kb = kb0 + kt * KT;
        uint32_t base = sbase + (uint32_t)(FB_BUF0 + p * FB_STRIDE) * 2;
        #pragma unroll
        for (int i = 0; i < 4; i++) {
            int idx = tid + i * 256;
            int e = idx >> 3, kq = (idx & 7) * 8;
            uint32_t dk = base + (uint32_t)(e * 72 + kq) * 2;
            CP16(dk, kmh + (size_t)e * NTOT + kb + kq);
            CP16(dk + FK_LO * 2, kml + (size_t)e * NTOT + kb + kq);
        }
        #pragma unroll
        for (int i = 0; i < 4; i++) {
            int idx = tid + i * 256;
            int ky = idx >> 4, eq = (idx & 15) * 8;
            uint32_t dg = base + (uint32_t)(FG_HI + ky * 136 + eq) * 2;
            CP16(dg, gh + (size_t)(kb + ky) * 128 + eq);
            CP16(dg + (FG_LO - FG_HI) * 2, gl + (size_t)(kb + ky) * 128 + eq);
        }
    };

    fillKG(0); CPCOMMIT();
    #pragma unroll
    for (int i = 0; i < 16; i++) {
        int idx = tid + i * 256;
        int r = idx >> 5, cq = idx & 31;
        size_t go = (size_t)(qrow0 + r) * 128 + cq * 4;
        *(uint2*)&fsm[FB_QH + r * 136 + cq * 4] = *(const uint2*)(qh + go);
        *(uint2*)&fsm[FB_QL + r * 136 + cq * 4] = *(const uint2*)(ql + go);
    }
    __syncthreads();

    int arow = lane & 15, akoff = (lane >> 4) * 8;
    int bkrow = (lane & 7) + ((lane >> 3) & 1) * 8;
    int bnoff = (lane >> 4) * 8;

    uint32_t qah[8][4], qal[8][4];
    #pragma unroll
    for (int kc = 0; kc < 8; kc++) {
        uint32_t qoff = (uint32_t)(((wid * 16 + arow) * 136 + kc * 16 + akoff) * 2);
        ldsm_x4(qah[kc], sbase + FB_QH * 2 + qoff);
        ldsm_x4(qal[kc], sbase + FB_QL * 2 + qoff);
    }

    float Oc[16][4];
    #pragma unroll
    for (int i = 0; i < 16; i++)
        #pragma unroll
        for (int j = 0; j < 4; j++) Oc[i][j] = 0.f;
    float m0 = -1e30f, m1 = -1e30f, l0 = 0.f, l1 = 0.f;

    constexpr int NKT = KEYS_PER / KT;   // 8
    for (int kt = 0; kt < NKT; kt++) {
        if (kt + 1 < NKT) { fillKG(kt + 1); CPCOMMIT(); CPWAIT1(); }
        else              { CPWAIT0(); }
        __syncthreads();

        int p = kt & 1;
        uint32_t sK_h = sbase + (uint32_t)(FB_BUF0 + p * FB_STRIDE) * 2;
        uint32_t sK_l = sK_h + FK_LO * 2;
        uint32_t sG_h = sK_h + FG_HI * 2;
        uint32_t sG_l = sK_h + FG_LO * 2;

        float S[8][4];
        #pragma unroll
        for (int i = 0; i < 8; i++)
            #pragma unroll
            for (int j = 0; j < 4; j++) S[i][j] = 0.f;

        #pragma unroll
        for (int kc = 0; kc < 8; kc++) {
            #pragma unroll
            for (int ng = 0; ng < 4; ng++) {
                uint32_t bh[4], bl[4];
                uint32_t koff = (uint32_t)(((kc * 16 + bkrow) * 72 + ng * 16 + bnoff) * 2);
                ldsm_x4t(bh, sK_h + koff);
                ldsm_x4t(bl, sK_l + koff);
                #pragma unroll
                for (int h = 0; h < 2; h++) {
                    int nt = ng * 2 + h;
                    mma16816(S[nt], qah[kc], bh[h*2], bh[h*2+1]);
                    mma16816(S[nt], qah[kc], bl[h*2], bl[h*2+1]);
                    mma16816(S[nt], qal[kc], bh[h*2], bh[h*2+1]);
                }
            }
        }

        float r0 = -1e30f, r1 = -1e30f;
        #pragma unroll
        for (int nt = 0; nt < 8; nt++) {
            r0 = fmaxf(r0, fmaxf(S[nt][0], S[nt][1]));
            r1 = fmaxf(r1, fmaxf(S[nt][2], S[nt][3]));
        }
        r0 = fmaxf(r0, __shfl_xor_sync(~0u, r0, 1));
        r0 = fmaxf(r0, __shfl_xor_sync(~0u, r0, 2));
        r1 = fmaxf(r1, __shfl_xor_sync(~0u, r1, 1));
        r1 = fmaxf(r1, __shfl_xor_sync(~0u, r1, 2));
        float mn0 = fmaxf(m0, r0), mn1 = fmaxf(m1, r1);
        float sc0 = __expf(m0 - mn0), sc1 = __expf(m1 - mn1);
        float rs0 = 0.f, rs1 = 0.f;
        #pragma unroll
        for (int nt = 0; nt < 8; nt++) {
            S[nt][0] = __expf(S[nt][0] - mn0);
            S[nt][1] = __expf(S[nt][1] - mn0);
            S[nt][2] = __expf(S[nt][2] - mn1);
            S[nt][3] = __expf(S[nt][3] - mn1);
            rs0 += S[nt][0] + S[nt][1];
            rs1 += S[nt][2] + S[nt][3];
        }
        rs0 += __shfl_xor_sync(~0u, rs0, 1);
        rs0 += __shfl_xor_sync(~0u, rs0, 2);
        rs1 += __shfl_xor_sync(~0u, rs1, 1);
        rs1 += __shfl_xor_sync(~0u, rs1, 2);
        l0 = l0 * sc0 + rs0;
        l1 = l1 * sc1 + rs1;
        m0 = mn0; m1 = mn1;
        #pragma unroll
        for (int nt = 0; nt < 16; nt++) {
            Oc[nt][0] *= sc0; Oc[nt][1] *= sc0;
            Oc[nt][2] *= sc1; Oc[nt][3] *= sc1;
        }

        #pragma unroll
        for (int j = 0; j < 4; j++) {
            uint32_t ph[4];
            ph[0] = packbf(S[2*j][0],   S[2*j][1]);
            ph[1] = packbf(S[2*j][2],   S[2*j][3]);
            ph[2] = packbf(S[2*j+1][0], S[2*j+1][1]);
            ph[3] = packbf(S[2*j+1][2], S[2*j+1][3]);
            #pragma unroll
            for (int ng = 0; ng < 8; ng++) {
                uint32_t gh4[4], gl4[4];
                uint32_t goff = (uint32_t)(((j * 16 + bkrow) * 136 + ng * 16 + bnoff) * 2);
                ldsm_x4t(gh4, sG_h + goff);
                ldsm_x4t(gl4, sG_l + goff);
                #pragma unroll
                for (int h = 0; h < 2; h++) {
                    int nt = ng * 2 + h;
                    mma16816(Oc[nt], ph, gh4[h*2], gh4[h*2+1]);
                    mma16816(Oc[nt], ph, gl4[h*2], gl4[h*2+1]);
                }
            }
        }
        __syncthreads();
    }

    int rr0 = qrow0 + wid * 16 + (lane >> 2);
    int rr1 = rr0 + 8;
    __half* Ob = Opart + (size_t)sp * NROWS * 128;
    #pragma unroll
    for (int nt = 0; nt < 16; nt++) {
        int c = nt * 8 + (lane & 3) * 2;
        __half2 o0 = __floats2half2_rn(Oc[nt][0], Oc[nt][1]);
        __half2 o1 = __floats2half2_rn(Oc[nt][2], Oc[nt][3]);
        *(__half2*)(Ob + (size_t)rr0 * 128 + c) = o0;
        *(__half2*)(Ob + (size_t)rr1 * 128 + c) = o1;
    }
    if ((lane & 3) == 0) {
        pm[sp * NROWS + rr0] = m0; pm[sp * NROWS + rr1] = m1;
        pl[sp * NROWS + rr0] = l0; pl[sp * NROWS + rr1] = l1;
    }
}

__global__ void __launch_bounds__(256) flash_combine(
    const __half* __restrict__ Opart, const float* __restrict__ pm,
    const float* __restrict__ pl, float* __restrict__ H)
{
    int row = blockIdx.x * 8 + (threadIdx.x >> 5);
    int lane = threadIdx.x & 31;
    float ms = -1e30f;
    #pragma unroll
    for (int s = 0; s < SPLIT; s++) ms = fmaxf(ms, pm[s * NROWS + row]);
    float w[SPLIT]; float lt = 0.f;
    #pragma unroll
    for (int s = 0; s < SPLIT; s++) {
        w[s] = __expf(pm[s * NROWS + row] - ms);
        lt += w[s] * pl[s * NROWS + row];
    }
    float4 acc = make_float4(0.f, 0.f, 0.f, 0.f);
    #pragma unroll
    for (int s = 0; s < SPLIT; s++) {
        uint2 raw = *(const uint2*)(Opart + ((size_t)s * NROWS + row) * 128 + lane * 4);
        float2 f0 = __half22float2(*(__half2*)&raw.x);
        float2 f1 = __half22float2(*(__half2*)&raw.y);
        acc.x += w[s] * f0.x; acc.y += w[s] * f0.y;
        acc.z += w[s] * f1.x; acc.w += w[s] * f1.y;
    }
    float inv = 1.f / lt;
    acc.x *= inv; acc.y *= inv; acc.z *= inv; acc.w *= inv;
    *(float4*)(H + (size_t)row * 128 + lane * 4) = acc;
}

// ---------------- orchestration ---------------------------------------------
extern "C" void kernel_launch(void* const* d_in, const int* in_sizes, int n_in,
                              void* d_out, int out_size) {
    const float* x    = (const float*)d_in[0];
    const float* nfr  = (const float*)d_in[1];
    const int*   eidx = (const int*)d_in[2];
    const int*   hidx = (const int*)d_in[3];
    const float* Wg1  = (const float*)d_in[4];   const float* bg1 = (const float*)d_in[5];
    const float* Wg2  = (const float*)d_in[6];   const float* bg2 = (const float*)d_in[7];
    const float* Wh1  = (const float*)d_in[8];   const float* bh1 = (const float*)d_in[9];
    const float* Wh2  = (const float*)d_in[10];  const float* bh2 = (const float*)d_in[11];
    const float* Wm   = (const float*)d_in[12];  const float* bm  = (const float*)d_in[13];
    const float* Wm2  = (const float*)d_in[14];  const float* bm2 = (const float*)d_in[15];
    const float* Ws   = (const float*)d_in[16];  const float* bsv = (const float*)d_in[17];
    const float* Wt   = (const float*)d_in[18];  const float* bt  = (const float*)d_in[19];
    float* out = (float*)d_out;

    float *t_, *ef_, *H_, *Op_, *pm_, *pl_;
    float *rsout_, *rsin_, *Dinv_, *Binv_;
    __nv_bfloat16 *aggh_, *aggl_, *vh_, *vl_, *qh_, *ql_, *kmh_, *kml_, *gh_, *gl_, *wh_, *wl_;
    int *offe_, *cole_, *offhn_, *colhn_, *offhe_, *colhe_;
    cudaGetSymbolAddress((void**)&t_,   d_t);
    cudaGetSymbolAddress((void**)&ef_,  d_ef);
    cudaGetSymbolAddress((void**)&H_,   d_H);
    cudaGetSymbolAddress((void**)&Op_,  d_Op);
    cudaGetSymbolAddress((void**)&pm_,  d_pm);
    cudaGetSymbolAddress((void**)&pl_,  d_pl);
    cudaGetSymbolAddress((void**)&aggh_, d_aggh);
    cudaGetSymbolAddress((void**)&aggl_, d_aggl);
    cudaGetSymbolAddress((void**)&vh_,  d_vh);
    cudaGetSymbolAddress((void**)&vl_,  d_vl);
    cudaGetSymbolAddress((void**)&qh_,  d_qh);
    cudaGetSymbolAddress((void**)&ql_,  d_ql);
    cudaGetSymbolAddress((void**)&kmh_, d_kmh);
    cudaGetSymbolAddress((void**)&kml_, d_kml);
    cudaGetSymbolAddress((void**)&gh_,  d_gh);
    cudaGetSymbolAddress((void**)&gl_,  d_gl);
    cudaGetSymbolAddress((void**)&wh_,  d_wh);
    cudaGetSymbolAddress((void**)&wl_,  d_wl);
    cudaGetSymbolAddress((void**)&rsout_, d_rsout);
    cudaGetSymbolAddress((void**)&rsin_,  d_rsin);
    cudaGetSymbolAddress((void**)&Dinv_,  d_Dinv);
    cudaGetSymbolAddress((void**)&Binv_,  d_Binv);
    cudaGetSymbolAddress((void**)&offe_,  d_off_e);
    cudaGetSymbolAddress((void**)&cole_,  d_col_e);
    cudaGetSymbolAddress((void**)&offhn_, d_off_hn);
    cudaGetSymbolAddress((void**)&colhn_, d_col_hn);
    cudaGetSymbolAddress((void**)&offhe_, d_off_he);
    cudaGetSymbolAddress((void**)&colhe_, d_col_he);
    __half* th_  = (__half*)t_;
    __half* efh_ = (__half*)ef_;
    __half* Oph_ = (__half*)Op_;

    cudaFuncSetAttribute(flash_attn, cudaFuncAttributeMaxDynamicSharedMemorySize, FSMEM2);
    dim3 thr(256);

    zero_counts<<<NTOT / 256, thr>>>();
    count_all<<<NE / 256 + NP / 256, thr>>>(eidx, hidx);
    PSArgs ps;
    ps.s[0] = Wg1; ps.s[1] = Wh1; ps.s[2] = Wg2; ps.s[3] = Wh2;
    ps.s[4] = Wm2; ps.s[5] = Wm;  ps.s[6] = Ws;  ps.s[7] = Wt;
    presplit_all<<<304, thr>>>(ps, wh_, wl_);
    // ncu slot: ga0 = nfr @ Wg1 (MODE1, half-out)
    MArgs ga0 = {};
    ga0.A = nfr; ga0.lda = 128; ga0.Bh = wh_ + OFF_WG1; ga0.Bl = wl_ + OFF_WG1; ga0.ldb = 128;
    ga0.Ch = (__nv_bfloat16*)th_; ga0.K = 128;
    mma_gemm<0, 9, 1><<<dim3(NTOT / 128, 1, 1), thr>>>(ga0);
    finalize_scales<<<NTOT / 256, thr>>>();
    scan1c<<<528, thr>>>();
    scan2c<<<3, thr>>>();
    scan3c<<<528, thr>>>();
    fill_all<<<NE / 256 + NP / 256, thr>>>(eidx, hidx);

    for (int layer = 0; layer < 2; layer++) {
        const float* bgv = layer ? bg2 : bg1;
        int whoff = layer ? OFF_WH2 : OFF_WH1;

        if (layer == 1) {
            MArgs ga = {};
            ga.Ah = vh_; ga.Al = vl_;
            ga.Bh = wh_ + OFF_WG2; ga.Bl = wl_ + OFF_WG2; ga.ldb = 128;
            ga.Ch = (__nv_bfloat16*)th_; ga.K = 128;
            mma_gemm<0, 9, 2><<<dim3(NTOT / 128, 1, 1), thr>>>(ga);
            gather_k<2, false, false><<<NTOT / 8, thr>>>(offe_, cole_, th_, nullptr,
                nullptr, nullptr, rsin_, bgv, nullptr, nullptr, aggh_, aggl_);
        } else {
            gather_k<2, false, true><<<NTOT / 8, thr>>>(offe_, cole_, th_, nullptr,
                nullptr, rsout_, rsin_, bgv, nullptr, nullptr, aggh_, aggl_);
        }

        MArgs gb = {};
        gb.Ah = aggh_; gb.Al = aggl_;
        gb.Bh = wh_ + whoff; gb.Bl = wl_ + whoff; gb.ldb = 128;
        gb.Ch = (__nv_bfloat16*)th_; gb.K = 128;
        mma_gemm<0, 9, 2><<<dim3(NTOT / 128, 1, 1), thr>>>(gb);

        gather_k<4, true, false><<<NHE / 8, thr>>>(offhe_, colhe_, th_, efh_,
            Binv_, nullptr, nullptr, nullptr, nullptr, nullptr, nullptr, nullptr);
        if (layer == 0) {
            gather_k<3, false, false><<<NTOT / 8, thr>>>(offhn_, colhn_, efh_, nullptr,
                nullptr, nullptr, Dinv_, bh1, nfr, rsout_, vh_, vl_);
        } else {
            gather_k<1, false, false><<<NTOT / 8, thr>>>(offhn_, colhn_, efh_, nullptr,
                nullptr, nullptr, Dinv_, bh2, nfr, nullptr, gh_, gl_);
        }
    }

    // q = relu(x @ Wm + bm) -> bf16 hi/lo
    MArgs gq = {};
    gq.A = x; gq.lda = ENCD; gq.Bh = wh_ + OFF_WM; gq.Bl = wl_ + OFF_WM; gq.ldb = 128;
    gq.Ch = qh_; gq.Cl = ql_; gq.K = ENCD; gq.bias = bm;
    mma_gemm<0, 6, 0><<<dim3(NROWS / 128, 1, 1), thr>>>(gq);

    // kmT = relu(g @ Wm2 + bm2)^T -> bf16 hi/lo
    MArgs gk = {};
    gk.Ah = gh_; gk.Al = gl_;
    gk.Bh = wh_ + OFF_WM2; gk.Bl = wl_ + OFF_WM2; gk.ldb = 128;
    gk.Ch = kmh_; gk.Cl = kml_; gk.ldc = NTOT; gk.K = 128; gk.bias = bm2;
    mma_gemm<0, 7, 2><<<dim3(NTOT / 128, 1, 1), thr>>>(gk);

    flash_attn<<<dim3(4, BSZ, SPLIT), thr, FSMEM2>>>(qh_, ql_, kmh_, kml_, gh_, gl_,
                                                     Oph_, pm_, pl_);
    flash_combine<<<NROWS / 8, thr>>>(Oph_, pm_, pl_, H_);

    MArgs ghd = {};
    ghd.A = x; ghd.lda = ENCD;
    ghd.Bh = wh_ + OFF_WS; ghd.Bl = wl_ + OFF_WS; ghd.ldb = 128;
    ghd.Bh2 = wh_ + OFF_WT; ghd.Bl2 = wl_ + OFF_WT;
    ghd.C = out; ghd.ldc = 256; ghd.K = ENCD + EMB;
    ghd.padd = H_; ghd.ldadd = 128; ghd.bias = bsv; ghd.bias2 = bt;
    mma_gemm<4, 8, 0><<<dim3(NROWS / 128, 2, 1), thr>>>(ghd);
}

// round 15
// speedup vs baseline: 1.1351x; 1.0353x over previous
#include <cuda_runtime.h>
#include <cuda_bf16.h>
#include <cuda_fp16.h>
#include <cstdint>

#define BSZ   8
#define NPER  8192
#define NTOT  65536
#define EMB   128
#define ENCD  512
#define LQ    512
#define NE    1048576
#define NHE   4096
#define NP    1048576
#define NROWS (BSZ*LQ)   // 4096
#define SPLIT 32
#define KEYS_PER (NPER/SPLIT)   // 256
#define KT    64

#define LDKA 24
#define LDNB 136

__device__ __forceinline__ uint32_t smem_u32(const void* p) {
    uint32_t a;
    asm("{ .reg .u64 t; cvta.to.shared.u64 t, %1; cvt.u32.u64 %0, t; }"
        : "=r"(a) : "l"(p));
    return a;
}
__device__ __forceinline__ void ldsm_x4(uint32_t* r, uint32_t addr) {
    asm volatile("ldmatrix.sync.aligned.m8n8.x4.shared.b16 {%0,%1,%2,%3}, [%4];"
                 : "=r"(r[0]), "=r"(r[1]), "=r"(r[2]), "=r"(r[3]) : "r"(addr));
}
__device__ __forceinline__ void ldsm_x4t(uint32_t* r, uint32_t addr) {
    asm volatile("ldmatrix.sync.aligned.m8n8.x4.trans.shared.b16 {%0,%1,%2,%3}, [%4];"
                 : "=r"(r[0]), "=r"(r[1]), "=r"(r[2]), "=r"(r[3]) : "r"(addr));
}
__device__ __forceinline__ void mma16816(float* c, const uint32_t* a,
                                         uint32_t b0, uint32_t b1) {
    asm volatile("mma.sync.aligned.m16n8k16.row.col.f32.bf16.bf16.f32 "
                 "{%0,%1,%2,%3}, {%4,%5,%6,%7}, {%8,%9}, {%0,%1,%2,%3};"
                 : "+f"(c[0]), "+f"(c[1]), "+f"(c[2]), "+f"(c[3])
                 : "r"(a[0]), "r"(a[1]), "r"(a[2]), "r"(a[3]), "r"(b0), "r"(b1));
}
__device__ __forceinline__ void split4(float4 av, uint2& hp, uint2& lp) {
    __nv_bfloat162 h0, h1, l0, l1;
    h0.x = __float2bfloat16_rn(av.x); h0.y = __float2bfloat16_rn(av.y);
    h1.x = __float2bfloat16_rn(av.z); h1.y = __float2bfloat16_rn(av.w);
    l0.x = __float2bfloat16_rn(av.x - __bfloat162float(h0.x));
    l0.y = __float2bfloat16_rn(av.y - __bfloat162float(h0.y));
    l1.x = __float2bfloat16_rn(av.z - __bfloat162float(h1.x));
    l1.y = __float2bfloat16_rn(av.w - __bfloat162float(h1.y));
    hp.x = *(uint32_t*)&h0; hp.y = *(uint32_t*)&h1;
    lp.x = *(uint32_t*)&l0; lp.y = *(uint32_t*)&l1;
}
__device__ __forceinline__ void splitpair(float a, float b, uint32_t& h, uint32_t& l) {
    __nv_bfloat162 hh, ll;
    hh.x = __float2bfloat16_rn(a); hh.y = __float2bfloat16_rn(b);
    ll.x = __float2bfloat16_rn(a - __bfloat162float(hh.x));
    ll.y = __float2bfloat16_rn(b - __bfloat162float(hh.y));
    h = *(uint32_t*)&hh; l = *(uint32_t*)&ll;
}
__device__ __forceinline__ uint32_t packbf(float a, float b) {
    __nv_bfloat162 h;
    h.x = __float2bfloat16_rn(a); h.y = __float2bfloat16_rn(b);
    return *(uint32_t*)&h;
}

#define CP16(s, gp) asm volatile("cp.async.ca.shared.global [%0], [%1], 16;" :: "r"(s), "l"(gp))
#define CPCOMMIT()  asm volatile("cp.async.commit_group;" ::: "memory")
#define CPWAIT1()   asm volatile("cp.async.wait_group 1;" ::: "memory")
#define CPWAIT0()   asm volatile("cp.async.wait_group 0;" ::: "memory")

// ---------------- scratch ----------------------------------------------------
__device__ float d_t  [(size_t)NTOT*EMB];      // reused as __half buffer
__device__ float d_ef [(size_t)NTOT*EMB];      // reused as __half buffer
__device__ float d_H  [(size_t)NROWS*EMB];
__device__ __half d_Op [(size_t)SPLIT*NROWS*EMB];
__device__ float d_pm [SPLIT*NROWS], d_pl[SPLIT*NROWS];
__device__ __nv_bfloat16 d_aggh[(size_t)NTOT*EMB], d_aggl[(size_t)NTOT*EMB];
__device__ __nv_bfloat16 d_vh  [(size_t)NTOT*EMB], d_vl  [(size_t)NTOT*EMB];
__device__ __nv_bfloat16 d_qh[(size_t)NROWS*EMB],  d_ql[(size_t)NROWS*EMB];
__device__ __nv_bfloat16 d_kmh[(size_t)EMB*NTOT],  d_kml[(size_t)EMB*NTOT];
__device__ __nv_bfloat16 d_gh[(size_t)NTOT*EMB],   d_gl[(size_t)NTOT*EMB];
#define OFF_WG1 0
#define OFF_WH1 16384
#define OFF_WG2 32768
#define OFF_WH2 49152
#define OFF_WM2 65536
#define OFF_WM  81920
#define OFF_WS  147456
#define OFF_WT  229376
__device__ __nv_bfloat16 d_wh[311296], d_wl[311296];
__device__ float d_rsout[NTOT], d_rsin[NTOT], d_Dinv[NTOT], d_Binv[NHE];
__device__ int   d_c0[NTOT], d_c1[NTOT], d_c2[NTOT], d_c3[NHE];
__device__ int d_off_e [NTOT+1], d_col_e [NE];
__device__ int d_off_hn[NTOT+1], d_col_hn[NP];
__device__ int d_off_he[NHE+1],  d_col_he[NP];
__device__ int d_cre[NTOT], d_crn[NTOT], d_crh[NHE];
__device__ int d_part3[3][257];

// ---------------- utility ----------------------------------------------------
struct PSArgs { const float* s[8]; };
__global__ void presplit_all(PSArgs a, __nv_bfloat16* __restrict__ hi,
                             __nv_bfloat16* __restrict__ lo) {
    const int bstart[8] = {0, 16, 32, 48, 64, 80, 144, 224};
    const int dstoff[8] = {0, 4096, 8192, 12288, 16384, 20480, 36864, 57344};
    int b = blockIdx.x;
    int seg = 0;
    #pragma unroll
    for (int s = 1; s < 8; s++) if (b >= bstart[s]) seg = s;
    int li = (b - bstart[seg]) * 256 + threadIdx.x;
    int n4 = (seg < 5) ? 4096 : (seg == 5 ? 16384 : 20480);
    if (li >= n4) return;
    float4 v = ((const float4*)a.s[seg])[li];
    uint2 hp, lp;
    split4(v, hp, lp);
    *(uint2*)(hi + ((size_t)dstoff[seg] + li) * 4) = hp;
    *(uint2*)(lo + ((size_t)dstoff[seg] + li) * 4) = lp;
}

__global__ void zero_counts() {
    int i = blockIdx.x * blockDim.x + threadIdx.x;
    if (i < NTOT) { d_c0[i] = 0; d_c1[i] = 0; d_c2[i] = 0; d_cre[i] = 0; d_crn[i] = 0; }
    if (i < NHE)  { d_c3[i] = 0; d_crh[i] = 0; }
}
__global__ void count_all(const int* __restrict__ eidx, const int* __restrict__ hidx) {
    int b = blockIdx.x, t = threadIdx.x;
    if (b < NE / 256) {
        int i = b * 256 + t;
        atomicAdd(&d_c0[eidx[i]], 1);
        atomicAdd(&d_c1[eidx[NE + i]], 1);
    } else {
        int i = (b - NE / 256) * 256 + t;
        atomicAdd(&d_c2[hidx[2 * i]], 1);
        atomicAdd(&d_c3[hidx[2 * i + 1]], 1);
    }
}
__global__ void finalize_scales() {
    int i = blockIdx.x * blockDim.x + threadIdx.x;
    if (i < NTOT) {
        d_rsout[i] = rsqrtf((float)max(d_c0[i], 1));
        d_rsin[i]  = rsqrtf((float)max(d_c1[i], 1));
        d_Dinv[i]  = d_c2[i] > 0 ? 1.f / (float)d_c2[i] : 0.f;
    }
    if (i < NHE) d_Binv[i] = d_c3[i] > 0 ? 1.f / (float)d_c3[i] : 0.f;
}

// ---------------- merged scans ----------------------------------------------
__global__ void scan1c() {
    int b = blockIdx.x;
    const int* cnt; int* off; int* part; int li;
    if (b < 256)      { cnt = d_c1; off = d_off_e;  part = d_part3[0]; li = b; }
    else if (b < 512) { cnt = d_c2; off = d_off_hn; part = d_part3[1]; li = b - 256; }
    else              { cnt = d_c3; off = d_off_he; part = d_part3[2]; li = b - 512; }
    __shared__ int sh[256];
    int t = threadIdx.x;
    int i = li * 256 + t;
    int v = cnt[i];
    sh[t] = v;
    __syncthreads();
    #pragma unroll
    for (int o = 1; o < 256; o <<= 1) {
        int add = (t >= o) ? sh[t - o] : 0;
        __syncthreads();
        sh[t] += add;
        __syncthreads();
    }
    off[i] = sh[t] - v;
    if (t == 255) part[li] = sh[255];
}
__global__ void scan2c() {
    int a = blockIdx.x;
    int nb = (a == 2) ? 16 : 256;
    int* part = d_part3[a];
    __shared__ int sh[256];
    int t = threadIdx.x;
    int v = (t < nb) ? part[t] : 0;
    sh[t] = v;
    __syncthreads();
    #pragma unroll
    for (int o = 1; o < 256; o <<= 1) {
        int add = (t >= o) ? sh[t - o] : 0;
        __syncthreads();
        sh[t] += add;
        __syncthreads();
    }
    part[t] = sh[t] - v;
    if (t == nb - 1) part[256] = sh[t];
}
__global__ void scan3c() {
    int b = blockIdx.x;
    int* off; int* part; int li; int n;
    if (b < 256)      { off = d_off_e;  part = d_part3[0]; li = b; n = NTOT; }
    else if (b < 512) { off = d_off_hn; part = d_part3[1]; li = b - 256; n = NTOT; }
    else              { off = d_off_he; part = d_part3[2]; li = b - 512; n = NHE; }
    int i = li * 256 + threadIdx.x;
    off[i] += part[li];
    if (i == 0) off[n] = part[256];
}

__global__ void fill_all(const int* __restrict__ eidx, const int* __restrict__ hidx) {
    int b = blockIdx.x, t = threadIdx.x;
    if (b < NE / 256) {
        int i = b * 256 + t;
        int s = eidx[i], d = eidx[NE + i];
        int p = atomicAdd(&d_cre[d], 1);
        d_col_e[d_off_e[d] + p] = s;
    } else {
        int i = (b - NE / 256) * 256 + t;
        int n = hidx[2 * i], e = hidx[2 * i + 1];
        int p1 = atomicAdd(&d_crn[n], 1);
        d_col_hn[d_off_hn[n] + p1] = e;
        int p2 = atomicAdd(&d_crh[e], 1);
        d_col_he[d_off_he[e] + p2] = n;
    }
}

// ---------------- CSR gather (fp16 in), warp-per-row, unroll 8 ---------------
// GEPI 4: scaled store -> half
// GEPI 2: (acc*s1[r]+pb[k]) -> bf16 hi/lo
// GEPI 3: ((relu(acc*s1[r]+pb[k])+padd[r,k])*s2[r]) -> bf16 hi/lo
// GEPI 1: (relu(acc*s1[r]+pb[k])+padd[r,k]) -> bf16 hi/lo
template<int GEPI, bool OSC, bool ISC>
__global__ void __launch_bounds__(256) gather_k(const int* __restrict__ off,
                                                const int* __restrict__ col,
                                                const __half* __restrict__ in,
                                                void* __restrict__ outp,
                                                const float* __restrict__ oscale,
                                                const float* __restrict__ iscale,
                                                const float* __restrict__ s1,
                                                const float* __restrict__ pb,
                                                const float* __restrict__ padd,
                                                const float* __restrict__ s2,
                                                __nv_bfloat16* __restrict__ oh,
                                                __nv_bfloat16* __restrict__ ol) {
    int r    = blockIdx.x * 8 + (threadIdx.x >> 5);
    int lane = threadIdx.x & 31;
    int b = off[r], e = off[r + 1];
    float4 acc = make_float4(0.f, 0.f, 0.f, 0.f);
    for (int j0 = b; j0 < e; j0 += 32) {
        int cj = 0;
        if (j0 + lane < e) cj = col[j0 + lane];
        int m = min(e - j0, 32);
        #pragma unroll 8
        for (int k = 0; k < m; k++) {
            int c = __shfl_sync(~0u, cj, k);
            uint2 raw = *(const uint2*)(in + (size_t)c * EMB + lane * 4);
            float2 f01 = __half22float2(*(__half2*)&raw.x);
            float2 f23 = __half22float2(*(__half2*)&raw.y);
            if (ISC) {
                float s = iscale[c];
                f01.x *= s; f01.y *= s; f23.x *= s; f23.y *= s;
            }
            acc.x += f01.x; acc.y += f01.y; acc.z += f23.x; acc.w += f23.y;
        }
    }
    if (OSC) {
        float s = oscale[r];
        acc.x *= s; acc.y *= s; acc.z *= s; acc.w *= s;
    }
    if (GEPI == 4) {
        __half2 o01 = __floats2half2_rn(acc.x, acc.y);
        __half2 o23 = __floats2half2_rn(acc.z, acc.w);
        uint2 st; st.x = *(uint32_t*)&o01; st.y = *(uint32_t*)&o23;
        *(uint2*)((__half*)outp + (size_t)r * EMB + lane * 4) = st;
        return;
    }
    float sr = s1[r];
    float4 bb = *(const float4*)(pb + lane * 4);
    acc.x = acc.x * sr + bb.x;
    acc.y = acc.y * sr + bb.y;
    acc.z = acc.z * sr + bb.z;
    acc.w = acc.w * sr + bb.w;
    if (GEPI == 3 || GEPI == 1) {
        float4 nn = *(const float4*)(padd + (size_t)r * EMB + lane * 4);
        acc.x = fmaxf(acc.x, 0.f) + nn.x;
        acc.y = fmaxf(acc.y, 0.f) + nn.y;
        acc.z = fmaxf(acc.z, 0.f) + nn.z;
        acc.w = fmaxf(acc.w, 0.f) + nn.w;
        if (GEPI == 3) {
            float so = s2[r];
            acc.x *= so; acc.y *= so; acc.z *= so; acc.w *= so;
        }
    }
    uint2 hp, lp;
    split4(acc, hp, lp);
    *(uint2*)(oh + (size_t)r * EMB + lane * 4) = hp;
    *(uint2*)(ol + (size_t)r * EMB + lane * 4) = lp;
}

// =============== mma.sync bf16-split GEMM ===================================
// MODE 0: chunked fp32 A (K=512/640) | MODE 1: B-res, fp32 A | MODE 2: B-res, pre-split A cp.async
// EPI: 0 fp32 | 6 relu+bias->hi/lo | 7 relu+bias->hi/lo transposed | 8 dual-head
//      | 9 plain store -> half (via Ch) | 10 row-scaled store -> half (scale = bias[r])
struct MArgs {
    const float* A; long lda;
    const __nv_bfloat16* Ah; const __nv_bfloat16* Al;
    const __nv_bfloat16* Bh; const __nv_bfloat16* Bl; long ldb;
    const __nv_bfloat16* Bh2; const __nv_bfloat16* Bl2;
    float* C; long ldc;
    __nv_bfloat16* Ch; __nv_bfloat16* Cl;
    int K;
    const float* padd; long ldadd;
    const float* bias; const float* bias2;
};

template<int PRO, int EPI, int MODE>
__global__ void __launch_bounds__(256, 2) mma_gemm(MArgs g) {
    constexpr int BROWS = (MODE >= 1) ? 128 : 16;
    constexpr int ABUF  = (MODE == 2) ? 3 : (MODE == 1 ? 2 : 1);
    __shared__ __align__(16) __nv_bfloat16 sAh[ABUF][128 * LDKA];
    __shared__ __align__(16) __nv_bfloat16 sAl[ABUF][128 * LDKA];
    __shared__ __align__(16) __nv_bfloat16 sBh[BROWS * LDNB];
    __shared__ __align__(16) __nv_bfloat16 sBl[BROWS * LDNB];

    const float* A = g.A;
    float* C = g.C;
    const __nv_bfloat16* Bh = g.Bh;
    const __nv_bfloat16* Bl = g.Bl;
    const float* bias = g.bias;
    if (EPI == 8 && blockIdx.y == 1) {
        Bh = g.Bh2; Bl = g.Bl2; bias = g.bias2; C = g.C + 128;
    }
    int m0 = blockIdx.x * 128;

    int tid = threadIdx.x, wid = tid >> 5, lane = tid & 31;
    int wm = wid >> 1, wn = wid & 1;

    float acc[2][8][4];
    #pragma unroll
    for (int i = 0; i < 2; i++)
        #pragma unroll
        for (int j = 0; j < 8; j++)
            #pragma unroll
            for (int q = 0; q < 4; q++) acc[i][j][q] = 0.f;

    uint32_t sBh_b = smem_u32(sBh), sBl_b = smem_u32(sBl);

    int arow = lane & 15, akoff = (lane >> 4) * 8;
    int bkrow = (lane & 7) + ((lane >> 3) & 1) * 8;
    int bnoff = (lane >> 4) * 8;

    if (MODE == 2) {
        #pragma unroll
        for (int i = 0; i < 16; i++) {
            int idx = tid + i * 256;
            int kr = idx >> 5, n = (idx & 31) * 4;
            size_t boff = (size_t)kr * g.ldb + n;
            *(uint2*)&sBh[kr * LDNB + n] = *(const uint2*)(Bh + boff);
            *(uint2*)&sBl[kr * LDNB + n] = *(const uint2*)(Bl + boff);
        }
        int row = tid >> 1, half = tid & 1;
        auto cpA = [&](int c) {
            int slot = c % 3;
            uint32_t sh_ = smem_u32(&sAh[slot][row * LDKA + half * 8]);
            uint32_t sl_ = smem_u32(&sAl[slot][row * LDKA + half * 8]);
            const __nv_bfloat16* gph = g.Ah + (size_t)(m0 + row) * 128 + c * 16 + half * 8;
            const __nv_bfloat16* gpl = g.Al + (size_t)(m0 + row) * 128 + c * 16 + half * 8;
            CP16(sh_, gph);
            CP16(sl_, gpl);
        };
        cpA(0); CPCOMMIT();
        cpA(1); CPCOMMIT();

        #pragma unroll
        for (int c = 0; c < 8; c++) {
            CPWAIT1();
            __syncthreads();
            if (c + 2 < 8) cpA(c + 2);
            CPCOMMIT();

            int slot = c % 3;
            uint32_t sAh_b = smem_u32(sAh[slot]), sAl_b = smem_u32(sAl[slot]);
            uint32_t a_h[2][4], a_l[2][4];
            #pragma unroll
            for (int mt = 0; mt < 2; mt++) {
                uint32_t off = (uint32_t)(((wm * 32 + mt * 16 + arow) * LDKA + akoff) * 2);
                ldsm_x4(a_h[mt], sAh_b + off);
                ldsm_x4(a_l[mt], sAl_b + off);
            }
            uint32_t b_h[4][4], b_l[4][4];
            #pragma unroll
            for (int ng = 0; ng < 4; ng++) {
                uint32_t off = (uint32_t)(((c * 16 + bkrow) * LDNB + wn * 64 + ng * 16 + bnoff) * 2);
                ldsm_x4t(b_h[ng], sBh_b + off);
                ldsm_x4t(b_l[ng], sBl_b + off);
            }
            #pragma unroll
            for (int mt = 0; mt < 2; mt++)
                #pragma unroll
                for (int ng = 0; ng < 4; ng++)
                    #pragma unroll
                    for (int h = 0; h < 2; h++) {
                        int nt = ng * 2 + h;
                        mma16816(acc[mt][nt], a_h[mt], b_h[ng][h*2], b_h[ng][h*2+1]);
                        mma16816(acc[mt][nt], a_h[mt], b_l[ng][h*2], b_l[ng][h*2+1]);
                        mma16816(acc[mt][nt], a_l[mt], b_h[ng][h*2], b_h[ng][h*2+1]);
                    }
        }
    } else if (MODE == 1) {
        float4 pAv[2];
        auto prefetchA = [&](int k0) {
            #pragma unroll
            for (int i = 0; i < 2; i++) {
                int idx = tid + i * 256;
                int r = idx >> 2, k = (idx & 3) * 4;
                pAv[i] = *(const float4*)(A + (size_t)(m0 + r) * g.lda + k0 + k);
            }
        };
        auto commitA = [&](int p) {
            #pragma unroll
            for (int i = 0; i < 2; i++) {
                int idx = tid + i * 256;
                int r = idx >> 2, k = (idx & 3) * 4;
                uint2 hp, lp;
                split4(pAv[i], hp, lp);
                *(uint2*)&sAh[p][r * LDKA + k] = hp;
                *(uint2*)&sAl[p][r * LDKA + k] = lp;
            }
        };
        #pragma unroll
        for (int i = 0; i < 16; i++) {
            int idx = tid + i * 256;
            int kr = idx >> 5, n = (idx & 31) * 4;
            size_t boff = (size_t)kr * g.ldb + n;
            *(uint2*)&sBh[kr * LDNB + n] = *(const uint2*)(Bh + boff);
            *(uint2*)&sBl[kr * LDNB + n] = *(const uint2*)(Bl + boff);
        }
        prefetchA(0);
        commitA(0);
        __syncthreads();
        #pragma unroll
        for (int c = 0; c < 8; c++) {
            int p = c & 1;
            uint32_t sAh_b = smem_u32(sAh[p]), sAl_b = smem_u32(sAl[p]);
            uint32_t a_h[2][4], a_l[2][4];
            #pragma unroll
            for (int mt = 0; mt < 2; mt++) {
                uint32_t off = (uint32_t)(((wm * 32 + mt * 16 + arow) * LDKA + akoff) * 2);
                ldsm_x4(a_h[mt], sAh_b + off);
                ldsm_x4(a_l[mt], sAl_b + off);
            }
            uint32_t b_h[4][4], b_l[4][4];
            #pragma unroll
            for (int ng = 0; ng < 4; ng++) {
                uint32_t off = (uint32_t)(((c * 16 + bkrow) * LDNB + wn * 64 + ng * 16 + bnoff) * 2);
                ldsm_x4t(b_h[ng], sBh_b + off);
                ldsm_x4t(b_l[ng], sBl_b + off);
            }
            if (c < 7) prefetchA((c + 1) * 16);
            #pragma unroll
            for (int mt = 0; mt < 2; mt++)
                #pragma unroll
                for (int ng = 0; ng < 4; ng++)
                    #pragma unroll
                    for (int h = 0; h < 2; h++) {
                        int nt = ng * 2 + h;
                        mma16816(acc[mt][nt], a_h[mt], b_h[ng][h*2], b_h[ng][h*2+1]);
                        mma16816(acc[mt][nt], a_h[mt], b_l[ng][h*2], b_l[ng][h*2+1]);
                        mma16816(acc[mt][nt], a_l[mt], b_h[ng][h*2], b_h[ng][h*2+1]);
                    }
            if (c < 7) {
                commitA(p ^ 1);
                __syncthreads();
            }
        }
    } else {
        uint32_t sAh_b = smem_u32(sAh[0]), sAl_b = smem_u32(sAl[0]);
        float4 pAv[2];
        uint2 pBhr[2], pBlr[2];
        auto prefetch = [&](int k0) {
            #pragma unroll
            for (int i = 0; i < 2; i++) {
                int idx = tid + i * 256;
                int r = idx >> 2, k = (idx & 3) * 4;
                int kk = k0 + k;
                if (PRO == 4) {
                    pAv[i] = (kk < ENCD)
                        ? *(const float4*)(A + (size_t)(m0 + r) * g.lda + kk)
                        : *(const float4*)(g.padd + (size_t)(m0 + r) * g.ldadd + (kk - ENCD));
                } else {
                    pAv[i] = *(const float4*)(A + (size_t)(m0 + r) * g.lda + kk);
                }
                int kr = idx >> 5, n = (idx & 31) * 4;
                size_t boff = (size_t)(k0 + kr) * g.ldb + n;
                pBhr[i] = *(const uint2*)(Bh + boff);
                pBlr[i] = *(const uint2*)(Bl + boff);
            }
        };
        auto commit = [&]() {
            #pragma unroll
            for (int i = 0; i < 2; i++) {
                int idx = tid + i * 256;
                int r = idx >> 2, k = (idx & 3) * 4;
                uint2 hp, lp;
                split4(pAv[i], hp, lp);
                *(uint2*)&sAh[0][r * LDKA + k] = hp;
                *(uint2*)&sAl[0][r * LDKA + k] = lp;
                int kr = idx >> 5, n = (idx & 31) * 4;
                *(uint2*)&sBh[kr * LDNB + n] = pBhr[i];
                *(uint2*)&sBl[kr * LDNB + n] = pBlr[i];
            }
        };
        prefetch(0);
        for (int k0 = 0; k0 < g.K; k0 += 16) {
            commit();
            __syncthreads();
            if (k0 + 16 < g.K) prefetch(k0 + 16);

            uint32_t a_h[2][4], a_l[2][4];
            #pragma unroll
            for (int mt = 0; mt < 2; mt++) {
                uint32_t off = (uint32_t)(((wm * 32 + mt * 16 + arow) * LDKA + akoff) * 2);
                ldsm_x4(a_h[mt], sAh_b + off);
                ldsm_x4(a_l[mt], sAl_b + off);
            }
            uint32_t b_h[4][4], b_l[4][4];
            #pragma unroll
            for (int ng = 0; ng < 4; ng++) {
                uint32_t off = (uint32_t)((bkrow * LDNB + wn * 64 + ng * 16 + bnoff) * 2);
                ldsm_x4t(b_h[ng], sBh_b + off);
                ldsm_x4t(b_l[ng], sBl_b + off);
            }
            #pragma unroll
            for (int mt = 0; mt < 2; mt++)
                #pragma unroll
                for (int ng = 0; ng < 4; ng++)
                    #pragma unroll
                    for (int h = 0; h < 2; h++) {
                        int nt = ng * 2 + h;
                        mma16816(acc[mt][nt], a_h[mt], b_h[ng][h*2], b_h[ng][h*2+1]);
                        mma16816(acc[mt][nt], a_h[mt], b_l[ng][h*2], b_l[ng][h*2+1]);
                        mma16816(acc[mt][nt], a_l[mt], b_h[ng][h*2], b_h[ng][h*2+1]);
                    }
            __syncthreads();
        }
    }

    // ---- epilogue ----
    float rs_[2][2];
    if (EPI == 10) {
        #pragma unroll
        for (int mt = 0; mt < 2; mt++)
            #pragma unroll
            for (int hh = 0; hh < 2; hh++)
                rs_[mt][hh] = bias[m0 + wm * 32 + mt * 16 + (lane >> 2) + hh * 8];
    }
    #pragma unroll
    for (int mt = 0; mt < 2; mt++) {
        #pragma unroll
        for (int nt = 0; nt < 8; nt++) {
            int r0 = m0 + wm * 32 + mt * 16 + (lane >> 2);
            int c  = wn * 64 + nt * 8 + (lane & 3) * 2;
            float* a4 = acc[mt][nt];
            #pragma unroll
            for (int half = 0; half < 2; half++) {
                int r = r0 + half * 8;
                float v0 = a4[half * 2 + 0], v1 = a4[half * 2 + 1];
                if (EPI >= 1 && EPI != 9 && EPI != 10) {
                    float2 bb = *(const float2*)(bias + c);
                    v0 += bb.x; v1 += bb.y;
                }
                if (EPI == 6 || EPI == 7) { v0 = fmaxf(v0, 0.f); v1 = fmaxf(v1, 0.f); }
                if (EPI == 8) {
                    if (blockIdx.y == 0) {
                        v0 = 1.f / (1.f + __expf(-v0));
                        v1 = 1.f / (1.f + __expf(-v1));
                    } else {
                        v0 = tanhf(v0); v1 = tanhf(v1);
                    }
                }
                if (EPI == 10) {
                    float s = rs_[mt][half];
                    __half2 hp = __floats2half2_rn(v0 * s, v1 * s);
                    *(__half2*)((__half*)g.Ch + (size_t)r * 128 + c) = hp;
                } else if (EPI == 9) {
                    __half2 hp = __floats2half2_rn(v0, v1);
                    *(__half2*)((__half*)g.Ch + (size_t)r * 128 + c) = hp;
                } else if (EPI == 6) {
                    uint32_t h, l;
                    splitpair(v0, v1, h, l);
                    *(uint32_t*)(g.Ch + (size_t)r * 128 + c) = h;
                    *(uint32_t*)(g.Cl + (size_t)r * 128 + c) = l;
                } else if (EPI == 7) {
                    __nv_bfloat16 h0 = __float2bfloat16_rn(v0);
                    __nv_bfloat16 h1 = __float2bfloat16_rn(v1);
                    g.Ch[(size_t)c * g.ldc + r]       = h0;
                    g.Ch[(size_t)(c + 1) * g.ldc + r] = h1;
                    g.Cl[(size_t)c * g.ldc + r]       = __float2bfloat16_rn(v0 - __bfloat162float(h0));
                    g.Cl[(size_t)(c + 1) * g.ldc + r] = __float2bfloat16_rn(v1 - __bfloat162float(h1));
                } else {
                    float* p = C + (size_t)r * g.ldc + c;
                    float2 o; o.x = v0; o.y = v1;
                    *(float2*)p = o;
                }
            }
        }
    }
}

// =============== fused flash attention (split-KV, cp.async K/G pipeline) ====
#define FB_QH 0
#define FB_QL 17408
#define FB_BUF0 34816
#define FB_STRIDE 35840
#define FK_LO 9216
#define FG_HI 18432
#define FG_LO 27136
#define FSMEM2 ((34816 + 2*35840) * 2)   // 212992 B

__global__ void __launch_bounds__(256) flash_attn(
    const __nv_bfloat16* __restrict__ qh, const __nv_bfloat16* __restrict__ ql,
    const __nv_bfloat16* __restrict__ kmh, const __nv_bfloat16* __restrict__ kml,
    const __nv_bfloat16* __restrict__ gh, const __nv_bfloat16* __restrict__ gl,
    __half* __restrict__ Opart, float* __restrict__ pm, float* __restrict__ pl)
{
    extern __shared__ __align__(16) __nv_bfloat16 fsm[];
    int qt = blockIdx.x, b = blockIdx.y, sp = blockIdx.z;
    int tid = threadIdx.x, wid = tid >> 5, lane = tid & 31;
    int qrow0 = b * LQ + qt * 128;
    int kb0 = b * NPER + sp * KEYS_PER;
    uint32_t sbase = smem_u32(fsm);

    auto fillKG = [&](int kt) {
        int p = kt & 1;
        int kb = kb0 + kt * KT;
        uint32_t base = sbase + (uint32_t)(FB_BUF0 + p * FB_STRIDE) * 2;
        #pragma unroll
        for (int i = 0; i < 4; i++) {
            int idx = tid + i * 256;
            int e = idx >> 3, kq = (idx & 7) * 8;
            uint32_t dk = base + (uint32_t)(e * 72 + kq) * 2;
            CP16(dk, kmh + (size_t)e * NTOT + kb + kq);
            CP16(dk + FK_LO * 2, kml + (size_t)e * NTOT + kb + kq);
        }
        #pragma unroll
        for (int i = 0; i < 4; i++) {
            int idx = tid + i * 256;
            int ky = idx >> 4, eq = (idx & 15) * 8;
            uint32_t dg = base + (uint32_t)(FG_HI + ky * 136 + eq) * 2;
            CP16(dg, gh + (size_t)(kb + ky) * 128 + eq);
            CP16(dg + (FG_LO - FG_HI) * 2, gl + (size_t)(kb + ky) * 128 + eq);
        }
    };

    fillKG(0); CPCOMMIT();
    #pragma unroll
    for (int i = 0; i < 16; i++) {
        int idx = tid + i * 256;
        int r = idx >> 5, cq = idx & 31;
        size_t go = (size_t)(qrow0 + r) * 128 + cq * 4;
        *(uint2*)&fsm[FB_QH + r * 136 + cq * 4] = *(const uint2*)(qh + go);
        *(uint2*)&fsm[FB_QL + r * 136 + cq * 4] = *(const uint2*)(ql + go);
    }
    __syncthreads();

    int arow = lane & 15, akoff = (lane >> 4) * 8;
    int bkrow = (lane & 7) + ((lane >> 3) & 1) * 8;
    int bnoff = (lane >> 4) * 8;

    uint32_t qah[8][4], qal[8][4];
    #pragma unroll
    for (int kc = 0; kc < 8; kc++) {
        uint32_t qoff = (uint32_t)(((wid * 16 + arow) * 136 + kc * 16 + akoff) * 2);
        ldsm_x4(qah[kc], sbase + FB_QH * 2 + qoff);
        ldsm_x4(qal[kc], sbase + FB_QL * 2 + qoff);
    }

    float Oc[16][4];
    #pragma unroll
    for (int i = 0; i < 16; i++)
        #pragma unroll
        for (int j = 0; j < 4; j++) Oc[i][j] = 0.f;
    float m0 = -1e30f, m1 = -1e30f, l0 = 0.f, l1 = 0.f;

    constexpr int NKT = KEYS_PER / KT;   // 4
    for (int kt = 0; kt < NKT; kt++) {
        if (kt + 1 < NKT) { fillKG(kt + 1); CPCOMMIT(); CPWAIT1(); }
        else              { CPWAIT0(); }
        __syncthreads();

        int p = kt & 1;
        uint32_t sK_h = sbase + (uint32_t)(FB_BUF0 + p * FB_STRIDE) * 2;
        uint32_t sK_l = sK_h + FK_LO * 2;
        uint32_t sG_h = sK_h + FG_HI * 2;
        uint32_t sG_l = sK_h + FG_LO * 2;

        float S[8][4];
        #pragma unroll
        for (int i = 0; i < 8; i++)
            #pragma unroll
            for (int j = 0; j < 4; j++) S[i][j] = 0.f;

        #pragma unroll
        for (int kc = 0; kc < 8; kc++) {
            #pragma unroll
            for (int ng = 0; ng < 4; ng++) {
                uint32_t bh[4], bl[4];
                uint32_t koff = (uint32_t)(((kc * 16 + bkrow) * 72 + ng * 16 + bnoff) * 2);
                ldsm_x4t(bh, sK_h + koff);
                ldsm_x4t(bl, sK_l + koff);
                #pragma unroll
                for (int h = 0; h < 2; h++) {
                    int nt = ng * 2 + h;
                    mma16816(S[nt], qah[kc], bh[h*2], bh[h*2+1]);
                    mma16816(S[nt], qah[kc], bl[h*2], bl[h*2+1]);
                    mma16816(S[nt], qal[kc], bh[h*2], bh[h*2+1]);
                }
            }
        }

        float r0 = -1e30f, r1 = -1e30f;
        #pragma unroll
        for (int nt = 0; nt < 8; nt++) {
            r0 = fmaxf(r0, fmaxf(S[nt][0], S[nt][1]));
            r1 = fmaxf(r1, fmaxf(S[nt][2], S[nt][3]));
        }
        r0 = fmaxf(r0, __shfl_xor_sync(~0u, r0, 1));
        r0 = fmaxf(r0, __shfl_xor_sync(~0u, r0, 2));
        r1 = fmaxf(r1, __shfl_xor_sync(~0u, r1, 1));
        r1 = fmaxf(r1, __shfl_xor_sync(~0u, r1, 2));
        float mn0 = fmaxf(m0, r0), mn1 = fmaxf(m1, r1);
        float sc0 = __expf(m0 - mn0), sc1 = __expf(m1 - mn1);
        float rs0 = 0.f, rs1 = 0.f;
        #pragma unroll
        for (int nt = 0; nt < 8; nt++) {
            S[nt][0] = __expf(S[nt][0] - mn0);
            S[nt][1] = __expf(S[nt][1] - mn0);
            S[nt][2] = __expf(S[nt][2] - mn1);
            S[nt][3] = __expf(S[nt][3] - mn1);
            rs0 += S[nt][0] + S[nt][1];
            rs1 += S[nt][2] + S[nt][3];
        }
        rs0 += __shfl_xor_sync(~0u, rs0, 1);
        rs0 += __shfl_xor_sync(~0u, rs0, 2);
        rs1 += __shfl_xor_sync(~0u, rs1, 1);
        rs1 += __shfl_xor_sync(~0u, rs1, 2);
        l0 = l0 * sc0 + rs0;
        l1 = l1 * sc1 + rs1;
        m0 = mn0; m1 = mn1;
        #pragma unroll
        for (int nt = 0; nt < 16; nt++) {
            Oc[nt][0] *= sc0; Oc[nt][1] *= sc0;
            Oc[nt][2] *= sc1; Oc[nt][3] *= sc1;
        }

        #pragma unroll
        for (int j = 0; j < 4; j++) {
            uint32_t ph[4];
            ph[0] = packbf(S[2*j][0],   S[2*j][1]);
            ph[1] = packbf(S[2*j][2],   S[2*j][3]);
            ph[2] = packbf(S[2*j+1][0], S[2*j+1][1]);
            ph[3] = packbf(S[2*j+1][2], S[2*j+1][3]);
            #pragma unroll
            for (int ng = 0; ng < 8; ng++) {
                uint32_t gh4[4], gl4[4];
                uint32_t goff = (uint32_t)(((j * 16 + bkrow) * 136 + ng * 16 + bnoff) * 2);
                ldsm_x4t(gh4, sG_h + goff);
                ldsm_x4t(gl4, sG_l + goff);
                #pragma unroll
                for (int h = 0; h < 2; h++) {
                    int nt = ng * 2 + h;
                    mma16816(Oc[nt], ph, gh4[h*2], gh4[h*2+1]);
                    mma16816(Oc[nt], ph, gl4[h*2], gl4[h*2+1]);
                }
            }
        }
        __syncthreads();
    }

    int rr0 = qrow0 + wid * 16 + (lane >> 2);
    int rr1 = rr0 + 8;
    __half* Ob = Opart + (size_t)sp * NROWS * 128;
    #pragma unroll
    for (int nt = 0; nt < 16; nt++) {
        int c = nt * 8 + (lane & 3) * 2;
        __half2 o0 = __floats2half2_rn(Oc[nt][0], Oc[nt][1]);
        __half2 o1 = __floats2half2_rn(Oc[nt][2], Oc[nt][3]);
        *(__half2*)(Ob + (size_t)rr0 * 128 + c) = o0;
        *(__half2*)(Ob + (size_t)rr1 * 128 + c) = o1;
    }
    if ((lane & 3) == 0) {
        pm[sp * NROWS + rr0] = m0; pm[sp * NROWS + rr1] = m1;
        pl[sp * NROWS + rr0] = l0; pl[sp * NROWS + rr1] = l1;
    }
}

__global__ void __launch_bounds__(256) flash_combine(
    const __half* __restrict__ Opart, const float* __restrict__ pm,
    const float* __restrict__ pl, float* __restrict__ H)
{
    int row = blockIdx.x * 8 + (threadIdx.x >> 5);
    int lane = threadIdx.x & 31;
    float ms = -1e30f;
    #pragma unroll
    for (int s = 0; s < SPLIT; s++) ms = fmaxf(ms, pm[s * NROWS + row]);
    float w[SPLIT]; float lt = 0.f;
    #pragma unroll
    for (int s = 0; s < SPLIT; s++) {
        w[s] = __expf(pm[s * NROWS + row] - ms);
        lt += w[s] * pl[s * NROWS + row];
    }
    float4 acc = make_float4(0.f, 0.f, 0.f, 0.f);
    #pragma unroll
    for (int s = 0; s < SPLIT; s++) {
        uint2 raw = *(const uint2*)(Opart + ((size_t)s * NROWS + row) * 128 + lane * 4);
        float2 f0 = __half22float2(*(__half2*)&raw.x);
        float2 f1 = __half22float2(*(__half2*)&raw.y);
        acc.x += w[s] * f0.x; acc.y += w[s] * f0.y;
        acc.z += w[s] * f1.x; acc.w += w[s] * f1.y;
    }
    float inv = 1.f / lt;
    acc.x *= inv; acc.y *= inv; acc.z *= inv; acc.w *= inv;
    *(float4*)(H + (size_t)row * 128 + lane * 4) = acc;
}

// ---------------- orchestration ---------------------------------------------
extern "C" void kernel_launch(void* const* d_in, const int* in_sizes, int n_in,
                              void* d_out, int out_size) {
    const float* x    = (const float*)d_in[0];
    const float* nfr  = (const float*)d_in[1];
    const int*   eidx = (const int*)d_in[2];
    const int*   hidx = (const int*)d_in[3];
    const float* Wg1  = (const float*)d_in[4];   const float* bg1 = (const float*)d_in[5];
    const float* Wg2  = (const float*)d_in[6];   const float* bg2 = (const float*)d_in[7];
    const float* Wh1  = (const float*)d_in[8];   const float* bh1 = (const float*)d_in[9];
    const float* Wh2  = (const float*)d_in[10];  const float* bh2 = (const float*)d_in[11];
    const float* Wm   = (const float*)d_in[12];  const float* bm  = (const float*)d_in[13];
    const float* Wm2  = (const float*)d_in[14];  const float* bm2 = (const float*)d_in[15];
    const float* Ws   = (const float*)d_in[16];  const float* bsv = (const float*)d_in[17];
    const float* Wt   = (const float*)d_in[18];  const float* bt  = (const float*)d_in[19];
    float* out = (float*)d_out;

    float *t_, *ef_, *H_, *pm_, *pl_;
    __half *Oph_;
    float *rsout_, *rsin_, *Dinv_, *Binv_;
    __nv_bfloat16 *aggh_, *aggl_, *vh_, *vl_, *qh_, *ql_, *kmh_, *kml_, *gh_, *gl_, *wh_, *wl_;
    int *offe_, *cole_, *offhn_, *colhn_, *offhe_, *colhe_;
    cudaGetSymbolAddress((void**)&t_,   d_t);
    cudaGetSymbolAddress((void**)&ef_,  d_ef);
    cudaGetSymbolAddress((void**)&H_,   d_H);
    cudaGetSymbolAddress((void**)&Oph_, d_Op);
    cudaGetSymbolAddress((void**)&pm_,  d_pm);
    cudaGetSymbolAddress((void**)&pl_,  d_pl);
    cudaGetSymbolAddress((void**)&aggh_, d_aggh);
    cudaGetSymbolAddress((void**)&aggl_, d_aggl);
    cudaGetSymbolAddress((void**)&vh_,  d_vh);
    cudaGetSymbolAddress((void**)&vl_,  d_vl);
    cudaGetSymbolAddress((void**)&qh_,  d_qh);
    cudaGetSymbolAddress((void**)&ql_,  d_ql);
    cudaGetSymbolAddress((void**)&kmh_, d_kmh);
    cudaGetSymbolAddress((void**)&kml_, d_kml);
    cudaGetSymbolAddress((void**)&gh_,  d_gh);
    cudaGetSymbolAddress((void**)&gl_,  d_gl);
    cudaGetSymbolAddress((void**)&wh_,  d_wh);
    cudaGetSymbolAddress((void**)&wl_,  d_wl);
    cudaGetSymbolAddress((void**)&rsout_, d_rsout);
    cudaGetSymbolAddress((void**)&rsin_,  d_rsin);
    cudaGetSymbolAddress((void**)&Dinv_,  d_Dinv);
    cudaGetSymbolAddress((void**)&Binv_,  d_Binv);
    cudaGetSymbolAddress((void**)&offe_,  d_off_e);
    cudaGetSymbolAddress((void**)&cole_,  d_col_e);
    cudaGetSymbolAddress((void**)&offhn_, d_off_hn);
    cudaGetSymbolAddress((void**)&colhn_, d_col_hn);
    cudaGetSymbolAddress((void**)&offhe_, d_off_he);
    cudaGetSymbolAddress((void**)&colhe_, d_col_he);
    __half* th_  = (__half*)t_;
    __half* efh_ = (__half*)ef_;

    cudaFuncSetAttribute(flash_attn, cudaFuncAttributeMaxDynamicSharedMemorySize, FSMEM2);
    dim3 thr(256);

    zero_counts<<<NTOT / 256, thr>>>();
    count_all<<<NE / 256 + NP / 256, thr>>>(eidx, hidx);
    finalize_scales<<<NTOT / 256, thr>>>();
    PSArgs ps;
    ps.s[0] = Wg1; ps.s[1] = Wh1; ps.s[2] = Wg2; ps.s[3] = Wh2;
    ps.s[4] = Wm2; ps.s[5] = Wm;  ps.s[6] = Ws;  ps.s[7] = Wt;
    presplit_all<<<304, thr>>>(ps, wh_, wl_);
    // ga0 = (nfr @ Wg1) * rsout[row] -> half (EPI 10 row-scale fold)
    MArgs ga0 = {};
    ga0.A = nfr; ga0.lda = 128; ga0.Bh = wh_ + OFF_WG1; ga0.Bl = wl_ + OFF_WG1; ga0.ldb = 128;
    ga0.Ch = (__nv_bfloat16*)th_; ga0.K = 128; ga0.bias = rsout_;
    mma_gemm<0, 10, 1><<<dim3(NTOT / 128, 1, 1), thr>>>(ga0);
    scan1c<<<528, thr>>>();
    scan2c<<<3, thr>>>();
    scan3c<<<528, thr>>>();
    fill_all<<<NE / 256 + NP / 256, thr>>>(eidx, hidx);

    for (int layer = 0; layer < 2; layer++) {
        const float* bgv = layer ? bg2 : bg1;
        int whoff = layer ? OFF_WH2 : OFF_WH1;

        if (layer == 1) {
            MArgs ga = {};
            ga.Ah = vh_; ga.Al = vl_;
            ga.Bh = wh_ + OFF_WG2; ga.Bl = wl_ + OFF_WG2; ga.ldb = 128;
            ga.Ch = (__nv_bfloat16*)th_; ga.K = 128;
            mma_gemm<0, 9, 2><<<dim3(NTOT / 128, 1, 1), thr>>>(ga);
        }
        // agg-hat = (sum t)*rsin + bg -> hi/lo  (rsout pre-folded in both layers)
        gather_k<2, false, false><<<NTOT / 8, thr>>>(offe_, cole_, th_, nullptr,
            nullptr, nullptr, rsin_, bgv, nullptr, nullptr, aggh_, aggl_);

        MArgs gb = {};
        gb.Ah = aggh_; gb.Al = aggl_;
        gb.Bh = wh_ + whoff; gb.Bl = wl_ + whoff; gb.ldb = 128;
        gb.Ch = (__nv_bfloat16*)th_; gb.K = 128;
        mma_gemm<0, 9, 2><<<dim3(NTOT / 128, 1, 1), thr>>>(gb);

        gather_k<4, true, false><<<NHE / 8, thr>>>(offhe_, colhe_, th_, efh_,
            Binv_, nullptr, nullptr, nullptr, nullptr, nullptr, nullptr, nullptr);
        if (layer == 0) {
            gather_k<3, false, false><<<NTOT / 8, thr>>>(offhn_, colhn_, efh_, nullptr,
                nullptr, nullptr, Dinv_, bh1, nfr, rsout_, vh_, vl_);
        } else {
            gather_k<1, false, false><<<NTOT / 8, thr>>>(offhn_, colhn_, efh_, nullptr,
                nullptr, nullptr, Dinv_, bh2, nfr, nullptr, gh_, gl_);
        }
    }

    // q = relu(x @ Wm + bm) -> bf16 hi/lo
    MArgs gq = {};
    gq.A = x; gq.lda = ENCD; gq.Bh = wh_ + OFF_WM; gq.Bl = wl_ + OFF_WM; gq.ldb = 128;
    gq.Ch = qh_; gq.Cl = ql_; gq.K = ENCD; gq.bias = bm;
    mma_gemm<0, 6, 0><<<dim3(NROWS / 128, 1, 1), thr>>>(gq);

    // kmT = relu(g @ Wm2 + bm2)^T -> bf16 hi/lo
    MArgs gk = {};
    gk.Ah = gh_; gk.Al = gl_;
    gk.Bh = wh_ + OFF_WM2; gk.Bl = wl_ + OFF_WM2; gk.ldb = 128;
    gk.Ch = kmh_; gk.Cl = kml_; gk.ldc = NTOT; gk.K = 128; gk.bias = bm2;
    mma_gemm<0, 7, 2><<<dim3(NTOT / 128, 1, 1), thr>>>(gk);

    flash_attn<<<dim3(4, BSZ, SPLIT), thr, FSMEM2>>>(qh_, ql_, kmh_, kml_, gh_, gl_,
                                                     Oph_, pm_, pl_);
    flash_combine<<<NROWS / 8, thr>>>(Oph_, pm_, pl_, H_);

    MArgs ghd = {};
    ghd.A = x; ghd.lda = ENCD;
    ghd.Bh = wh_ + OFF_WS; ghd.Bl = wl_ + OFF_WS; ghd.ldb = 128;
    ghd.Bh2 = wh_ + OFF_WT; ghd.Bl2 = wl_ + OFF_WT;
    ghd.C = out; ghd.ldc = 256; ghd.K = ENCD + EMB;
    ghd.padd = H_; ghd.ldadd = 128; ghd.bias = bsv; ghd.bias2 = bt;
    mma_gemm<4, 8, 0><<<dim3(NROWS / 128, 2, 1), thr>>>(ghd);
}

// round 16
// speedup vs baseline: 1.1623x; 1.0239x over previous
#include <cuda_runtime.h>
#include <cuda_bf16.h>
#include <cuda_fp16.h>
#include <cstdint>

#define BSZ   8
#define NPER  8192
#define NTOT  65536
#define EMB   128
#define ENCD  512
#define LQ    512
#define NE    1048576
#define NHE   4096
#define NP    1048576
#define NROWS (BSZ*LQ)   // 4096
#define SPLIT 32
#define KEYS_PER (NPER/SPLIT)   // 256
#define KT    64

#define LDKA 24
#define LDNB 136

__device__ __forceinline__ uint32_t smem_u32(const void* p) {
    uint32_t a;
    asm("{ .reg .u64 t; cvta.to.shared.u64 t, %1; cvt.u32.u64 %0, t; }"
        : "=r"(a) : "l"(p));
    return a;
}
__device__ __forceinline__ void ldsm_x4(uint32_t* r, uint32_t addr) {
    asm volatile("ldmatrix.sync.aligned.m8n8.x4.shared.b16 {%0,%1,%2,%3}, [%4];"
                 : "=r"(r[0]), "=r"(r[1]), "=r"(r[2]), "=r"(r[3]) : "r"(addr));
}
__device__ __forceinline__ void ldsm_x4t(uint32_t* r, uint32_t addr) {
    asm volatile("ldmatrix.sync.aligned.m8n8.x4.trans.shared.b16 {%0,%1,%2,%3}, [%4];"
                 : "=r"(r[0]), "=r"(r[1]), "=r"(r[2]), "=r"(r[3]) : "r"(addr));
}
__device__ __forceinline__ void mma16816(float* c, const uint32_t* a,
                                         uint32_t b0, uint32_t b1) {
    asm volatile("mma.sync.aligned.m16n8k16.row.col.f32.bf16.bf16.f32 "
                 "{%0,%1,%2,%3}, {%4,%5,%6,%7}, {%8,%9}, {%0,%1,%2,%3};"
                 : "+f"(c[0]), "+f"(c[1]), "+f"(c[2]), "+f"(c[3])
                 : "r"(a[0]), "r"(a[1]), "r"(a[2]), "r"(a[3]), "r"(b0), "r"(b1));
}
__device__ __forceinline__ void split4(float4 av, uint2& hp, uint2& lp) {
    __nv_bfloat162 h0, h1, l0, l1;
    h0.x = __float2bfloat16_rn(av.x); h0.y = __float2bfloat16_rn(av.y);
    h1.x = __float2bfloat16_rn(av.z); h1.y = __float2bfloat16_rn(av.w);
    l0.x = __float2bfloat16_rn(av.x - __bfloat162float(h0.x));
    l0.y = __float2bfloat16_rn(av.y - __bfloat162float(h0.y));
    l1.x = __float2bfloat16_rn(av.z - __bfloat162float(h1.x));
    l1.y = __float2bfloat16_rn(av.w - __bfloat162float(h1.y));
    hp.x = *(uint32_t*)&h0; hp.y = *(uint32_t*)&h1;
    lp.x = *(uint32_t*)&l0; lp.y = *(uint32_t*)&l1;
}
__device__ __forceinline__ void splitpair(float a, float b, uint32_t& h, uint32_t& l) {
    __nv_bfloat162 hh, ll;
    hh.x = __float2bfloat16_rn(a); hh.y = __float2bfloat16_rn(b);
    ll.x = __float2bfloat16_rn(a - __bfloat162float(hh.x));
    ll.y = __float2bfloat16_rn(b - __bfloat162float(hh.y));
    h = *(uint32_t*)&hh; l = *(uint32_t*)&ll;
}
__device__ __forceinline__ uint32_t packbf(float a, float b) {
    __nv_bfloat162 h;
    h.x = __float2bfloat16_rn(a); h.y = __float2bfloat16_rn(b);
    return *(uint32_t*)&h;
}

#define CP16(s, gp) asm volatile("cp.async.ca.shared.global [%0], [%1], 16;" :: "r"(s), "l"(gp))
#define CPCOMMIT()  asm volatile("cp.async.commit_group;" ::: "memory")
#define CPWAIT1()   asm volatile("cp.async.wait_group 1;" ::: "memory")
#define CPWAIT0()   asm volatile("cp.async.wait_group 0;" ::: "memory")

// ---------------- scratch ----------------------------------------------------
__device__ float d_t  [(size_t)NTOT*EMB];      // reused as __half buffer
__device__ float d_ef [(size_t)NTOT*EMB];      // reused as __half buffer
__device__ float d_H  [(size_t)NROWS*EMB];
__device__ __half d_Op [(size_t)SPLIT*NROWS*EMB];
__device__ float d_pm [SPLIT*NROWS], d_pl[SPLIT*NROWS];
__device__ __nv_bfloat16 d_aggh[(size_t)NTOT*EMB], d_aggl[(size_t)NTOT*EMB];
__device__ __nv_bfloat16 d_vh  [(size_t)NTOT*EMB], d_vl  [(size_t)NTOT*EMB];
__device__ __nv_bfloat16 d_qh[(size_t)NROWS*EMB],  d_ql[(size_t)NROWS*EMB];
__device__ __nv_bfloat16 d_kmh[(size_t)EMB*NTOT],  d_kml[(size_t)EMB*NTOT];
__device__ __nv_bfloat16 d_gh[(size_t)NTOT*EMB],   d_gl[(size_t)NTOT*EMB];
#define OFF_WG1 0
#define OFF_WH1 16384
#define OFF_WG2 32768
#define OFF_WH2 49152
#define OFF_WM2 65536
#define OFF_WM  81920
#define OFF_WS  147456
#define OFF_WT  229376
__device__ __nv_bfloat16 d_wh[311296], d_wl[311296];
__device__ float d_rsout[NTOT], d_rsin[NTOT], d_Dinv[NTOT], d_Binv[NHE];
__device__ int   d_c0[NTOT], d_c1[NTOT], d_c2[NTOT], d_c3[NHE];
__device__ int d_off_e [NTOT+1], d_col_e [NE];
__device__ int d_off_hn[NTOT+1], d_col_hn[NP];
__device__ int d_off_he[NHE+1],  d_col_he[NP];
__device__ int d_cre[NTOT], d_crn[NTOT], d_crh[NHE];
__device__ int d_part3[3][257];

// ---------------- utility ----------------------------------------------------
struct PSArgs { const float* s[8]; };
__global__ void presplit_all(PSArgs a, __nv_bfloat16* __restrict__ hi,
                             __nv_bfloat16* __restrict__ lo) {
    const int bstart[8] = {0, 16, 32, 48, 64, 80, 144, 224};
    const int dstoff[8] = {0, 4096, 8192, 12288, 16384, 20480, 36864, 57344};
    int b = blockIdx.x;
    int seg = 0;
    #pragma unroll
    for (int s = 1; s < 8; s++) if (b >= bstart[s]) seg = s;
    int li = (b - bstart[seg]) * 256 + threadIdx.x;
    int n4 = (seg < 5) ? 4096 : (seg == 5 ? 16384 : 20480);
    if (li >= n4) return;
    float4 v = ((const float4*)a.s[seg])[li];
    uint2 hp, lp;
    split4(v, hp, lp);
    *(uint2*)(hi + ((size_t)dstoff[seg] + li) * 4) = hp;
    *(uint2*)(lo + ((size_t)dstoff[seg] + li) * 4) = lp;
}

__global__ void zero_counts() {
    int i = blockIdx.x * blockDim.x + threadIdx.x;
    if (i < NTOT) { d_c0[i] = 0; d_c1[i] = 0; d_c2[i] = 0; d_cre[i] = 0; d_crn[i] = 0; }
    if (i < NHE)  { d_c3[i] = 0; d_crh[i] = 0; }
}
__global__ void count_all(const int* __restrict__ eidx, const int* __restrict__ hidx) {
    int b = blockIdx.x, t = threadIdx.x;
    if (b < NE / 256) {
        int i = b * 256 + t;
        atomicAdd(&d_c0[eidx[i]], 1);
        atomicAdd(&d_c1[eidx[NE + i]], 1);
    } else {
        int i = (b - NE / 256) * 256 + t;
        atomicAdd(&d_c2[hidx[2 * i]], 1);
        atomicAdd(&d_c3[hidx[2 * i + 1]], 1);
    }
}
__global__ void finalize_scales() {
    int i = blockIdx.x * blockDim.x + threadIdx.x;
    if (i < NTOT) {
        d_rsout[i] = rsqrtf((float)max(d_c0[i], 1));
        d_rsin[i]  = rsqrtf((float)max(d_c1[i], 1));
        d_Dinv[i]  = d_c2[i] > 0 ? 1.f / (float)d_c2[i] : 0.f;
    }
    if (i < NHE) d_Binv[i] = d_c3[i] > 0 ? 1.f / (float)d_c3[i] : 0.f;
}

// ---------------- merged scans ----------------------------------------------
__global__ void scan1c() {
    int b = blockIdx.x;
    const int* cnt; int* off; int* part; int li;
    if (b < 256)      { cnt = d_c1; off = d_off_e;  part = d_part3[0]; li = b; }
    else if (b < 512) { cnt = d_c2; off = d_off_hn; part = d_part3[1]; li = b - 256; }
    else              { cnt = d_c3; off = d_off_he; part = d_part3[2]; li = b - 512; }
    __shared__ int sh[256];
    int t = threadIdx.x;
    int i = li * 256 + t;
    int v = cnt[i];
    sh[t] = v;
    __syncthreads();
    #pragma unroll
    for (int o = 1; o < 256; o <<= 1) {
        int add = (t >= o) ? sh[t - o] : 0;
        __syncthreads();
        sh[t] += add;
        __syncthreads();
    }
    off[i] = sh[t] - v;
    if (t == 255) part[li] = sh[255];
}
__global__ void scan2c() {
    int a = blockIdx.x;
    int nb = (a == 2) ? 16 : 256;
    int* part = d_part3[a];
    __shared__ int sh[256];
    int t = threadIdx.x;
    int v = (t < nb) ? part[t] : 0;
    sh[t] = v;
    __syncthreads();
    #pragma unroll
    for (int o = 1; o < 256; o <<= 1) {
        int add = (t >= o) ? sh[t - o] : 0;
        __syncthreads();
        sh[t] += add;
        __syncthreads();
    }
    part[t] = sh[t] - v;
    if (t == nb - 1) part[256] = sh[t];
}
__global__ void scan3c() {
    int b = blockIdx.x;
    int* off; int* part; int li; int n;
    if (b < 256)      { off = d_off_e;  part = d_part3[0]; li = b; n = NTOT; }
    else if (b < 512) { off = d_off_hn; part = d_part3[1]; li = b - 256; n = NTOT; }
    else              { off = d_off_he; part = d_part3[2]; li = b - 512; n = NHE; }
    int i = li * 256 + threadIdx.x;
    off[i] += part[li];
    if (i == 0) off[n] = part[256];
}

__global__ void fill_all(const int* __restrict__ eidx, const int* __restrict__ hidx) {
    int b = blockIdx.x, t = threadIdx.x;
    if (b < NE / 256) {
        int i = b * 256 + t;
        int s = eidx[i], d = eidx[NE + i];
        int p = atomicAdd(&d_cre[d], 1);
        d_col_e[d_off_e[d] + p] = s;
    } else {
        int i = (b - NE / 256) * 256 + t;
        int n = hidx[2 * i], e = hidx[2 * i + 1];
        int p1 = atomicAdd(&d_crn[n], 1);
        d_col_hn[d_off_hn[n] + p1] = e;
        int p2 = atomicAdd(&d_crh[e], 1);
        d_col_he[d_off_he[e] + p2] = n;
    }
}

// ---------------- CSR gather (fp16 in), warp-per-row, unroll 8 ---------------
// GEPI 4: scaled store -> half
// GEPI 2: (acc*s1[r]+pb[k]) -> bf16 hi/lo
// GEPI 3: ((relu(acc*s1[r]+pb[k])+padd[r,k])*s2[r]) -> bf16 hi/lo
// GEPI 1: (relu(acc*s1[r]+pb[k])+padd[r,k]) -> bf16 hi/lo
template<int GEPI, bool OSC, bool ISC>
__global__ void __launch_bounds__(256) gather_k(const int* __restrict__ off,
                                                const int* __restrict__ col,
                                                const __half* __restrict__ in,
                                                void* __restrict__ outp,
                                                const float* __restrict__ oscale,
                                                const float* __restrict__ iscale,
                                                const float* __restrict__ s1,
                                                const float* __restrict__ pb,
                                                const float* __restrict__ padd,
                                                const float* __restrict__ s2,
                                                __nv_bfloat16* __restrict__ oh,
                                                __nv_bfloat16* __restrict__ ol) {
    int r    = blockIdx.x * 8 + (threadIdx.x >> 5);
    int lane = threadIdx.x & 31;
    int b = off[r], e = off[r + 1];
    float4 acc = make_float4(0.f, 0.f, 0.f, 0.f);
    for (int j0 = b; j0 < e; j0 += 32) {
        int cj = 0;
        if (j0 + lane < e) cj = col[j0 + lane];
        int m = min(e - j0, 32);
        #pragma unroll 8
        for (int k = 0; k < m; k++) {
            int c = __shfl_sync(~0u, cj, k);
            uint2 raw = *(const uint2*)(in + (size_t)c * EMB + lane * 4);
            float2 f01 = __half22float2(*(__half2*)&raw.x);
            float2 f23 = __half22float2(*(__half2*)&raw.y);
            if (ISC) {
                float s = iscale[c];
                f01.x *= s; f01.y *= s; f23.x *= s; f23.y *= s;
            }
            acc.x += f01.x; acc.y += f01.y; acc.z += f23.x; acc.w += f23.y;
        }
    }
    if (OSC) {
        float s = oscale[r];
        acc.x *= s; acc.y *= s; acc.z *= s; acc.w *= s;
    }
    if (GEPI == 4) {
        __half2 o01 = __floats2half2_rn(acc.x, acc.y);
        __half2 o23 = __floats2half2_rn(acc.z, acc.w);
        uint2 st; st.x = *(uint32_t*)&o01; st.y = *(uint32_t*)&o23;
        *(uint2*)((__half*)outp + (size_t)r * EMB + lane * 4) = st;
        return;
    }
    float sr = s1[r];
    float4 bb = *(const float4*)(pb + lane * 4);
    acc.x = acc.x * sr + bb.x;
    acc.y = acc.y * sr + bb.y;
    acc.z = acc.z * sr + bb.z;
    acc.w = acc.w * sr + bb.w;
    if (GEPI == 3 || GEPI == 1) {
        float4 nn = *(const float4*)(padd + (size_t)r * EMB + lane * 4);
        acc.x = fmaxf(acc.x, 0.f) + nn.x;
        acc.y = fmaxf(acc.y, 0.f) + nn.y;
        acc.z = fmaxf(acc.z, 0.f) + nn.z;
        acc.w = fmaxf(acc.w, 0.f) + nn.w;
        if (GEPI == 3) {
            float so = s2[r];
            acc.x *= so; acc.y *= so; acc.z *= so; acc.w *= so;
        }
    }
    uint2 hp, lp;
    split4(acc, hp, lp);
    *(uint2*)(oh + (size_t)r * EMB + lane * 4) = hp;
    *(uint2*)(ol + (size_t)r * EMB + lane * 4) = lp;
}

// ---------------- hyperedge gather: 4 warps per row (deg ~256) ----------------
// ef[r] = Binv[r] * sum_{n in row r} in[n]; fp16 in/out.
__global__ void __launch_bounds__(256) gather_he(const int* __restrict__ off,
                                                 const int* __restrict__ col,
                                                 const __half* __restrict__ in,
                                                 __half* __restrict__ outp,
                                                 const float* __restrict__ Binv) {
    __shared__ float4 red[2][4][32];
    int grp = threadIdx.x >> 7;              // 0..1
    int wig = (threadIdx.x >> 5) & 3;        // warp in group 0..3
    int lane = threadIdx.x & 31;
    int r = blockIdx.x * 2 + grp;
    int b = off[r], e = off[r + 1];
    float4 acc = make_float4(0.f, 0.f, 0.f, 0.f);
    for (int j0 = b + wig * 32; j0 < e; j0 += 128) {
        int cj = 0;
        if (j0 + lane < e) cj = col[j0 + lane];
        int m = min(e - j0, 32);
        #pragma unroll 8
        for (int k = 0; k < m; k++) {
            int c = __shfl_sync(~0u, cj, k);
            uint2 raw = *(const uint2*)(in + (size_t)c * EMB + lane * 4);
            float2 f01 = __half22float2(*(__half2*)&raw.x);
            float2 f23 = __half22float2(*(__half2*)&raw.y);
            acc.x += f01.x; acc.y += f01.y; acc.z += f23.x; acc.w += f23.y;
        }
    }
    red[grp][wig][lane] = acc;
    __syncthreads();
    if (wig == 0) {
        float4 a0 = red[grp][0][lane], a1 = red[grp][1][lane];
        float4 a2 = red[grp][2][lane], a3 = red[grp][3][lane];
        float s = Binv[r];
        float4 o;
        o.x = (a0.x + a1.x + a2.x + a3.x) * s;
        o.y = (a0.y + a1.y + a2.y + a3.y) * s;
        o.z = (a0.z + a1.z + a2.z + a3.z) * s;
        o.w = (a0.w + a1.w + a2.w + a3.w) * s;
        __half2 o01 = __floats2half2_rn(o.x, o.y);
        __half2 o23 = __floats2half2_rn(o.z, o.w);
        uint2 st; st.x = *(uint32_t*)&o01; st.y = *(uint32_t*)&o23;
        *(uint2*)(outp + (size_t)r * EMB + lane * 4) = st;
    }
}

// =============== mma.sync bf16-split GEMM ===================================
// MODE 0: chunked fp32 A (K=512/640) | MODE 1: B-res, fp32 A | MODE 2: B-res, pre-split A cp.async
// EPI: 0 fp32 | 6 relu+bias->hi/lo | 7 relu+bias->hi/lo transposed | 8 dual-head
//      | 9 plain store -> half (via Ch) | 10 row-scaled store -> half (scale = bias[r])
struct MArgs {
    const float* A; long lda;
    const __nv_bfloat16* Ah; const __nv_bfloat16* Al;
    const __nv_bfloat16* Bh; const __nv_bfloat16* Bl; long ldb;
    const __nv_bfloat16* Bh2; const __nv_bfloat16* Bl2;
    float* C; long ldc;
    __nv_bfloat16* Ch; __nv_bfloat16* Cl;
    int K;
    const float* padd; long ldadd;
    const float* bias; const float* bias2;
};

template<int PRO, int EPI, int MODE>
__global__ void __launch_bounds__(256, 2) mma_gemm(MArgs g) {
    constexpr int BROWS = (MODE >= 1) ? 128 : 16;
    constexpr int ABUF  = (MODE == 2) ? 3 : (MODE == 1 ? 2 : 1);
    __shared__ __align__(16) __nv_bfloat16 sAh[ABUF][128 * LDKA];
    __shared__ __align__(16) __nv_bfloat16 sAl[ABUF][128 * LDKA];
    __shared__ __align__(16) __nv_bfloat16 sBh[BROWS * LDNB];
    __shared__ __align__(16) __nv_bfloat16 sBl[BROWS * LDNB];

    const float* A = g.A;
    float* C = g.C;
    const __nv_bfloat16* Bh = g.Bh;
    const __nv_bfloat16* Bl = g.Bl;
    const float* bias = g.bias;
    if (EPI == 8 && blockIdx.y == 1) {
        Bh = g.Bh2; Bl = g.Bl2; bias = g.bias2; C = g.C + 128;
    }
    int m0 = blockIdx.x * 128;

    int tid = threadIdx.x, wid = tid >> 5, lane = tid & 31;
    int wm = wid >> 1, wn = wid & 1;

    float acc[2][8][4];
    #pragma unroll
    for (int i = 0; i < 2; i++)
        #pragma unroll
        for (int j = 0; j < 8; j++)
            #pragma unroll
            for (int q = 0; q < 4; q++) acc[i][j][q] = 0.f;

    uint32_t sBh_b = smem_u32(sBh), sBl_b = smem_u32(sBl);

    int arow = lane & 15, akoff = (lane >> 4) * 8;
    int bkrow = (lane & 7) + ((lane >> 3) & 1) * 8;
    int bnoff = (lane >> 4) * 8;

    if (MODE == 2) {
        #pragma unroll
        for (int i = 0; i < 16; i++) {
            int idx = tid + i * 256;
            int kr = idx >> 5, n = (idx & 31) * 4;
            size_t boff = (size_t)kr * g.ldb + n;
            *(uint2*)&sBh[kr * LDNB + n] = *(const uint2*)(Bh + boff);
            *(uint2*)&sBl[kr * LDNB + n] = *(const uint2*)(Bl + boff);
        }
        int row = tid >> 1, half = tid & 1;
        auto cpA = [&](int c) {
            int slot = c % 3;
            uint32_t sh_ = smem_u32(&sAh[slot][row * LDKA + half * 8]);
            uint32_t sl_ = smem_u32(&sAl[slot][row * LDKA + half * 8]);
            const __nv_bfloat16* gph = g.Ah + (size_t)(m0 + row) * 128 + c * 16 + half * 8;
            const __nv_bfloat16* gpl = g.Al + (size_t)(m0 + row) * 128 + c * 16 + half * 8;
            CP16(sh_, gph);
            CP16(sl_, gpl);
        };
        cpA(0); CPCOMMIT();
        cpA(1); CPCOMMIT();

        #pragma unroll
        for (int c = 0; c < 8; c++) {
            CPWAIT1();
            __syncthreads();
            if (c + 2 < 8) cpA(c + 2);
            CPCOMMIT();

            int slot = c % 3;
            uint32_t sAh_b = smem_u32(sAh[slot]), sAl_b = smem_u32(sAl[slot]);
            uint32_t a_h[2][4], a_l[2][4];
            #pragma unroll
            for (int mt = 0; mt < 2; mt++) {
                uint32_t off = (uint32_t)(((wm * 32 + mt * 16 + arow) * LDKA + akoff) * 2);
                ldsm_x4(a_h[mt], sAh_b + off);
                ldsm_x4(a_l[mt], sAl_b + off);
            }
            uint32_t b_h[4][4], b_l[4][4];
            #pragma unroll
            for (int ng = 0; ng < 4; ng++) {
                uint32_t off = (uint32_t)(((c * 16 + bkrow) * LDNB + wn * 64 + ng * 16 + bnoff) * 2);
                ldsm_x4t(b_h[ng], sBh_b + off);
                ldsm_x4t(b_l[ng], sBl_b + off);
            }
            #pragma unroll
            for (int mt = 0; mt < 2; mt++)
                #pragma unroll
                for (int ng = 0; ng < 4; ng++)
                    #pragma unroll
                    for (int h = 0; h < 2; h++) {
                        int nt = ng * 2 + h;
                        mma16816(acc[mt][nt], a_h[mt], b_h[ng][h*2], b_h[ng][h*2+1]);
                        mma16816(acc[mt][nt], a_h[mt], b_l[ng][h*2], b_l[ng][h*2+1]);
                        mma16816(acc[mt][nt], a_l[mt], b_h[ng][h*2], b_h[ng][h*2+1]);
                    }
        }
    } else if (MODE == 1) {
        float4 pAv[2];
        auto prefetchA = [&](int k0) {
            #pragma unroll
            for (int i = 0; i < 2; i++) {
                int idx = tid + i * 256;
                int r = idx >> 2, k = (idx & 3) * 4;
                pAv[i] = *(const float4*)(A + (size_t)(m0 + r) * g.lda + k0 + k);
            }
        };
        auto commitA = [&](int p) {
            #pragma unroll
            for (int i = 0; i < 2; i++) {
                int idx = tid + i * 256;
                int r = idx >> 2, k = (idx & 3) * 4;
                uint2 hp, lp;
                split4(pAv[i], hp, lp);
                *(uint2*)&sAh[p][r * LDKA + k] = hp;
                *(uint2*)&sAl[p][r * LDKA + k] = lp;
            }
        };
        #pragma unroll
        for (int i = 0; i < 16; i++) {
            int idx = tid + i * 256;
            int kr = idx >> 5, n = (idx & 31) * 4;
            size_t boff = (size_t)kr * g.ldb + n;
            *(uint2*)&sBh[kr * LDNB + n] = *(const uint2*)(Bh + boff);
            *(uint2*)&sBl[kr * LDNB + n] = *(const uint2*)(Bl + boff);
        }
        prefetchA(0);
        commitA(0);
        __syncthreads();
        #pragma unroll
        for (int c = 0; c < 8; c++) {
            int p = c & 1;
            uint32_t sAh_b = smem_u32(sAh[p]), sAl_b = smem_u32(sAl[p]);
            uint32_t a_h[2][4], a_l[2][4];
            #pragma unroll
            for (int mt = 0; mt < 2; mt++) {
                uint32_t off = (uint32_t)(((wm * 32 + mt * 16 + arow) * LDKA + akoff) * 2);
                ldsm_x4(a_h[mt], sAh_b + off);
                ldsm_x4(a_l[mt], sAl_b + off);
            }
            uint32_t b_h[4][4], b_l[4][4];
            #pragma unroll
            for (int ng = 0; ng < 4; ng++) {
                uint32_t off = (uint32_t)(((c * 16 + bkrow) * LDNB + wn * 64 + ng * 16 + bnoff) * 2);
                ldsm_x4t(b_h[ng], sBh_b + off);
                ldsm_x4t(b_l[ng], sBl_b + off);
            }
            if (c < 7) prefetchA((c + 1) * 16);
            #pragma unroll
            for (int mt = 0; mt < 2; mt++)
                #pragma unroll
                for (int ng = 0; ng < 4; ng++)
                    #pragma unroll
                    for (int h = 0; h < 2; h++) {
                        int nt = ng * 2 + h;
                        mma16816(acc[mt][nt], a_h[mt], b_h[ng][h*2], b_h[ng][h*2+1]);
                        mma16816(acc[mt][nt], a_h[mt], b_l[ng][h*2], b_l[ng][h*2+1]);
                        mma16816(acc[mt][nt], a_l[mt], b_h[ng][h*2], b_h[ng][h*2+1]);
                    }
            if (c < 7) {
                commitA(p ^ 1);
                __syncthreads();
            }
        }
    } else {
        uint32_t sAh_b = smem_u32(sAh[0]), sAl_b = smem_u32(sAl[0]);
        float4 pAv[2];
        uint2 pBhr[2], pBlr[2];
        auto prefetch = [&](int k0) {
            #pragma unroll
            for (int i = 0; i < 2; i++) {
                int idx = tid + i * 256;
                int r = idx >> 2, k = (idx & 3) * 4;
                int kk = k0 + k;
                if (PRO == 4) {
                    pAv[i] = (kk < ENCD)
                        ? *(const float4*)(A + (size_t)(m0 + r) * g.lda + kk)
                        : *(const float4*)(g.padd + (size_t)(m0 + r) * g.ldadd + (kk - ENCD));
                } else {
                    pAv[i] = *(const float4*)(A + (size_t)(m0 + r) * g.lda + kk);
                }
                int kr = idx >> 5, n = (idx & 31) * 4;
                size_t boff = (size_t)(k0 + kr) * g.ldb + n;
                pBhr[i] = *(const uint2*)(Bh + boff);
                pBlr[i] = *(const uint2*)(Bl + boff);
            }
        };
        auto commit = [&]() {
            #pragma unroll
            for (int i = 0; i < 2; i++) {
                int idx = tid + i * 256;
                int r = idx >> 2, k = (idx & 3) * 4;
                uint2 hp, lp;
                split4(pAv[i], hp, lp);
                *(uint2*)&sAh[0][r * LDKA + k] = hp;
                *(uint2*)&sAl[0][r * LDKA + k] = lp;
                int kr = idx >> 5, n = (idx & 31) * 4;
                *(uint2*)&sBh[kr * LDNB + n] = pBhr[i];
                *(uint2*)&sBl[kr * LDNB + n] = pBlr[i];
            }
        };
        prefetch(0);
        for (int k0 = 0; k0 < g.K; k0 += 16) {
            commit();
            __syncthreads();
            if (k0 + 16 < g.K) prefetch(k0 + 16);

            uint32_t a_h[2][4], a_l[2][4];
            #pragma unroll
            for (int mt = 0; mt < 2; mt++) {
                uint32_t off = (uint32_t)(((wm * 32 + mt * 16 + arow) * LDKA + akoff) * 2);
                ldsm_x4(a_h[mt], sAh_b + off);
                ldsm_x4(a_l[mt], sAl_b + off);
            }
            uint32_t b_h[4][4], b_l[4][4];
            #pragma unroll
            for (int ng = 0; ng < 4; ng++) {
                uint32_t off = (uint32_t)((bkrow * LDNB + wn * 64 + ng * 16 + bnoff) * 2);
                ldsm_x4t(b_h[ng], sBh_b + off);
                ldsm_x4t(b_l[ng], sBl_b + off);
            }
            #pragma unroll
            for (int mt = 0; mt < 2; mt++)
                #pragma unroll
                for (int ng = 0; ng < 4; ng++)
                    #pragma unroll
                    for (int h = 0; h < 2; h++) {
                        int nt = ng * 2 + h;
                        mma16816(acc[mt][nt], a_h[mt], b_h[ng][h*2], b_h[ng][h*2+1]);
                        mma16816(acc[mt][nt], a_h[mt], b_l[ng][h*2], b_l[ng][h*2+1]);
                        mma16816(acc[mt][nt], a_l[mt], b_h[ng][h*2], b_h[ng][h*2+1]);
                    }
            __syncthreads();
        }
    }

    // ---- epilogue ----
    float rs_[2][2];
    if (EPI == 10) {
        #pragma unroll
        for (int mt = 0; mt < 2; mt++)
            #pragma unroll
            for (int hh = 0; hh < 2; hh++)
                rs_[mt][hh] = bias[m0 + wm * 32 + mt * 16 + (lane >> 2) + hh * 8];
    }
    #pragma unroll
    for (int mt = 0; mt < 2; mt++) {
        #pragma unroll
        for (int nt = 0; nt < 8; nt++) {
            int r0 = m0 + wm * 32 + mt * 16 + (lane >> 2);
            int c  = wn * 64 + nt * 8 + (lane & 3) * 2;
            float* a4 = acc[mt][nt];
            #pragma unroll
            for (int half = 0; half < 2; half++) {
                int r = r0 + half * 8;
                float v0 = a4[half * 2 + 0], v1 = a4[half * 2 + 1];
                if (EPI >= 1 && EPI != 9 && EPI != 10) {
                    float2 bb = *(const float2*)(bias + c);
                    v0 += bb.x; v1 += bb.y;
                }
                if (EPI == 6 || EPI == 7) { v0 = fmaxf(v0, 0.f); v1 = fmaxf(v1, 0.f); }
                if (EPI == 8) {
                    if (blockIdx.y == 0) {
                        v0 = 1.f / (1.f + __expf(-v0));
                        v1 = 1.f / (1.f + __expf(-v1));
                    } else {
                        v0 = tanhf(v0); v1 = tanhf(v1);
                    }
                }
                if (EPI == 10) {
                    float s = rs_[mt][half];
                    __half2 hp = __floats2half2_rn(v0 * s, v1 * s);
                    *(__half2*)((__half*)g.Ch + (size_t)r * 128 + c) = hp;
                } else if (EPI == 9) {
                    __half2 hp = __floats2half2_rn(v0, v1);
                    *(__half2*)((__half*)g.Ch + (size_t)r * 128 + c) = hp;
                } else if (EPI == 6) {
                    uint32_t h, l;
                    splitpair(v0, v1, h, l);
                    *(uint32_t*)(g.Ch + (size_t)r * 128 + c) = h;
                    *(uint32_t*)(g.Cl + (size_t)r * 128 + c) = l;
                } else if (EPI == 7) {
                    __nv_bfloat16 h0 = __float2bfloat16_rn(v0);
                    __nv_bfloat16 h1 = __float2bfloat16_rn(v1);
                    g.Ch[(size_t)c * g.ldc + r]       = h0;
                    g.Ch[(size_t)(c + 1) * g.ldc + r] = h1;
                    g.Cl[(size_t)c * g.ldc + r]       = __float2bfloat16_rn(v0 - __bfloat162float(h0));
                    g.Cl[(size_t)(c + 1) * g.ldc + r] = __float2bfloat16_rn(v1 - __bfloat162float(h1));
                } else {
                    float* p = C + (size_t)r * g.ldc + c;
                    float2 o; o.x = v0; o.y = v1;
                    *(float2*)p = o;
                }
            }
        }
    }
}

// =============== fused flash attention (split-KV, cp.async K/G pipeline) ====
#define FB_QH 0
#define FB_QL 17408
#define FB_BUF0 34816
#define FB_STRIDE 35840
#define FK_LO 9216
#define FG_HI 18432
#define FG_LO 27136
#define FSMEM2 ((34816 + 2*35840) * 2)   // 212992 B

__global__ void __launch_bounds__(256) flash_attn(
    const __nv_bfloat16* __restrict__ qh, const __nv_bfloat16* __restrict__ ql,
    const __nv_bfloat16* __restrict__ kmh, const __nv_bfloat16* __restrict__ kml,
    const __nv_bfloat16* __restrict__ gh, const __nv_bfloat16* __restrict__ gl,
    __half* __restrict__ Opart, float* __restrict__ pm, float* __restrict__ pl)
{
    extern __shared__ __align__(16) __nv_bfloat16 fsm[];
    int qt = blockIdx.x, b = blockIdx.y, sp = blockIdx.z;
    int tid = threadIdx.x, wid = tid >> 5, lane = tid & 31;
    int qrow0 = b * LQ + qt * 128;
    int kb0 = b * NPER + sp * KEYS_PER;
    uint32_t sbase = smem_u32(fsm);

    auto fillKG = [&](int kt) {
        int p = kt & 1;
        int kb = kb0 + kt * KT;
        uint32_t base = sbase + (uint32_t)(FB_BUF0 + p * FB_STRIDE) * 2;
        #pragma unroll
        for (int i = 0; i < 4; i++) {
            int idx = tid + i * 256;
            int e = idx >> 3, kq = (idx & 7) * 8;
            uint32_t dk = base + (uint32_t)(e * 72 + kq) * 2;
            CP16(dk, kmh + (size_t)e * NTOT + kb + kq);
            CP16(dk + FK_LO * 2, kml + (size_t)e * NTOT + kb + kq);
        }
        #pragma unroll
        for (int i = 0; i < 4; i++) {
            int idx = tid + i * 256;
            int ky = idx >> 4, eq = (idx & 15) * 8;
            uint32_t dg = base + (uint32_t)(FG_HI + ky * 136 + eq) * 2;
            CP16(dg, gh + (size_t)(kb + ky) * 128 + eq);
            CP16(dg + (FG_LO - FG_HI) * 2, gl + (size_t)(kb + ky) * 128 + eq);
        }
    };

    fillKG(0); CPCOMMIT();
    #pragma unroll
    for (int i = 0; i < 16; i++) {
        int idx = tid + i * 256;
        int r = idx >> 5, cq = idx & 31;
        size_t go = (size_t)(qrow0 + r) * 128 + cq * 4;
        *(uint2*)&fsm[FB_QH + r * 136 + cq * 4] = *(const uint2*)(qh + go);
        *(uint2*)&fsm[FB_QL + r * 136 + cq * 4] = *(const uint2*)(ql + go);
    }
    __syncthreads();

    int arow = lane & 15, akoff = (lane >> 4) * 8;
    int bkrow = (lane & 7) + ((lane >> 3) & 1) * 8;
    int bnoff = (lane >> 4) * 8;

    uint32_t qah[8][4], qal[8][4];
    #pragma unroll
    for (int kc = 0; kc < 8; kc++) {
        uint32_t qoff = (uint32_t)(((wid * 16 + arow) * 136 + kc * 16 + akoff) * 2);
        ldsm_x4(qah[kc], sbase + FB_QH * 2 + qoff);
        ldsm_x4(qal[kc], sbase + FB_QL * 2 + qoff);
    }

    float Oc[16][4];
    #pragma unroll
    for (int i = 0; i < 16; i++)
        #pragma unroll
        for (int j = 0; j < 4; j++) Oc[i][j] = 0.f;
    float m0 = -1e30f, m1 = -1e30f, l0 = 0.f, l1 = 0.f;

    constexpr int NKT = KEYS_PER / KT;   // 4
    for (int kt = 0; kt < NKT; kt++) {
        if (kt + 1 < NKT) { fillKG(kt + 1); CPCOMMIT(); CPWAIT1(); }
        else              { CPWAIT0(); }
        __syncthreads();

        int p = kt & 1;
        uint32_t sK_h = sbase + (uint32_t)(FB_BUF0 + p * FB_STRIDE) * 2;
        uint32_t sK_l = sK_h + FK_LO * 2;
        uint32_t sG_h = sK_h + FG_HI * 2;
        uint32_t sG_l = sK_h + FG_LO * 2;

        float S[8][4];
        #pragma unroll
        for (int i = 0; i < 8; i++)
            #pragma unroll
            for (int j = 0; j < 4; j++) S[i][j] = 0.f;

        #pragma unroll
        for (int kc = 0; kc < 8; kc++) {
            #pragma unroll
            for (int ng = 0; ng < 4; ng++) {
                uint32_t bh[4], bl[4];
                uint32_t koff = (uint32_t)(((kc * 16 + bkrow) * 72 + ng * 16 + bnoff) * 2);
                ldsm_x4t(bh, sK_h + koff);
                ldsm_x4t(bl, sK_l + koff);
                #pragma unroll
                for (int h = 0; h < 2; h++) {
                    int nt = ng * 2 + h;
                    mma16816(S[nt], qah[kc], bh[h*2], bh[h*2+1]);
                    mma16816(S[nt], qah[kc], bl[h*2], bl[h*2+1]);
                    mma16816(S[nt], qal[kc], bh[h*2], bh[h*2+1]);
                }
            }
        }

        float r0 = -1e30f, r1 = -1e30f;
        #pragma unroll
        for (int nt = 0; nt < 8; nt++) {
            r0 = fmaxf(r0, fmaxf(S[nt][0], S[nt][1]));
            r1 = fmaxf(r1, fmaxf(S[nt][2], S[nt][3]));
        }
        r0 = fmaxf(r0, __shfl_xor_sync(~0u, r0, 1));
        r0 = fmaxf(r0, __shfl_xor_sync(~0u, r0, 2));
        r1 = fmaxf(r1, __shfl_xor_sync(~0u, r1, 1));
        r1 = fmaxf(r1, __shfl_xor_sync(~0u, r1, 2));
        float mn0 = fmaxf(m0, r0), mn1 = fmaxf(m1, r1);
        float sc0 = __expf(m0 - mn0), sc1 = __expf(m1 - mn1);
        float rs0 = 0.f, rs1 = 0.f;
        #pragma unroll
        for (int nt = 0; nt < 8; nt++) {
            S[nt][0] = __expf(S[nt][0] - mn0);
            S[nt][1] = __expf(S[nt][1] - mn0);
            S[nt][2] = __expf(S[nt][2] - mn1);
            S[nt][3] = __expf(S[nt][3] - mn1);
            rs0 += S[nt][0] + S[nt][1];
            rs1 += S[nt][2] + S[nt][3];
        }
        rs0 += __shfl_xor_sync(~0u, rs0, 1);
        rs0 += __shfl_xor_sync(~0u, rs0, 2);
        rs1 += __shfl_xor_sync(~0u, rs1, 1);
        rs1 += __shfl_xor_sync(~0u, rs1, 2);
        l0 = l0 * sc0 + rs0;
        l1 = l1 * sc1 + rs1;
        m0 = mn0; m1 = mn1;
        #pragma unroll
        for (int nt = 0; nt < 16; nt++) {
            Oc[nt][0] *= sc0; Oc[nt][1] *= sc0;
            Oc[nt][2] *= sc1; Oc[nt][3] *= sc1;
        }

        #pragma unroll
        for (int j = 0; j < 4; j++) {
            uint32_t ph[4];
            ph[0] = packbf(S[2*j][0],   S[2*j][1]);
            ph[1] = packbf(S[2*j][2],   S[2*j][3]);
            ph[2] = packbf(S[2*j+1][0], S[2*j+1][1]);
            ph[3] = packbf(S[2*j+1][2], S[2*j+1][3]);
            #pragma unroll
            for (int ng = 0; ng < 8; ng++) {
                uint32_t gh4[4], gl4[4];
                uint32_t goff = (uint32_t)(((j * 16 + bkrow) * 136 + ng * 16 + bnoff) * 2);
                ldsm_x4t(gh4, sG_h + goff);
                ldsm_x4t(gl4, sG_l + goff);
                #pragma unroll
                for (int h = 0; h < 2; h++) {
                    int nt = ng * 2 + h;
                    mma16816(Oc[nt], ph, gh4[h*2], gh4[h*2+1]);
                    mma16816(Oc[nt], ph, gl4[h*2], gl4[h*2+1]);
                }
            }
        }
        __syncthreads();
    }

    int rr0 = qrow0 + wid * 16 + (lane >> 2);
    int rr1 = rr0 + 8;
    __half* Ob = Opart + (size_t)sp * NROWS * 128;
    #pragma unroll
    for (int nt = 0; nt < 16; nt++) {
        int c = nt * 8 + (lane & 3) * 2;
        __half2 o0 = __floats2half2_rn(Oc[nt][0], Oc[nt][1]);
        __half2 o1 = __floats2half2_rn(Oc[nt][2], Oc[nt][3]);
        *(__half2*)(Ob + (size_t)rr0 * 128 + c) = o0;
        *(__half2*)(Ob + (size_t)rr1 * 128 + c) = o1;
    }
    if ((lane & 3) == 0) {
        pm[sp * NROWS + rr0] = m0; pm[sp * NROWS + rr1] = m1;
        pl[sp * NROWS + rr0] = l0; pl[sp * NROWS + rr1] = l1;
    }
}

__global__ void __launch_bounds__(256) flash_combine(
    const __half* __restrict__ Opart, const float* __restrict__ pm,
    const float* __restrict__ pl, float* __restrict__ H)
{
    int row = blockIdx.x * 8 + (threadIdx.x >> 5);
    int lane = threadIdx.x & 31;
    float ms = -1e30f;
    #pragma unroll
    for (int s = 0; s < SPLIT; s++) ms = fmaxf(ms, pm[s * NROWS + row]);
    float w[SPLIT]; float lt = 0.f;
    #pragma unroll
    for (int s = 0; s < SPLIT; s++) {
        w[s] = __expf(pm[s * NROWS + row] - ms);
        lt += w[s] * pl[s * NROWS + row];
    }
    float4 acc = make_float4(0.f, 0.f, 0.f, 0.f);
    #pragma unroll
    for (int s = 0; s < SPLIT; s++) {
        uint2 raw = *(const uint2*)(Opart + ((size_t)s * NROWS + row) * 128 + lane * 4);
        float2 f0 = __half22float2(*(__half2*)&raw.x);
        float2 f1 = __half22float2(*(__half2*)&raw.y);
        acc.x += w[s] * f0.x; acc.y += w[s] * f0.y;
        acc.z += w[s] * f1.x; acc.w += w[s] * f1.y;
    }
    float inv = 1.f / lt;
    acc.x *= inv; acc.y *= inv; acc.z *= inv; acc.w *= inv;
    *(float4*)(H + (size_t)row * 128 + lane * 4) = acc;
}

// ---------------- orchestration ---------------------------------------------
extern "C" void kernel_launch(void* const* d_in, const int* in_sizes, int n_in,
                              void* d_out, int out_size) {
    const float* x    = (const float*)d_in[0];
    const float* nfr  = (const float*)d_in[1];
    const int*   eidx = (const int*)d_in[2];
    const int*   hidx = (const int*)d_in[3];
    const float* Wg1  = (const float*)d_in[4];   const float* bg1 = (const float*)d_in[5];
    const float* Wg2  = (const float*)d_in[6];   const float* bg2 = (const float*)d_in[7];
    const float* Wh1  = (const float*)d_in[8];   const float* bh1 = (const float*)d_in[9];
    const float* Wh2  = (const float*)d_in[10];  const float* bh2 = (const float*)d_in[11];
    const float* Wm   = (const float*)d_in[12];  const float* bm  = (const float*)d_in[13];
    const float* Wm2  = (const float*)d_in[14];  const float* bm2 = (const float*)d_in[15];
    const float* Ws   = (const float*)d_in[16];  const float* bsv = (const float*)d_in[17];
    const float* Wt   = (const float*)d_in[18];  const float* bt  = (const float*)d_in[19];
    float* out = (float*)d_out;

    float *t_, *ef_, *H_, *pm_, *pl_;
    __half *Oph_;
    float *rsout_, *rsin_, *Dinv_, *Binv_;
    __nv_bfloat16 *aggh_, *aggl_, *vh_, *vl_, *qh_, *ql_, *kmh_, *kml_, *gh_, *gl_, *wh_, *wl_;
    int *offe_, *cole_, *offhn_, *colhn_, *offhe_, *colhe_;
    cudaGetSymbolAddress((void**)&t_,   d_t);
    cudaGetSymbolAddress((void**)&ef_,  d_ef);
    cudaGetSymbolAddress((void**)&H_,   d_H);
    cudaGetSymbolAddress((void**)&Oph_, d_Op);
    cudaGetSymbolAddress((void**)&pm_,  d_pm);
    cudaGetSymbolAddress((void**)&pl_,  d_pl);
    cudaGetSymbolAddress((void**)&aggh_, d_aggh);
    cudaGetSymbolAddress((void**)&aggl_, d_aggl);
    cudaGetSymbolAddress((void**)&vh_,  d_vh);
    cudaGetSymbolAddress((void**)&vl_,  d_vl);
    cudaGetSymbolAddress((void**)&qh_,  d_qh);
    cudaGetSymbolAddress((void**)&ql_,  d_ql);
    cudaGetSymbolAddress((void**)&kmh_, d_kmh);
    cudaGetSymbolAddress((void**)&kml_, d_kml);
    cudaGetSymbolAddress((void**)&gh_,  d_gh);
    cudaGetSymbolAddress((void**)&gl_,  d_gl);
    cudaGetSymbolAddress((void**)&wh_,  d_wh);
    cudaGetSymbolAddress((void**)&wl_,  d_wl);
    cudaGetSymbolAddress((void**)&rsout_, d_rsout);
    cudaGetSymbolAddress((void**)&rsin_,  d_rsin);
    cudaGetSymbolAddress((void**)&Dinv_,  d_Dinv);
    cudaGetSymbolAddress((void**)&Binv_,  d_Binv);
    cudaGetSymbolAddress((void**)&offe_,  d_off_e);
    cudaGetSymbolAddress((void**)&cole_,  d_col_e);
    cudaGetSymbolAddress((void**)&offhn_, d_off_hn);
    cudaGetSymbolAddress((void**)&colhn_, d_col_hn);
    cudaGetSymbolAddress((void**)&offhe_, d_off_he);
    cudaGetSymbolAddress((void**)&colhe_, d_col_he);
    __half* th_  = (__half*)t_;
    __half* efh_ = (__half*)ef_;

    cudaFuncSetAttribute(flash_attn, cudaFuncAttributeMaxDynamicSharedMemorySize, FSMEM2);
    dim3 thr(256);

    zero_counts<<<NTOT / 256, thr>>>();
    count_all<<<NE / 256 + NP / 256, thr>>>(eidx, hidx);
    finalize_scales<<<NTOT / 256, thr>>>();
    PSArgs ps;
    ps.s[0] = Wg1; ps.s[1] = Wh1; ps.s[2] = Wg2; ps.s[3] = Wh2;
    ps.s[4] = Wm2; ps.s[5] = Wm;  ps.s[6] = Ws;  ps.s[7] = Wt;
    presplit_all<<<304, thr>>>(ps, wh_, wl_);
    // ga0 = (nfr @ Wg1) * rsout[row] -> half (EPI 10 row-scale fold)
    MArgs ga0 = {};
    ga0.A = nfr; ga0.lda = 128; ga0.Bh = wh_ + OFF_WG1; ga0.Bl = wl_ + OFF_WG1; ga0.ldb = 128;
    ga0.Ch = (__nv_bfloat16*)th_; ga0.K = 128; ga0.bias = rsout_;
    mma_gemm<0, 10, 1><<<dim3(NTOT / 128, 1, 1), thr>>>(ga0);
    scan1c<<<528, thr>>>();
    scan2c<<<3, thr>>>();
    scan3c<<<528, thr>>>();
    fill_all<<<NE / 256 + NP / 256, thr>>>(eidx, hidx);

    for (int layer = 0; layer < 2; layer++) {
        const float* bgv = layer ? bg2 : bg1;
        int whoff = layer ? OFF_WH2 : OFF_WH1;

        if (layer == 1) {
            MArgs ga = {};
            ga.Ah = vh_; ga.Al = vl_;
            ga.Bh = wh_ + OFF_WG2; ga.Bl = wl_ + OFF_WG2; ga.ldb = 128;
            ga.Ch = (__nv_bfloat16*)th_; ga.K = 128;
            mma_gemm<0, 9, 2><<<dim3(NTOT / 128, 1, 1), thr>>>(ga);
        }
        // agg-hat = (sum t)*rsin + bg -> hi/lo  (rsout pre-folded in both layers)
        gather_k<2, false, false><<<NTOT / 8, thr>>>(offe_, cole_, th_, nullptr,
            nullptr, nullptr, rsin_, bgv, nullptr, nullptr, aggh_, aggl_);

        MArgs gb = {};
        gb.Ah = aggh_; gb.Al = aggl_;
        gb.Bh = wh_ + whoff; gb.Bl = wl_ + whoff; gb.ldb = 128;
        gb.Ch = (__nv_bfloat16*)th_; gb.K = 128;
        mma_gemm<0, 9, 2><<<dim3(NTOT / 128, 1, 1), thr>>>(gb);

        // ef = Binv * (sum over hyperedge members)  -- 4 warps per row
        gather_he<<<NHE / 2, thr>>>(offhe_, colhe_, th_, efh_, Binv_);
        if (layer == 0) {
            gather_k<3, false, false><<<NTOT / 8, thr>>>(offhn_, colhn_, efh_, nullptr,
                nullptr, nullptr, Dinv_, bh1, nfr, rsout_, vh_, vl_);
        } else {
            gather_k<1, false, false><<<NTOT / 8, thr>>>(offhn_, colhn_, efh_, nullptr,
                nullptr, nullptr, Dinv_, bh2, nfr, nullptr, gh_, gl_);
        }
    }

    // q = relu(x @ Wm + bm) -> bf16 hi/lo
    MArgs gq = {};
    gq.A = x; gq.lda = ENCD; gq.Bh = wh_ + OFF_WM; gq.Bl = wl_ + OFF_WM; gq.ldb = 128;
    gq.Ch = qh_; gq.Cl = ql_; gq.K = ENCD; gq.bias = bm;
    mma_gemm<0, 6, 0><<<dim3(NROWS / 128, 1, 1), thr>>>(gq);

    // kmT = relu(g @ Wm2 + bm2)^T -> bf16 hi/lo
    MArgs gk = {};
    gk.Ah = gh_; gk.Al = gl_;
    gk.Bh = wh_ + OFF_WM2; gk.Bl = wl_ + OFF_WM2; gk.ldb = 128;
    gk.Ch = kmh_; gk.Cl = kml_; gk.ldc = NTOT; gk.K = 128; gk.bias = bm2;
    mma_gemm<0, 7, 2><<<dim3(NTOT / 128, 1, 1), thr>>>(gk);

    flash_attn<<<dim3(4, BSZ, SPLIT), thr, FSMEM2>>>(qh_, ql_, kmh_, kml_, gh_, gl_,
                                                     Oph_, pm_, pl_);
    flash_combine<<<NROWS / 8, thr>>>(Oph_, pm_, pl_, H_);

    MArgs ghd = {};
    ghd.A = x; ghd.lda = ENCD;
    ghd.Bh = wh_ + OFF_WS; ghd.Bl = wl_ + OFF_WS; ghd.ldb = 128;
    ghd.Bh2 = wh_ + OFF_WT; ghd.Bl2 = wl_ + OFF_WT;
    ghd.C = out; ghd.ldc = 256; ghd.K = ENCD + EMB;
    ghd.padd = H_; ghd.ldadd = 128; ghd.bias = bsv; ghd.bias2 = bt;
    mma_gemm<4, 8, 0><<<dim3(NROWS / 128, 2, 1), thr>>>(ghd);
}

// round 17
// speedup vs baseline: 1.2124x; 1.0431x over previous
#include <cuda_runtime.h>
#include <cuda_bf16.h>
#include <cuda_fp16.h>
#include <cstdint>

#define BSZ   8
#define NPER  8192
#define NTOT  65536
#define EMB   128
#define ENCD  512
#define LQ    512
#define NE    1048576
#define NHE   4096
#define NP    1048576
#define NROWS (BSZ*LQ)   // 4096
#define SPLIT 32
#define KEYS_PER (NPER/SPLIT)   // 256
#define KT    64

#define LDKA 24
#define LDNB 136

__device__ __forceinline__ uint32_t smem_u32(const void* p) {
    uint32_t a;
    asm("{ .reg .u64 t; cvta.to.shared.u64 t, %1; cvt.u32.u64 %0, t; }"
        : "=r"(a) : "l"(p));
    return a;
}
__device__ __forceinline__ void ldsm_x4(uint32_t* r, uint32_t addr) {
    asm volatile("ldmatrix.sync.aligned.m8n8.x4.shared.b16 {%0,%1,%2,%3}, [%4];"
                 : "=r"(r[0]), "=r"(r[1]), "=r"(r[2]), "=r"(r[3]) : "r"(addr));
}
__device__ __forceinline__ void ldsm_x4t(uint32_t* r, uint32_t addr) {
    asm volatile("ldmatrix.sync.aligned.m8n8.x4.trans.shared.b16 {%0,%1,%2,%3}, [%4];"
                 : "=r"(r[0]), "=r"(r[1]), "=r"(r[2]), "=r"(r[3]) : "r"(addr));
}
__device__ __forceinline__ void mma16816(float* c, const uint32_t* a,
                                         uint32_t b0, uint32_t b1) {
    asm volatile("mma.sync.aligned.m16n8k16.row.col.f32.bf16.bf16.f32 "
                 "{%0,%1,%2,%3}, {%4,%5,%6,%7}, {%8,%9}, {%0,%1,%2,%3};"
                 : "+f"(c[0]), "+f"(c[1]), "+f"(c[2]), "+f"(c[3])
                 : "r"(a[0]), "r"(a[1]), "r"(a[2]), "r"(a[3]), "r"(b0), "r"(b1));
}
__device__ __forceinline__ void split4(float4 av, uint2& hp, uint2& lp) {
    __nv_bfloat162 h0, h1, l0, l1;
    h0.x = __float2bfloat16_rn(av.x); h0.y = __float2bfloat16_rn(av.y);
    h1.x = __float2bfloat16_rn(av.z); h1.y = __float2bfloat16_rn(av.w);
    l0.x = __float2bfloat16_rn(av.x - __bfloat162float(h0.x));
    l0.y = __float2bfloat16_rn(av.y - __bfloat162float(h0.y));
    l1.x = __float2bfloat16_rn(av.z - __bfloat162float(h1.x));
    l1.y = __float2bfloat16_rn(av.w - __bfloat162float(h1.y));
    hp.x = *(uint32_t*)&h0; hp.y = *(uint32_t*)&h1;
    lp.x = *(uint32_t*)&l0; lp.y = *(uint32_t*)&l1;
}
__device__ __forceinline__ void splitpair(float a, float b, uint32_t& h, uint32_t& l) {
    __nv_bfloat162 hh, ll;
    hh.x = __float2bfloat16_rn(a); hh.y = __float2bfloat16_rn(b);
    ll.x = __float2bfloat16_rn(a - __bfloat162float(hh.x));
    ll.y = __float2bfloat16_rn(b - __bfloat162float(hh.y));
    h = *(uint32_t*)&hh; l = *(uint32_t*)&ll;
}
__device__ __forceinline__ uint32_t packbf(float a, float b) {
    __nv_bfloat162 h;
    h.x = __float2bfloat16_rn(a); h.y = __float2bfloat16_rn(b);
    return *(uint32_t*)&h;
}

#define CP16(s, gp) asm volatile("cp.async.ca.shared.global [%0], [%1], 16;" :: "r"(s), "l"(gp))
#define CPCOMMIT()  asm volatile("cp.async.commit_group;" ::: "memory")
#define CPWAIT1()   asm volatile("cp.async.wait_group 1;" ::: "memory")
#define CPWAIT0()   asm volatile("cp.async.wait_group 0;" ::: "memory")

// ---------------- scratch ----------------------------------------------------
__device__ float d_t  [(size_t)NTOT*EMB];      // reused as __half buffer
__device__ float d_ef [(size_t)NTOT*EMB];      // reused as __half buffer
__device__ float d_H  [(size_t)NROWS*EMB];
__device__ __half d_Op [(size_t)SPLIT*NROWS*EMB];
__device__ float d_pm [SPLIT*NROWS], d_pl[SPLIT*NROWS];
__device__ __nv_bfloat16 d_aggh[(size_t)NTOT*EMB], d_aggl[(size_t)NTOT*EMB];
__device__ __nv_bfloat16 d_vh  [(size_t)NTOT*EMB], d_vl  [(size_t)NTOT*EMB];
__device__ __nv_bfloat16 d_qh[(size_t)NROWS*EMB],  d_ql[(size_t)NROWS*EMB];
__device__ __nv_bfloat16 d_kmh[(size_t)EMB*NTOT],  d_kml[(size_t)EMB*NTOT];
__device__ __nv_bfloat16 d_gh[(size_t)NTOT*EMB],   d_gl[(size_t)NTOT*EMB];
#define OFF_WG1 0
#define OFF_WH1 16384
#define OFF_WG2 32768
#define OFF_WH2 49152
#define OFF_WM2 65536
#define OFF_WM  81920
#define OFF_WS  147456
#define OFF_WT  229376
__device__ __nv_bfloat16 d_wh[311296], d_wl[311296];
__device__ float d_rsout[NTOT], d_rsin[NTOT], d_Dinv[NTOT], d_Binv[NHE];
__device__ int   d_c0[NTOT], d_c1[NTOT], d_c2[NTOT], d_c3[NHE];
__device__ int d_off_e [NTOT+1], d_col_e [NE];
__device__ int d_off_hn[NTOT+1], d_col_hn[NP];
__device__ int d_off_he[NHE+1],  d_col_he[NP];
__device__ int d_cre[NTOT], d_crn[NTOT], d_crh[NHE];
__device__ int d_part3[3][257];

// ---------------- utility ----------------------------------------------------
struct PSArgs { const float* s[8]; };
__global__ void presplit_all(PSArgs a, __nv_bfloat16* __restrict__ hi,
                             __nv_bfloat16* __restrict__ lo) {
    const int bstart[8] = {0, 16, 32, 48, 64, 80, 144, 224};
    const int dstoff[8] = {0, 4096, 8192, 12288, 16384, 20480, 36864, 57344};
    int b = blockIdx.x;
    int seg = 0;
    #pragma unroll
    for (int s = 1; s < 8; s++) if (b >= bstart[s]) seg = s;
    int li = (b - bstart[seg]) * 256 + threadIdx.x;
    int n4 = (seg < 5) ? 4096 : (seg == 5 ? 16384 : 20480);
    if (li >= n4) return;
    float4 v = ((const float4*)a.s[seg])[li];
    uint2 hp, lp;
    split4(v, hp, lp);
    *(uint2*)(hi + ((size_t)dstoff[seg] + li) * 4) = hp;
    *(uint2*)(lo + ((size_t)dstoff[seg] + li) * 4) = lp;
}

__global__ void zero_counts() {
    int i = blockIdx.x * blockDim.x + threadIdx.x;
    if (i < NTOT) { d_c0[i] = 0; d_c1[i] = 0; d_c2[i] = 0; d_cre[i] = 0; d_crn[i] = 0; }
    if (i < NHE)  { d_c3[i] = 0; d_crh[i] = 0; }
}
__global__ void count_all(const int* __restrict__ eidx, const int* __restrict__ hidx) {
    int b = blockIdx.x, t = threadIdx.x;
    if (b < NE / 256) {
        int i = b * 256 + t;
        atomicAdd(&d_c0[eidx[i]], 1);
        atomicAdd(&d_c1[eidx[NE + i]], 1);
    } else {
        int i = (b - NE / 256) * 256 + t;
        atomicAdd(&d_c2[hidx[2 * i]], 1);
        atomicAdd(&d_c3[hidx[2 * i + 1]], 1);
    }
}
__global__ void finalize_scales() {
    int i = blockIdx.x * blockDim.x + threadIdx.x;
    if (i < NTOT) {
        d_rsout[i] = rsqrtf((float)max(d_c0[i], 1));
        d_rsin[i]  = rsqrtf((float)max(d_c1[i], 1));
        d_Dinv[i]  = d_c2[i] > 0 ? 1.f / (float)d_c2[i] : 0.f;
    }
    if (i < NHE) d_Binv[i] = d_c3[i] > 0 ? 1.f / (float)d_c3[i] : 0.f;
}

// ---------------- merged scans ----------------------------------------------
__global__ void scan1c() {
    int b = blockIdx.x;
    const int* cnt; int* off; int* part; int li;
    if (b < 256)      { cnt = d_c1; off = d_off_e;  part = d_part3[0]; li = b; }
    else if (b < 512) { cnt = d_c2; off = d_off_hn; part = d_part3[1]; li = b - 256; }
    else              { cnt = d_c3; off = d_off_he; part = d_part3[2]; li = b - 512; }
    __shared__ int sh[256];
    int t = threadIdx.x;
    int i = li * 256 + t;
    int v = cnt[i];
    sh[t] = v;
    __syncthreads();
    #pragma unroll
    for (int o = 1; o < 256; o <<= 1) {
        int add = (t >= o) ? sh[t - o] : 0;
        __syncthreads();
        sh[t] += add;
        __syncthreads();
    }
    off[i] = sh[t] - v;
    if (t == 255) part[li] = sh[255];
}
__global__ void scan2c() {
    int a = blockIdx.x;
    int nb = (a == 2) ? 16 : 256;
    int* part = d_part3[a];
    __shared__ int sh[256];
    int t = threadIdx.x;
    int v = (t < nb) ? part[t] : 0;
    sh[t] = v;
    __syncthreads();
    #pragma unroll
    for (int o = 1; o < 256; o <<= 1) {
        int add = (t >= o) ? sh[t - o] : 0;
        __syncthreads();
        sh[t] += add;
        __syncthreads();
    }
    part[t] = sh[t] - v;
    if (t == nb - 1) part[256] = sh[t];
}
__global__ void scan3c() {
    int b = blockIdx.x;
    int* off; int* part; int li; int n;
    if (b < 256)      { off = d_off_e;  part = d_part3[0]; li = b; n = NTOT; }
    else if (b < 512) { off = d_off_hn; part = d_part3[1]; li = b - 256; n = NTOT; }
    else              { off = d_off_he; part = d_part3[2]; li = b - 512; n = NHE; }
    int i = li * 256 + threadIdx.x;
    off[i] += part[li];
    if (i == 0) off[n] = part[256];
}

__global__ void fill_all(const int* __restrict__ eidx, const int* __restrict__ hidx) {
    int b = blockIdx.x, t = threadIdx.x;
    if (b < NE / 256) {
        int i = b * 256 + t;
        int s = eidx[i], d = eidx[NE + i];
        int p = atomicAdd(&d_cre[d], 1);
        d_col_e[d_off_e[d] + p] = s;
    } else {
        int i = (b - NE / 256) * 256 + t;
        int n = hidx[2 * i], e = hidx[2 * i + 1];
        int p1 = atomicAdd(&d_crn[n], 1);
        d_col_hn[d_off_hn[n] + p1] = e;
        int p2 = atomicAdd(&d_crh[e], 1);
        d_col_he[d_off_he[e] + p2] = n;
    }
}

// ---------------- CSR gather (fp16 in), warp-per-row, unroll 8 ---------------
template<int GEPI, bool OSC, bool ISC>
__global__ void __launch_bounds__(256) gather_k(const int* __restrict__ off,
                                                const int* __restrict__ col,
                                                const __half* __restrict__ in,
                                                void* __restrict__ outp,
                                                const float* __restrict__ oscale,
                                                const float* __restrict__ iscale,
                                                const float* __restrict__ s1,
                                                const float* __restrict__ pb,
                                                const float* __restrict__ padd,
                                                const float* __restrict__ s2,
                                                __nv_bfloat16* __restrict__ oh,
                                                __nv_bfloat16* __restrict__ ol) {
    int r    = blockIdx.x * 8 + (threadIdx.x >> 5);
    int lane = threadIdx.x & 31;
    int b = off[r], e = off[r + 1];
    float4 acc = make_float4(0.f, 0.f, 0.f, 0.f);
    for (int j0 = b; j0 < e; j0 += 32) {
        int cj = 0;
        if (j0 + lane < e) cj = col[j0 + lane];
        int m = min(e - j0, 32);
        #pragma unroll 8
        for (int k = 0; k < m; k++) {
            int c = __shfl_sync(~0u, cj, k);
            uint2 raw = *(const uint2*)(in + (size_t)c * EMB + lane * 4);
            float2 f01 = __half22float2(*(__half2*)&raw.x);
            float2 f23 = __half22float2(*(__half2*)&raw.y);
            if (ISC) {
                float s = iscale[c];
                f01.x *= s; f01.y *= s; f23.x *= s; f23.y *= s;
            }
            acc.x += f01.x; acc.y += f01.y; acc.z += f23.x; acc.w += f23.y;
        }
    }
    if (OSC) {
        float s = oscale[r];
        acc.x *= s; acc.y *= s; acc.z *= s; acc.w *= s;
    }
    if (GEPI == 4) {
        __half2 o01 = __floats2half2_rn(acc.x, acc.y);
        __half2 o23 = __floats2half2_rn(acc.z, acc.w);
        uint2 st; st.x = *(uint32_t*)&o01; st.y = *(uint32_t*)&o23;
        *(uint2*)((__half*)outp + (size_t)r * EMB + lane * 4) = st;
        return;
    }
    float sr = s1[r];
    float4 bb = *(const float4*)(pb + lane * 4);
    acc.x = acc.x * sr + bb.x;
    acc.y = acc.y * sr + bb.y;
    acc.z = acc.z * sr + bb.z;
    acc.w = acc.w * sr + bb.w;
    if (GEPI == 3 || GEPI == 1) {
        float4 nn = *(const float4*)(padd + (size_t)r * EMB + lane * 4);
        acc.x = fmaxf(acc.x, 0.f) + nn.x;
        acc.y = fmaxf(acc.y, 0.f) + nn.y;
        acc.z = fmaxf(acc.z, 0.f) + nn.z;
        acc.w = fmaxf(acc.w, 0.f) + nn.w;
        if (GEPI == 3) {
            float so = s2[r];
            acc.x *= so; acc.y *= so; acc.z *= so; acc.w *= so;
        }
    }
    uint2 hp, lp;
    split4(acc, hp, lp);
    *(uint2*)(oh + (size_t)r * EMB + lane * 4) = hp;
    *(uint2*)(ol + (size_t)r * EMB + lane * 4) = lp;
}

// ---------------- hyperedge gather: 4 warps per row (deg ~256) ----------------
__global__ void __launch_bounds__(256) gather_he(const int* __restrict__ off,
                                                 const int* __restrict__ col,
                                                 const __half* __restrict__ in,
                                                 __half* __restrict__ outp,
                                                 const float* __restrict__ Binv) {
    __shared__ float4 red[2][4][32];
    int grp = threadIdx.x >> 7;
    int wig = (threadIdx.x >> 5) & 3;
    int lane = threadIdx.x & 31;
    int r = blockIdx.x * 2 + grp;
    int b = off[r], e = off[r + 1];
    float4 acc = make_float4(0.f, 0.f, 0.f, 0.f);
    for (int j0 = b + wig * 32; j0 < e; j0 += 128) {
        int cj = 0;
        if (j0 + lane < e) cj = col[j0 + lane];
        int m = min(e - j0, 32);
        #pragma unroll 8
        for (int k = 0; k < m; k++) {
            int c = __shfl_sync(~0u, cj, k);
            uint2 raw = *(const uint2*)(in + (size_t)c * EMB + lane * 4);
            float2 f01 = __half22float2(*(__half2*)&raw.x);
            float2 f23 = __half22float2(*(__half2*)&raw.y);
            acc.x += f01.x; acc.y += f01.y; acc.z += f23.x; acc.w += f23.y;
        }
    }
    red[grp][wig][lane] = acc;
    __syncthreads();
    if (wig == 0) {
        float4 a0 = red[grp][0][lane], a1 = red[grp][1][lane];
        float4 a2 = red[grp][2][lane], a3 = red[grp][3][lane];
        float s = Binv[r];
        float4 o;
        o.x = (a0.x + a1.x + a2.x + a3.x) * s;
        o.y = (a0.y + a1.y + a2.y + a3.y) * s;
        o.z = (a0.z + a1.z + a2.z + a3.z) * s;
        o.w = (a0.w + a1.w + a2.w + a3.w) * s;
        __half2 o01 = __floats2half2_rn(o.x, o.y);
        __half2 o23 = __floats2half2_rn(o.z, o.w);
        uint2 st; st.x = *(uint32_t*)&o01; st.y = *(uint32_t*)&o23;
        *(uint2*)(outp + (size_t)r * EMB + lane * 4) = st;
    }
}

// =============== mma.sync bf16-split GEMM ===================================
struct MArgs {
    const float* A; long lda;
    const __nv_bfloat16* Ah; const __nv_bfloat16* Al;
    const __nv_bfloat16* Bh; const __nv_bfloat16* Bl; long ldb;
    const __nv_bfloat16* Bh2; const __nv_bfloat16* Bl2;
    float* C; long ldc;
    __nv_bfloat16* Ch; __nv_bfloat16* Cl;
    int K;
    const float* padd; long ldadd;
    const float* bias; const float* bias2;
};

template<int PRO, int EPI, int MODE>
__global__ void __launch_bounds__(256, 2) mma_gemm(MArgs g) {
    constexpr int BROWS = (MODE >= 1) ? 128 : 16;
    constexpr int ABUF  = (MODE == 2) ? 3 : (MODE == 1 ? 2 : 1);
    __shared__ __align__(16) __nv_bfloat16 sAh[ABUF][128 * LDKA];
    __shared__ __align__(16) __nv_bfloat16 sAl[ABUF][128 * LDKA];
    __shared__ __align__(16) __nv_bfloat16 sBh[BROWS * LDNB];
    __shared__ __align__(16) __nv_bfloat16 sBl[BROWS * LDNB];

    const float* A = g.A;
    float* C = g.C;
    const __nv_bfloat16* Bh = g.Bh;
    const __nv_bfloat16* Bl = g.Bl;
    const float* bias = g.bias;
    if (EPI == 8 && blockIdx.y == 1) {
        Bh = g.Bh2; Bl = g.Bl2; bias = g.bias2; C = g.C + 128;
    }
    int m0 = blockIdx.x * 128;

    int tid = threadIdx.x, wid = tid >> 5, lane = tid & 31;
    int wm = wid >> 1, wn = wid & 1;

    float acc[2][8][4];
    #pragma unroll
    for (int i = 0; i < 2; i++)
        #pragma unroll
        for (int j = 0; j < 8; j++)
            #pragma unroll
            for (int q = 0; q < 4; q++) acc[i][j][q] = 0.f;

    uint32_t sBh_b = smem_u32(sBh), sBl_b = smem_u32(sBl);

    int arow = lane & 15, akoff = (lane >> 4) * 8;
    int bkrow = (lane & 7) + ((lane >> 3) & 1) * 8;
    int bnoff = (lane >> 4) * 8;

    if (MODE == 2) {
        #pragma unroll
        for (int i = 0; i < 16; i++) {
            int idx = tid + i * 256;
            int kr = idx >> 5, n = (idx & 31) * 4;
            size_t boff = (size_t)kr * g.ldb + n;
            *(uint2*)&sBh[kr * LDNB + n] = *(const uint2*)(Bh + boff);
            *(uint2*)&sBl[kr * LDNB + n] = *(const uint2*)(Bl + boff);
        }
        int row = tid >> 1, half = tid & 1;
        auto cpA = [&](int c) {
            int slot = c % 3;
            uint32_t sh_ = smem_u32(&sAh[slot][row * LDKA + half * 8]);
            uint32_t sl_ = smem_u32(&sAl[slot][row * LDKA + half * 8]);
            const __nv_bfloat16* gph = g.Ah + (size_t)(m0 + row) * 128 + c * 16 + half * 8;
            const __nv_bfloat16* gpl = g.Al + (size_t)(m0 + row) * 128 + c * 16 + half * 8;
            CP16(sh_, gph);
            CP16(sl_, gpl);
        };
        cpA(0); CPCOMMIT();
        cpA(1); CPCOMMIT();

        #pragma unroll
        for (int c = 0; c < 8; c++) {
            CPWAIT1();
            __syncthreads();
            if (c + 2 < 8) cpA(c + 2);
            CPCOMMIT();

            int slot = c % 3;
            uint32_t sAh_b = smem_u32(sAh[slot]), sAl_b = smem_u32(sAl[slot]);
            uint32_t a_h[2][4], a_l[2][4];
            #pragma unroll
            for (int mt = 0; mt < 2; mt++) {
                uint32_t off = (uint32_t)(((wm * 32 + mt * 16 + arow) * LDKA + akoff) * 2);
                ldsm_x4(a_h[mt], sAh_b + off);
                ldsm_x4(a_l[mt], sAl_b + off);
            }
            uint32_t b_h[4][4], b_l[4][4];
            #pragma unroll
            for (int ng = 0; ng < 4; ng++) {
                uint32_t off = (uint32_t)(((c * 16 + bkrow) * LDNB + wn * 64 + ng * 16 + bnoff) * 2);
                ldsm_x4t(b_h[ng], sBh_b + off);
                ldsm_x4t(b_l[ng], sBl_b + off);
            }
            #pragma unroll
            for (int mt = 0; mt < 2; mt++)
                #pragma unroll
                for (int ng = 0; ng < 4; ng++)
                    #pragma unroll
                    for (int h = 0; h < 2; h++) {
                        int nt = ng * 2 + h;
                        mma16816(acc[mt][nt], a_h[mt], b_h[ng][h*2], b_h[ng][h*2+1]);
                        mma16816(acc[mt][nt], a_h[mt], b_l[ng][h*2], b_l[ng][h*2+1]);
                        mma16816(acc[mt][nt], a_l[mt], b_h[ng][h*2], b_h[ng][h*2+1]);
                    }
        }
    } else if (MODE == 1) {
        float4 pAv[2];
        auto prefetchA = [&](int k0) {
            #pragma unroll
            for (int i = 0; i < 2; i++) {
                int idx = tid + i * 256;
                int r = idx >> 2, k = (idx & 3) * 4;
                pAv[i] = *(const float4*)(A + (size_t)(m0 + r) * g.lda + k0 + k);
            }
        };
        auto commitA = [&](int p) {
            #pragma unroll
            for (int i = 0; i < 2; i++) {
                int idx = tid + i * 256;
                int r = idx >> 2, k = (idx & 3) * 4;
                uint2 hp, lp;
                split4(pAv[i], hp, lp);
                *(uint2*)&sAh[p][r * LDKA + k] = hp;
                *(uint2*)&sAl[p][r * LDKA + k] = lp;
            }
        };
        #pragma unroll
        for (int i = 0; i < 16; i++) {
            int idx = tid + i * 256;
            int kr = idx >> 5, n = (idx & 31) * 4;
            size_t boff = (size_t)kr * g.ldb + n;
            *(uint2*)&sBh[kr * LDNB + n] = *(const uint2*)(Bh + boff);
            *(uint2*)&sBl[kr * LDNB + n] = *(const uint2*)(Bl + boff);
        }
        prefetchA(0);
        commitA(0);
        __syncthreads();
        #pragma unroll
        for (int c = 0; c < 8; c++) {
            int p = c & 1;
            uint32_t sAh_b = smem_u32(sAh[p]), sAl_b = smem_u32(sAl[p]);
            uint32_t a_h[2][4], a_l[2][4];
            #pragma unroll
            for (int mt = 0; mt < 2; mt++) {
                uint32_t off = (uint32_t)(((wm * 32 + mt * 16 + arow) * LDKA + akoff) * 2);
                ldsm_x4(a_h[mt], sAh_b + off);
                ldsm_x4(a_l[mt], sAl_b + off);
            }
            uint32_t b_h[4][4], b_l[4][4];
            #pragma unroll
            for (int ng = 0; ng < 4; ng++) {
                uint32_t off = (uint32_t)(((c * 16 + bkrow) * LDNB + wn * 64 + ng * 16 + bnoff) * 2);
                ldsm_x4t(b_h[ng], sBh_b + off);
                ldsm_x4t(b_l[ng], sBl_b + off);
            }
            if (c < 7) prefetchA((c + 1) * 16);
            #pragma unroll
            for (int mt = 0; mt < 2; mt++)
                #pragma unroll
                for (int ng = 0; ng < 4; ng++)
                    #pragma unroll
                    for (int h = 0; h < 2; h++) {
                        int nt = ng * 2 + h;
                        mma16816(acc[mt][nt], a_h[mt], b_h[ng][h*2], b_h[ng][h*2+1]);
                        mma16816(acc[mt][nt], a_h[mt], b_l[ng][h*2], b_l[ng][h*2+1]);
                        mma16816(acc[mt][nt], a_l[mt], b_h[ng][h*2], b_h[ng][h*2+1]);
                    }
            if (c < 7) {
                commitA(p ^ 1);
                __syncthreads();
            }
        }
    } else {
        uint32_t sAh_b = smem_u32(sAh[0]), sAl_b = smem_u32(sAl[0]);
        float4 pAv[2];
        uint2 pBhr[2], pBlr[2];
        auto prefetch = [&](int k0) {
            #pragma unroll
            for (int i = 0; i < 2; i++) {
                int idx = tid + i * 256;
                int r = idx >> 2, k = (idx & 3) * 4;
                int kk = k0 + k;
                if (PRO == 4) {
                    pAv[i] = (kk < ENCD)
                        ? *(const float4*)(A + (size_t)(m0 + r) * g.lda + kk)
                        : *(const float4*)(g.padd + (size_t)(m0 + r) * g.ldadd + (kk - ENCD));
                } else {
                    pAv[i] = *(const float4*)(A + (size_t)(m0 + r) * g.lda + kk);
                }
                int kr = idx >> 5, n = (idx & 31) * 4;
                size_t boff = (size_t)(k0 + kr) * g.ldb + n;
                pBhr[i] = *(const uint2*)(Bh + boff);
                pBlr[i] = *(const uint2*)(Bl + boff);
            }
        };
        auto commit = [&]() {
            #pragma unroll
            for (int i = 0; i < 2; i++) {
                int idx = tid + i * 256;
                int r = idx >> 2, k = (idx & 3) * 4;
                uint2 hp, lp;
                split4(pAv[i], hp, lp);
                *(uint2*)&sAh[0][r * LDKA + k] = hp;
                *(uint2*)&sAl[0][r * LDKA + k] = lp;
                int kr = idx >> 5, n = (idx & 31) * 4;
                *(uint2*)&sBh[kr * LDNB + n] = pBhr[i];
                *(uint2*)&sBl[kr * LDNB + n] = pBlr[i];
            }
        };
        prefetch(0);
        for (int k0 = 0; k0 < g.K; k0 += 16) {
            commit();
            __syncthreads();
            if (k0 + 16 < g.K) prefetch(k0 + 16);

            uint32_t a_h[2][4], a_l[2][4];
            #pragma unroll
            for (int mt = 0; mt < 2; mt++) {
                uint32_t off = (uint32_t)(((wm * 32 + mt * 16 + arow) * LDKA + akoff) * 2);
                ldsm_x4(a_h[mt], sAh_b + off);
                ldsm_x4(a_l[mt], sAl_b + off);
            }
            uint32_t b_h[4][4], b_l[4][4];
            #pragma unroll
            for (int ng = 0; ng < 4; ng++) {
                uint32_t off = (uint32_t)((bkrow * LDNB + wn * 64 + ng * 16 + bnoff) * 2);
                ldsm_x4t(b_h[ng], sBh_b + off);
                ldsm_x4t(b_l[ng], sBl_b + off);
            }
            #pragma unroll
            for (int mt = 0; mt < 2; mt++)
                #pragma unroll
                for (int ng = 0; ng < 4; ng++)
                    #pragma unroll
                    for (int h = 0; h < 2; h++) {
                        int nt = ng * 2 + h;
                        mma16816(acc[mt][nt], a_h[mt], b_h[ng][h*2], b_h[ng][h*2+1]);
                        mma16816(acc[mt][nt], a_h[mt], b_l[ng][h*2], b_l[ng][h*2+1]);
                        mma16816(acc[mt][nt], a_l[mt], b_h[ng][h*2], b_h[ng][h*2+1]);
                    }
            __syncthreads();
        }
    }

    // ---- epilogue ----
    float rs_[2][2];
    if (EPI == 10) {
        #pragma unroll
        for (int mt = 0; mt < 2; mt++)
            #pragma unroll
            for (int hh = 0; hh < 2; hh++)
                rs_[mt][hh] = bias[m0 + wm * 32 + mt * 16 + (lane >> 2) + hh * 8];
    }
    #pragma unroll
    for (int mt = 0; mt < 2; mt++) {
        #pragma unroll
        for (int nt = 0; nt < 8; nt++) {
            int r0 = m0 + wm * 32 + mt * 16 + (lane >> 2);
            int c  = wn * 64 + nt * 8 + (lane & 3) * 2;
            float* a4 = acc[mt][nt];
            #pragma unroll
            for (int half = 0; half < 2; half++) {
                int r = r0 + half * 8;
                float v0 = a4[half * 2 + 0], v1 = a4[half * 2 + 1];
                if (EPI >= 1 && EPI != 9 && EPI != 10) {
                    float2 bb = *(const float2*)(bias + c);
                    v0 += bb.x; v1 += bb.y;
                }
                if (EPI == 6 || EPI == 7) { v0 = fmaxf(v0, 0.f); v1 = fmaxf(v1, 0.f); }
                if (EPI == 8) {
                    if (blockIdx.y == 0) {
                        v0 = 1.f / (1.f + __expf(-v0));
                        v1 = 1.f / (1.f + __expf(-v1));
                    } else {
                        v0 = tanhf(v0); v1 = tanhf(v1);
                    }
                }
                if (EPI == 10) {
                    float s = rs_[mt][half];
                    __half2 hp = __floats2half2_rn(v0 * s, v1 * s);
                    *(__half2*)((__half*)g.Ch + (size_t)r * 128 + c) = hp;
                } else if (EPI == 9) {
                    __half2 hp = __floats2half2_rn(v0, v1);
                    *(__half2*)((__half*)g.Ch + (size_t)r * 128 + c) = hp;
                } else if (EPI == 6) {
                    uint32_t h, l;
                    splitpair(v0, v1, h, l);
                    *(uint32_t*)(g.Ch + (size_t)r * 128 + c) = h;
                    *(uint32_t*)(g.Cl + (size_t)r * 128 + c) = l;
                } else if (EPI == 7) {
                    __nv_bfloat16 h0 = __float2bfloat16_rn(v0);
                    __nv_bfloat16 h1 = __float2bfloat16_rn(v1);
                    g.Ch[(size_t)c * g.ldc + r]       = h0;
                    g.Ch[(size_t)(c + 1) * g.ldc + r] = h1;
                    g.Cl[(size_t)c * g.ldc + r]       = __float2bfloat16_rn(v0 - __bfloat162float(h0));
                    g.Cl[(size_t)(c + 1) * g.ldc + r] = __float2bfloat16_rn(v1 - __bfloat162float(h1));
                } else {
                    float* p = C + (size_t)r * g.ldc + c;
                    float2 o; o.x = v0; o.y = v1;
                    *(float2*)p = o;
                }
            }
        }
    }
}

// =============== fused flash attention (split-KV, cp.async K/G pipeline) ====
#define FB_QH 0
#define FB_QL 17408
#define FB_BUF0 34816
#define FB_STRIDE 35840
#define FK_LO 9216
#define FG_HI 18432
#define FG_LO 27136
#define FSMEM2 ((34816 + 2*35840) * 2)   // 212992 B

__global__ void __launch_bounds__(256) flash_attn(
    const __nv_bfloat16* __restrict__ qh, const __nv_bfloat16* __restrict__ ql,
    const __nv_bfloat16* __restrict__ kmh, const __nv_bfloat16* __restrict__ kml,
    const __nv_bfloat16* __restrict__ gh, const __nv_bfloat16* __restrict__ gl,
    __half* __restrict__ Opart, float* __restrict__ pm, float* __restrict__ pl)
{
    extern __shared__ __align__(16) __nv_bfloat16 fsm[];
    int qt = blockIdx.x, b = blockIdx.y, sp = blockIdx.z;
    int tid = threadIdx.x, wid = tid >> 5, lane = tid & 31;
    int qrow0 = b * LQ + qt * 128;
    int kb0 = b * NPER + sp * KEYS_PER;
    uint32_t sbase = smem_u32(fsm);

    auto fillKG = [&](int kt) {
        int p = kt & 1;
        int kb = kb0 + kt * KT;
        uint32_t base = sbase + (uint32_t)(FB_BUF0 + p * FB_STRIDE) * 2;
        #pragma unroll
        for (int i = 0; i < 4; i++) {
            int idx = tid + i * 256;
            int e = idx >> 3, kq = (idx & 7) * 8;
            uint32_t dk = base + (uint32_t)(e * 72 + kq) * 2;
            CP16(dk, kmh + (size_t)e * NTOT + kb + kq);
            CP16(dk + FK_LO * 2, kml + (size_t)e * NTOT + kb + kq);
        }
        #pragma unroll
        for (int i = 0; i < 4; i++) {
            int idx = tid + i * 256;
            int ky = idx >> 4, eq = (idx & 15) * 8;
            uint32_t dg = base + (uint32_t)(FG_HI + ky * 136 + eq) * 2;
            CP16(dg, gh + (size_t)(kb + ky) * 128 + eq);
            CP16(dg + (FG_LO - FG_HI) * 2, gl + (size_t)(kb + ky) * 128 + eq);
        }
    };

    fillKG(0); CPCOMMIT();
    #pragma unroll
    for (int i = 0; i < 16; i++) {
        int idx = tid + i * 256;
        int r = idx >> 5, cq = idx & 31;
        size_t go = (size_t)(qrow0 + r) * 128 + cq * 4;
        *(uint2*)&fsm[FB_QH + r * 136 + cq * 4] = *(const uint2*)(qh + go);
        *(uint2*)&fsm[FB_QL + r * 136 + cq * 4] = *(const uint2*)(ql + go);
    }
    __syncthreads();

    int arow = lane & 15, akoff = (lane >> 4) * 8;
    int bkrow = (lane & 7) + ((lane >> 3) & 1) * 8;
    int bnoff = (lane >> 4) * 8;

    uint32_t qah[8][4], qal[8][4];
    #pragma unroll
    for (int kc = 0; kc < 8; kc++) {
        uint32_t qoff = (uint32_t)(((wid * 16 + arow) * 136 + kc * 16 + akoff) * 2);
        ldsm_x4(qah[kc], sbase + FB_QH * 2 + qoff);
        ldsm_x4(qal[kc], sbase + FB_QL * 2 + qoff);
    }

    float Oc[16][4];
    #pragma unroll
    for (int i = 0; i < 16; i++)
        #pragma unroll
        for (int j = 0; j < 4; j++) Oc[i][j] = 0.f;
    float m0 = -1e30f, m1 = -1e30f, l0 = 0.f, l1 = 0.f;

    constexpr int NKT = KEYS_PER / KT;   // 4
    for (int kt = 0; kt < NKT; kt++) {
        if (kt + 1 < NKT) { fillKG(kt + 1); CPCOMMIT(); CPWAIT1(); }
        else              { CPWAIT0(); }
        __syncthreads();

        int p = kt & 1;
        uint32_t sK_h = sbase + (uint32_t)(FB_BUF0 + p * FB_STRIDE) * 2;
        uint32_t sK_l = sK_h + FK_LO * 2;
        uint32_t sG_h = sK_h + FG_HI * 2;
        uint32_t sG_l = sK_h + FG_LO * 2;

        float S[8][4];
        #pragma unroll
        for (int i = 0; i < 8; i++)
            #pragma unroll
            for (int j = 0; j < 4; j++) S[i][j] = 0.f;

        #pragma unroll
        for (int kc = 0; kc < 8; kc++) {
            #pragma unroll
            for (int ng = 0; ng < 4; ng++) {
                uint32_t bh[4], bl[4];
                uint32_t koff = (uint32_t)(((kc * 16 + bkrow) * 72 + ng * 16 + bnoff) * 2);
                ldsm_x4t(bh, sK_h + koff);
                ldsm_x4t(bl, sK_l + koff);
                #pragma unroll
                for (int h = 0; h < 2; h++) {
                    int nt = ng * 2 + h;
                    mma16816(S[nt], qah[kc], bh[h*2], bh[h*2+1]);
                    mma16816(S[nt], qah[kc], bl[h*2], bl[h*2+1]);
                    mma16816(S[nt], qal[kc], bh[h*2], bh[h*2+1]);
                }
            }
        }

        float r0 = -1e30f, r1 = -1e30f;
        #pragma unroll
        for (int nt = 0; nt < 8; nt++) {
            r0 = fmaxf(r0, fmaxf(S[nt][0], S[nt][1]));
            r1 = fmaxf(r1, fmaxf(S[nt][2], S[nt][3]));
        }
        r0 = fmaxf(r0, __shfl_xor_sync(~0u, r0, 1));
        r0 = fmaxf(r0, __shfl_xor_sync(~0u, r0, 2));
        r1 = fmaxf(r1, __shfl_xor_sync(~0u, r1, 1));
        r1 = fmaxf(r1, __shfl_xor_sync(~0u, r1, 2));
        float mn0 = fmaxf(m0, r0), mn1 = fmaxf(m1, r1);
        float sc0 = __expf(m0 - mn0), sc1 = __expf(m1 - mn1);
        float rs0 = 0.f, rs1 = 0.f;
        #pragma unroll
        for (int nt = 0; nt < 8; nt++) {
            S[nt][0] = __expf(S[nt][0] - mn0);
            S[nt][1] = __expf(S[nt][1] - mn0);
            S[nt][2] = __expf(S[nt][2] - mn1);
            S[nt][3] = __expf(S[nt][3] - mn1);
            rs0 += S[nt][0] + S[nt][1];
            rs1 += S[nt][2] + S[nt][3];
        }
        rs0 += __shfl_xor_sync(~0u, rs0, 1);
        rs0 += __shfl_xor_sync(~0u, rs0, 2);
        rs1 += __shfl_xor_sync(~0u, rs1, 1);
        rs1 += __shfl_xor_sync(~0u, rs1, 2);
        l0 = l0 * sc0 + rs0;
        l1 = l1 * sc1 + rs1;
        m0 = mn0; m1 = mn1;
        #pragma unroll
        for (int nt = 0; nt < 16; nt++) {
            Oc[nt][0] *= sc0; Oc[nt][1] *= sc0;
            Oc[nt][2] *= sc1; Oc[nt][3] *= sc1;
        }

        #pragma unroll
        for (int j = 0; j < 4; j++) {
            uint32_t ph[4];
            ph[0] = packbf(S[2*j][0],   S[2*j][1]);
            ph[1] = packbf(S[2*j][2],   S[2*j][3]);
            ph[2] = packbf(S[2*j+1][0], S[2*j+1][1]);
            ph[3] = packbf(S[2*j+1][2], S[2*j+1][3]);
            #pragma unroll
            for (int ng = 0; ng < 8; ng++) {
                uint32_t gh4[4], gl4[4];
                uint32_t goff = (uint32_t)(((j * 16 + bkrow) * 136 + ng * 16 + bnoff) * 2);
                ldsm_x4t(gh4, sG_h + goff);
                ldsm_x4t(gl4, sG_l + goff);
                #pragma unroll
                for (int h = 0; h < 2; h++) {
                    int nt = ng * 2 + h;
                    mma16816(Oc[nt], ph, gh4[h*2], gh4[h*2+1]);
                    mma16816(Oc[nt], ph, gl4[h*2], gl4[h*2+1]);
                }
            }
        }
        __syncthreads();
    }

    int rr0 = qrow0 + wid * 16 + (lane >> 2);
    int rr1 = rr0 + 8;
    __half* Ob = Opart + (size_t)sp * NROWS * 128;
    #pragma unroll
    for (int nt = 0; nt < 16; nt++) {
        int c = nt * 8 + (lane & 3) * 2;
        __half2 o0 = __floats2half2_rn(Oc[nt][0], Oc[nt][1]);
        __half2 o1 = __floats2half2_rn(Oc[nt][2], Oc[nt][3]);
        *(__half2*)(Ob + (size_t)rr0 * 128 + c) = o0;
        *(__half2*)(Ob + (size_t)rr1 * 128 + c) = o1;
    }
    if ((lane & 3) == 0) {
        pm[sp * NROWS + rr0] = m0; pm[sp * NROWS + rr1] = m1;
        pl[sp * NROWS + rr0] = l0; pl[sp * NROWS + rr1] = l1;
    }
}

__global__ void __launch_bounds__(256) flash_combine(
    const __half* __restrict__ Opart, const float* __restrict__ pm,
    const float* __restrict__ pl, float* __restrict__ H)
{
    int row = blockIdx.x * 8 + (threadIdx.x >> 5);
    int lane = threadIdx.x & 31;
    float ms = -1e30f;
    #pragma unroll
    for (int s = 0; s < SPLIT; s++) ms = fmaxf(ms, pm[s * NROWS + row]);
    float w[SPLIT]; float lt = 0.f;
    #pragma unroll
    for (int s = 0; s < SPLIT; s++) {
        w[s] = __expf(pm[s * NROWS + row] - ms);
        lt += w[s] * pl[s * NROWS + row];
    }
    float4 acc = make_float4(0.f, 0.f, 0.f, 0.f);
    #pragma unroll
    for (int s = 0; s < SPLIT; s++) {
        uint2 raw = *(const uint2*)(Opart + ((size_t)s * NROWS + row) * 128 + lane * 4);
        float2 f0 = __half22float2(*(__half2*)&raw.x);
        float2 f1 = __half22float2(*(__half2*)&raw.y);
        acc.x += w[s] * f0.x; acc.y += w[s] * f0.y;
        acc.z += w[s] * f1.x; acc.w += w[s] * f1.y;
    }
    float inv = 1.f / lt;
    acc.x *= inv; acc.y *= inv; acc.z *= inv; acc.w *= inv;
    *(float4*)(H + (size_t)row * 128 + lane * 4) = acc;
}

// ---------------- orchestration ---------------------------------------------
extern "C" void kernel_launch(void* const* d_in, const int* in_sizes, int n_in,
                              void* d_out, int out_size) {
    const float* x    = (const float*)d_in[0];
    const float* nfr  = (const float*)d_in[1];
    const int*   eidx = (const int*)d_in[2];
    const int*   hidx = (const int*)d_in[3];
    const float* Wg1  = (const float*)d_in[4];   const float* bg1 = (const float*)d_in[5];
    const float* Wg2  = (const float*)d_in[6];   const float* bg2 = (const float*)d_in[7];
    const float* Wh1  = (const float*)d_in[8];   const float* bh1 = (const float*)d_in[9];
    const float* Wh2  = (const float*)d_in[10];  const float* bh2 = (const float*)d_in[11];
    const float* Wm   = (const float*)d_in[12];  const float* bm  = (const float*)d_in[13];
    const float* Wm2  = (const float*)d_in[14];  const float* bm2 = (const float*)d_in[15];
    const float* Ws   = (const float*)d_in[16];  const float* bsv = (const float*)d_in[17];
    const float* Wt   = (const float*)d_in[18];  const float* bt  = (const float*)d_in[19];
    float* out = (float*)d_out;

    float *t_, *ef_, *H_, *pm_, *pl_;
    __half *Oph_;
    float *rsout_, *rsin_, *Dinv_, *Binv_;
    __nv_bfloat16 *aggh_, *aggl_, *vh_, *vl_, *qh_, *ql_, *kmh_, *kml_, *gh_, *gl_, *wh_, *wl_;
    int *offe_, *cole_, *offhn_, *colhn_, *offhe_, *colhe_;
    cudaGetSymbolAddress((void**)&t_,   d_t);
    cudaGetSymbolAddress((void**)&ef_,  d_ef);
    cudaGetSymbolAddress((void**)&H_,   d_H);
    cudaGetSymbolAddress((void**)&Oph_, d_Op);
    cudaGetSymbolAddress((void**)&pm_,  d_pm);
    cudaGetSymbolAddress((void**)&pl_,  d_pl);
    cudaGetSymbolAddress((void**)&aggh_, d_aggh);
    cudaGetSymbolAddress((void**)&aggl_, d_aggl);
    cudaGetSymbolAddress((void**)&vh_,  d_vh);
    cudaGetSymbolAddress((void**)&vl_,  d_vl);
    cudaGetSymbolAddress((void**)&qh_,  d_qh);
    cudaGetSymbolAddress((void**)&ql_,  d_ql);
    cudaGetSymbolAddress((void**)&kmh_, d_kmh);
    cudaGetSymbolAddress((void**)&kml_, d_kml);
    cudaGetSymbolAddress((void**)&gh_,  d_gh);
    cudaGetSymbolAddress((void**)&gl_,  d_gl);
    cudaGetSymbolAddress((void**)&wh_,  d_wh);
    cudaGetSymbolAddress((void**)&wl_,  d_wl);
    cudaGetSymbolAddress((void**)&rsout_, d_rsout);
    cudaGetSymbolAddress((void**)&rsin_,  d_rsin);
    cudaGetSymbolAddress((void**)&Dinv_,  d_Dinv);
    cudaGetSymbolAddress((void**)&Binv_,  d_Binv);
    cudaGetSymbolAddress((void**)&offe_,  d_off_e);
    cudaGetSymbolAddress((void**)&cole_,  d_col_e);
    cudaGetSymbolAddress((void**)&offhn_, d_off_hn);
    cudaGetSymbolAddress((void**)&colhn_, d_col_hn);
    cudaGetSymbolAddress((void**)&offhe_, d_off_he);
    cudaGetSymbolAddress((void**)&colhe_, d_col_he);
    __half* th_  = (__half*)t_;
    __half* efh_ = (__half*)ef_;

    // one-time stream/event setup (host objects; no device allocations)
    static cudaStream_t s1 = nullptr;
    static cudaEvent_t evFork = nullptr, evFin = nullptr, evJoin = nullptr;
    if (s1 == nullptr) {
        cudaStreamCreateWithFlags(&s1, cudaStreamNonBlocking);
        cudaEventCreateWithFlags(&evFork, cudaEventDisableTiming);
        cudaEventCreateWithFlags(&evFin,  cudaEventDisableTiming);
        cudaEventCreateWithFlags(&evJoin, cudaEventDisableTiming);
        cudaFuncSetAttribute(flash_attn, cudaFuncAttributeMaxDynamicSharedMemorySize, FSMEM2);
    }
    dim3 thr(256);

    // ---- fork: side stream handles weight split + q GEMM + ga0 ----
    cudaEventRecord(evFork, 0);
    cudaStreamWaitEvent(s1, evFork, 0);

    PSArgs ps;
    ps.s[0] = Wg1; ps.s[1] = Wh1; ps.s[2] = Wg2; ps.s[3] = Wh2;
    ps.s[4] = Wm2; ps.s[5] = Wm;  ps.s[6] = Ws;  ps.s[7] = Wt;
    presplit_all<<<304, thr, 0, s1>>>(ps, wh_, wl_);

    // q = relu(x @ Wm + bm) -> bf16 hi/lo  (independent of graph chain)
    MArgs gq = {};
    gq.A = x; gq.lda = ENCD; gq.Bh = wh_ + OFF_WM; gq.Bl = wl_ + OFF_WM; gq.ldb = 128;
    gq.Ch = qh_; gq.Cl = ql_; gq.K = ENCD; gq.bias = bm;
    mma_gemm<0, 6, 0><<<dim3(NROWS / 128, 1, 1), thr, 0, s1>>>(gq);

    // ---- main stream: graph setup chain ----
    zero_counts<<<NTOT / 256, thr>>>();
    count_all<<<NE / 256 + NP / 256, thr>>>(eidx, hidx);
    finalize_scales<<<NTOT / 256, thr>>>();
    cudaEventRecord(evFin, 0);
    scan1c<<<528, thr>>>();
    scan2c<<<3, thr>>>();
    scan3c<<<528, thr>>>();
    fill_all<<<NE / 256 + NP / 256, thr>>>(eidx, hidx);

    // ---- side stream: ga0 needs rsout (finalize) ----
    cudaStreamWaitEvent(s1, evFin, 0);
    MArgs ga0 = {};
    ga0.A = nfr; ga0.lda = 128; ga0.Bh = wh_ + OFF_WG1; ga0.Bl = wl_ + OFF_WG1; ga0.ldb = 128;
    ga0.Ch = (__nv_bfloat16*)th_; ga0.K = 128; ga0.bias = rsout_;
    mma_gemm<0, 10, 1><<<dim3(NTOT / 128, 1, 1), thr, 0, s1>>>(ga0);
    cudaEventRecord(evJoin, s1);
    cudaStreamWaitEvent(0, evJoin, 0);

    // ---- serial chain on main stream ----
    for (int layer = 0; layer < 2; layer++) {
        const float* bgv = layer ? bg2 : bg1;
        int whoff = layer ? OFF_WH2 : OFF_WH1;

        if (layer == 1) {
            MArgs ga = {};
            ga.Ah = vh_; ga.Al = vl_;
            ga.Bh = wh_ + OFF_WG2; ga.Bl = wl_ + OFF_WG2; ga.ldb = 128;
            ga.Ch = (__nv_bfloat16*)th_; ga.K = 128;
            mma_gemm<0, 9, 2><<<dim3(NTOT / 128, 1, 1), thr>>>(ga);
        }
        gather_k<2, false, false><<<NTOT / 8, thr>>>(offe_, cole_, th_, nullptr,
            nullptr, nullptr, rsin_, bgv, nullptr, nullptr, aggh_, aggl_);

        MArgs gb = {};
        gb.Ah = aggh_; gb.Al = aggl_;
        gb.Bh = wh_ + whoff; gb.Bl = wl_ + whoff; gb.ldb = 128;
        gb.Ch = (__nv_bfloat16*)th_; gb.K = 128;
        mma_gemm<0, 9, 2><<<dim3(NTOT / 128, 1, 1), thr>>>(gb);

        gather_he<<<NHE / 2, thr>>>(offhe_, colhe_, th_, efh_, Binv_);
        if (layer == 0) {
            gather_k<3, false, false><<<NTOT / 8, thr>>>(offhn_, colhn_, efh_, nullptr,
                nullptr, nullptr, Dinv_, bh1, nfr, rsout_, vh_, vl_);
        } else {
            gather_k<1, false, false><<<NTOT / 8, thr>>>(offhn_, colhn_, efh_, nullptr,
                nullptr, nullptr, Dinv_, bh2, nfr, nullptr, gh_, gl_);
        }
    }

    // kmT = relu(g @ Wm2 + bm2)^T -> bf16 hi/lo
    MArgs gk = {};
    gk.Ah = gh_; gk.Al = gl_;
    gk.Bh = wh_ + OFF_WM2; gk.Bl = wl_ + OFF_WM2; gk.ldb = 128;
    gk.Ch = kmh_; gk.Cl = kml_; gk.ldc = NTOT; gk.K = 128; gk.bias = bm2;
    mma_gemm<0, 7, 2><<<dim3(NTOT / 128, 1, 1), thr>>>(gk);

    flash_attn<<<dim3(4, BSZ, SPLIT), thr, FSMEM2>>>(qh_, ql_, kmh_, kml_, gh_, gl_,
                                                     Oph_, pm_, pl_);
    flash_combine<<<NROWS / 8, thr>>>(Oph_, pm_, pl_, H_);

    MArgs ghd = {};
    ghd.A = x; ghd.lda = ENCD;
    ghd.Bh = wh_ + OFF_WS; ghd.Bl = wl_ + OFF_WS; ghd.ldb = 128;
    ghd.Bh2 = wh_ + OFF_WT; ghd.Bl2 = wl_ + OFF_WT;
    ghd.C = out; ghd.ldc = 256; ghd.K = ENCD + EMB;
    ghd.padd = H_; ghd.ldadd = 128; ghd.bias = bsv; ghd.bias2 = bt;
    mma_gemm<4, 8, 0><<<dim3(NROWS / 128, 2, 1), thr>>>(ghd);
}